// round 4
// baseline (speedup 1.0000x reference)
#include <cuda_runtime.h>
#include <math.h>
#include <stdint.h>

#define BB   4
#define L1C  1024
#define L2C  512
#define LT   1536
#define DPG  2304
#define DEX  1024
#define NH   8
#define NKV  4
#define DHD  256
#define QK_SCALE 0.0625f

// ---------------- scratch (device globals; no allocation allowed) ----------
__device__ float g_Q[(size_t)BB * LT * NH * DHD];     // [b, l, h, d] fp32 (exact)
__device__ float g_K[(size_t)BB * LT * NKV * DHD];
__device__ float g_V[(size_t)BB * LT * NKV * DHD];
__device__ float g_att_hi[(size_t)BB * LT * NH * DHD];  // attention out, tf32 hi
__device__ float g_att_lo[(size_t)BB * LT * NH * DHD];  // attention out, tf32 lo

// tf32 hi/lo copies of GEMM operands
#define OFF_PG   0u
#define OFF_EX   9437184u
#define OFF_WQ0  11534336u
#define OFF_WK0  16252928u
#define OFF_WV0  18612224u
#define OFF_WO0  20971520u
#define OFF_WQ1  25690112u
#define OFF_WK1  27787264u
#define OFF_WV1  28835840u
#define OFF_WO1  29884416u
#define CVT_TOTAL 31981568u
__device__ unsigned g_hi[CVT_TOTAL];
__device__ unsigned g_lo[CVT_TOTAL];

// ---------------- tf32 helpers ----------------------------------------------
__device__ __forceinline__ unsigned rtf_u(float x)
{
    unsigned u;
    asm("cvt.rna.tf32.f32 %0, %1;" : "=r"(u) : "f"(x));
    return u;
}
__device__ __forceinline__ float rtf(float x) { return __uint_as_float(rtf_u(x)); }

// split conversion: hi = tf32(x), lo = tf32(x - hi)
__global__ void cvt_split(const float4* __restrict__ in, uint4* __restrict__ hi,
                          uint4* __restrict__ lo, int n4)
{
    int i = blockIdx.x * blockDim.x + threadIdx.x;
    if (i < n4) {
        float4 v = in[i];
        uint4 h, l;
        h.x = rtf_u(v.x); l.x = rtf_u(v.x - __uint_as_float(h.x));
        h.y = rtf_u(v.y); l.y = rtf_u(v.y - __uint_as_float(h.y));
        h.z = rtf_u(v.z); l.z = rtf_u(v.z - __uint_as_float(h.z));
        h.w = rtf_u(v.w); l.w = rtf_u(v.w - __uint_as_float(h.w));
        hi[i] = h; lo[i] = l;
    }
}

#define MMA_TF32(d, a, b)                                                     \
    asm volatile("mma.sync.aligned.m16n8k8.row.col.f32.tf32.tf32.f32 "        \
                 "{%0,%1,%2,%3}, {%4,%5,%6,%7}, {%8,%9}, {%0,%1,%2,%3};"      \
                 : "+f"(d[0]), "+f"(d[1]), "+f"(d[2]), "+f"(d[3])             \
                 : "r"(a[0]), "r"(a[1]), "r"(a[2]), "r"(a[3]),                \
                   "r"(b[0]), "r"(b[1]))

__device__ __forceinline__ void cpa16(uint32_t dst, const void* src)
{
    asm volatile("cp.async.cg.shared.global [%0], [%1], 16;" :: "r"(dst), "l"(src));
}

// ---------------- 3xTF32 NT GEMM (near-fp32 exact) ---------------------------
// C[m,n] = sum_k A[m,k]*W[n,k] with A = A_hi + A_lo, W = W_hi + W_lo (tf32 pairs)
// acc += A_lo*W_hi + A_hi*W_lo + A_hi*W_hi   (lo*lo dropped, ~2^-22)
#define GLDA 36
#define GBUF (128 * GLDA)
#define GSMEM_BYTES (8 * GBUF * 4)   // 2 stages x {A_hi, A_lo, W_hi, W_lo}

__global__ __launch_bounds__(256, 1) void gemm3x(
    const unsigned* __restrict__ Ah, const unsigned* __restrict__ Al,
    const unsigned* __restrict__ Wh, const unsigned* __restrict__ Wl,
    float* __restrict__ C, int K,
    int a_rpb, int a_bstride, int a_off,
    int c_rpb, int c_bstride, int c_off, int ldc)
{
    extern __shared__ unsigned smem[];

    const int tid    = threadIdx.x;
    const int wid    = tid >> 5;
    const int lane   = tid & 31;
    const int warp_m = wid >> 1;
    const int warp_n = wid & 1;
    const int bm = blockIdx.y * 128;
    const int bn = blockIdx.x * 128;

    const int lrow = tid >> 1;
    const int lcol = (tid & 1) * 16;
    const int am = bm + lrow;
    const int ar = (am / a_rpb) * a_bstride + a_off + (am % a_rpb);
    const size_t aoff = (size_t)ar * K + lcol;
    const size_t woff = (size_t)(bn + lrow) * K + lcol;

    const uint32_t sbase = (uint32_t)__cvta_generic_to_shared(smem);
    const uint32_t dst0 = sbase + (lrow * GLDA + lcol) * 4;

    float acc[2][8][4];
#pragma unroll
    for (int i = 0; i < 2; i++)
#pragma unroll
        for (int j = 0; j < 8; j++)
#pragma unroll
            for (int r = 0; r < 4; r++) acc[i][j][r] = 0.f;

    const int nk = K >> 5;
    const unsigned* srcs[4];

    // prologue: chunk 0 -> stage 0
    {
        const unsigned* s0 = Ah + aoff; const unsigned* s1 = Al + aoff;
        const unsigned* s2 = Wh + woff; const unsigned* s3 = Wl + woff;
        srcs[0] = s0; srcs[1] = s1; srcs[2] = s2; srcs[3] = s3;
#pragma unroll
        for (int t = 0; t < 4; t++)
#pragma unroll
            for (int j = 0; j < 4; j++)
                cpa16(dst0 + (t * GBUF) * 4 + j * 16, srcs[t] + j * 4);
        asm volatile("cp.async.commit_group;");
    }

    const int lr = lane >> 2;
    const int lc = lane & 3;

    for (int kc = 0; kc < nk; kc++) {
        const int cur = kc & 1;
        if (kc + 1 < nk) {
            const int nxt = (kc + 1) & 1;
            const int ko = (kc + 1) * 32;
            srcs[0] = Ah + aoff + ko; srcs[1] = Al + aoff + ko;
            srcs[2] = Wh + woff + ko; srcs[3] = Wl + woff + ko;
            const uint32_t db = dst0 + (nxt * 4 * GBUF) * 4;
#pragma unroll
            for (int t = 0; t < 4; t++)
#pragma unroll
                for (int j = 0; j < 4; j++)
                    cpa16(db + (t * GBUF) * 4 + j * 16, srcs[t] + j * 4);
            asm volatile("cp.async.commit_group;");
            asm volatile("cp.async.wait_group 1;");
        } else {
            asm volatile("cp.async.wait_group 0;");
        }
        __syncthreads();

        const unsigned* ash = smem + (cur * 4 + 0) * GBUF + (warp_m * 32 + lr) * GLDA + lc;
        const unsigned* asl = smem + (cur * 4 + 1) * GBUF + (warp_m * 32 + lr) * GLDA + lc;
        const unsigned* wsh = smem + (cur * 4 + 2) * GBUF + (warp_n * 64 + lr) * GLDA + lc;
        const unsigned* wsl = smem + (cur * 4 + 3) * GBUF + (warp_n * 64 + lr) * GLDA + lc;

#pragma unroll
        for (int ks = 0; ks < 4; ks++) {
            const int k0 = ks * 8;
            unsigned ah[2][4], al[2][4], bh[8][2], bl[8][2];
#pragma unroll
            for (int mf = 0; mf < 2; mf++) {
                const unsigned* ph = ash + mf * 16 * GLDA + k0;
                const unsigned* pl = asl + mf * 16 * GLDA + k0;
                ah[mf][0] = ph[0]; ah[mf][1] = ph[8 * GLDA];
                ah[mf][2] = ph[4]; ah[mf][3] = ph[8 * GLDA + 4];
                al[mf][0] = pl[0]; al[mf][1] = pl[8 * GLDA];
                al[mf][2] = pl[4]; al[mf][3] = pl[8 * GLDA + 4];
            }
#pragma unroll
            for (int nf = 0; nf < 8; nf++) {
                const unsigned* ph = wsh + nf * 8 * GLDA + k0;
                const unsigned* pl = wsl + nf * 8 * GLDA + k0;
                bh[nf][0] = ph[0]; bh[nf][1] = ph[4];
                bl[nf][0] = pl[0]; bl[nf][1] = pl[4];
            }
#pragma unroll
            for (int mf = 0; mf < 2; mf++)
#pragma unroll
                for (int nf = 0; nf < 8; nf++) {
                    MMA_TF32(acc[mf][nf], al[mf], bh[nf]);
                    MMA_TF32(acc[mf][nf], ah[mf], bl[nf]);
                    MMA_TF32(acc[mf][nf], ah[mf], bh[nf]);
                }
        }
        __syncthreads();
    }

#pragma unroll
    for (int mf = 0; mf < 2; mf++) {
        const int m0 = bm + warp_m * 32 + mf * 16 + lr;
        const int m1 = m0 + 8;
        const int r0 = (m0 / c_rpb) * c_bstride + c_off + (m0 % c_rpb);
        const int r1 = (m1 / c_rpb) * c_bstride + c_off + (m1 % c_rpb);
#pragma unroll
        for (int nf = 0; nf < 8; nf++) {
            const int col = bn + warp_n * 64 + nf * 8 + lc * 2;
            *(float2*)&C[(size_t)r0 * ldc + col] = make_float2(acc[mf][nf][0], acc[mf][nf][1]);
            *(float2*)&C[(size_t)r1 * ldc + col] = make_float2(acc[mf][nf][2], acc[mf][nf][3]);
        }
    }
}

// ---------------- RoPE (folds QK scale into Q) -------------------------------
__global__ void rope_kernel(float* __restrict__ X, const float* __restrict__ cs,
                            const float* __restrict__ sn, int nheads, float scale)
{
    const int h = blockIdx.x;
    const int l = blockIdx.y;
    const int b = blockIdx.z;
    const int i = threadIdx.x;
    const size_t row = (size_t)b * LT + l;
    const float c = cs[row * (DHD / 2) + i];
    const float s = sn[row * (DHD / 2) + i];
    const size_t base = (row * nheads + h) * DHD;
    const float x1 = X[base + i];
    const float x2 = X[base + (DHD / 2) + i];
    X[base + i]             = (x1 * c - x2 * s) * scale;
    X[base + (DHD / 2) + i] = (x2 * c + x1 * s) * scale;
}

// ---------------- tensor-core flash attention --------------------------------
// Block: (64-query tile, head, batch), 256 threads = 8 warps (wm 0..3, wn 0..1)
// smem strides chosen conflict-free: Q/K stride 268 (12*lr+lc spans 32 banks),
// V^T / S stride 68 (4*lr+lc spans 32 banks).
#define QKS 268
#define VTS 68
#define SS  68
#define SM_QS 0
#define SM_KS 17152
#define SM_VT 34304
#define SM_S  51712
#define SM_AL 56064
#define SM_LS 56128
#define SMEM_ATTN ((56192) * 4)

__global__ __launch_bounds__(256, 1) void attn_mma(const float* __restrict__ mask)
{
    extern __shared__ float sm[];
    float* Qs  = sm + SM_QS;
    float* Ks  = sm + SM_KS;
    float* VT  = sm + SM_VT;
    float* S   = sm + SM_S;
    float* Asc = sm + SM_AL;
    float* Lsc = sm + SM_LS;

    const int tid = threadIdx.x;
    const int qt = blockIdx.x;    // 0..23
    const int h  = blockIdx.y;
    const int b  = blockIdx.z;
    const int hkv = h >> 1;
    const int wid = tid >> 5, lane = tid & 31;
    const int wm = wid >> 1, wn = wid & 1;
    const int lr = lane >> 2, lc = lane & 3;
    const int srow = tid >> 2, spart = tid & 3;   // softmax: 4 threads / row

    // ---- stage Q (tf32-rounded; QK scale already folded by rope) ----
    for (int i = tid; i < 64 * 64; i += 256) {
        const int row = i >> 6, dq = i & 63;
        const float4 v = *(const float4*)&g_Q[((((size_t)b * LT + qt * 64 + row) * NH + h) * DHD) + dq * 4];
        float4 r = make_float4(rtf(v.x), rtf(v.y), rtf(v.z), rtf(v.w));
        *(float4*)&Qs[row * QKS + dq * 4] = r;
    }

    float accO[16][4];
#pragma unroll
    for (int i = 0; i < 16; i++)
#pragma unroll
        for (int j = 0; j < 4; j++) accO[i][j] = 0.f;
    float m_run = -1e30f, l_run = 0.f;

    for (int kt = 0; kt < LT / 64; kt++) {
        __syncthreads();  // prev PV/softmax done; smem free (covers Q staging too)
        // ---- stage K tile (rounded) ----
        for (int i = tid; i < 64 * 64; i += 256) {
            const int row = i >> 6, dq = i & 63;
            const float4 v = *(const float4*)&g_K[((((size_t)b * LT + kt * 64 + row) * NKV + hkv) * DHD) + dq * 4];
            float4 r = make_float4(rtf(v.x), rtf(v.y), rtf(v.z), rtf(v.w));
            *(float4*)&Ks[row * QKS + dq * 4] = r;
        }
        // ---- stage V^T (rounded): VT[d][key] ----
        for (int i = tid; i < 64 * 64; i += 256) {
            const int key = i & 63, dq = i >> 6;
            const float4 v = *(const float4*)&g_V[((((size_t)b * LT + kt * 64 + key) * NKV + hkv) * DHD) + dq * 4];
            VT[(dq * 4 + 0) * VTS + key] = rtf(v.x);
            VT[(dq * 4 + 1) * VTS + key] = rtf(v.y);
            VT[(dq * 4 + 2) * VTS + key] = rtf(v.z);
            VT[(dq * 4 + 3) * VTS + key] = rtf(v.w);
        }
        __syncthreads();

        // ---- S = Q K^T (warp tile 16x32, k = 256) ----
        float accS[4][4];
#pragma unroll
        for (int i = 0; i < 4; i++)
#pragma unroll
            for (int j = 0; j < 4; j++) accS[i][j] = 0.f;
        {
            const unsigned* qb = (const unsigned*)Qs + (wm * 16 + lr) * QKS + lc;
            const unsigned* kb = (const unsigned*)Ks + (wn * 32 + lr) * QKS + lc;
#pragma unroll 4
            for (int ks = 0; ks < 32; ks++) {
                const int k0 = ks * 8;
                unsigned a[4];
                a[0] = qb[k0]; a[1] = qb[8 * QKS + k0];
                a[2] = qb[k0 + 4]; a[3] = qb[8 * QKS + k0 + 4];
#pragma unroll
                for (int nf = 0; nf < 4; nf++) {
                    unsigned bfr[2];
                    const unsigned* p = kb + nf * 8 * QKS + k0;
                    bfr[0] = p[0]; bfr[1] = p[4];
                    MMA_TF32(accS[nf], a, bfr);
                }
            }
        }
        // ---- add mask, write S (fp32) ----
        {
            const size_t mrow0 = ((size_t)b * LT + qt * 64 + wm * 16 + lr) * LT + kt * 64 + wn * 32;
            const size_t mrow1 = mrow0 + (size_t)8 * LT;
#pragma unroll
            for (int nf = 0; nf < 4; nf++) {
                const int col = nf * 8 + lc * 2;
                const float2 m0 = *(const float2*)&mask[mrow0 + col];
                const float2 m1 = *(const float2*)&mask[mrow1 + col];
                *(float2*)&S[(wm * 16 + lr) * SS + wn * 32 + col] =
                    make_float2(accS[nf][0] + m0.x, accS[nf][1] + m0.y);
                *(float2*)&S[(wm * 16 + lr + 8) * SS + wn * 32 + col] =
                    make_float2(accS[nf][2] + m1.x, accS[nf][3] + m1.y);
            }
        }
        __syncthreads();

        // ---- online softmax (4 threads per row, 16 cols each) ----
        {
            float* sp = S + srow * SS + spart * 16;
            float lm = -1e30f;
#pragma unroll
            for (int j = 0; j < 16; j++) lm = fmaxf(lm, sp[j]);
            lm = fmaxf(lm, __shfl_xor_sync(0xffffffffu, lm, 1));
            lm = fmaxf(lm, __shfl_xor_sync(0xffffffffu, lm, 2));
            const float mnew = fmaxf(m_run, lm);
            const float alpha = __expf(m_run - mnew);
            float ls = 0.f;
#pragma unroll
            for (int j = 0; j < 16; j++) {
                const float p = __expf(sp[j] - mnew);
                ls += p;
                sp[j] = rtf(p);   // P as tf32 for PV mma
            }
            ls += __shfl_xor_sync(0xffffffffu, ls, 1);
            ls += __shfl_xor_sync(0xffffffffu, ls, 2);
            l_run = l_run * alpha + ls;
            m_run = mnew;
            if (spart == 0) Asc[srow] = alpha;
        }
        __syncthreads();

        // ---- rescale O, then O += P V (warp tile 16x128, k = 64) ----
        {
            const float a0 = Asc[wm * 16 + lr];
            const float a1 = Asc[wm * 16 + lr + 8];
#pragma unroll
            for (int nf = 0; nf < 16; nf++) {
                accO[nf][0] *= a0; accO[nf][1] *= a0;
                accO[nf][2] *= a1; accO[nf][3] *= a1;
            }
            const unsigned* pb = (const unsigned*)S + (wm * 16 + lr) * SS + lc;
            const unsigned* vb = (const unsigned*)VT + (wn * 128 + lr) * VTS + lc;
#pragma unroll
            for (int ks = 0; ks < 8; ks++) {
                const int k0 = ks * 8;
                unsigned a[4];
                a[0] = pb[k0]; a[1] = pb[8 * SS + k0];
                a[2] = pb[k0 + 4]; a[3] = pb[8 * SS + k0 + 4];
#pragma unroll
                for (int nf = 0; nf < 16; nf++) {
                    unsigned bfr[2];
                    const unsigned* p = vb + nf * 8 * VTS + k0;
                    bfr[0] = p[0]; bfr[1] = p[4];
                    MMA_TF32(accO[nf], a, bfr);
                }
            }
        }
    }

    if (spart == 0) Lsc[srow] = l_run;
    __syncthreads();

    // ---- epilogue: normalize, emit tf32 hi/lo for out-projection ----
    {
        const float il0 = 1.f / Lsc[wm * 16 + lr];
        const float il1 = 1.f / Lsc[wm * 16 + lr + 8];
        const size_t r0 = (size_t)b * LT + qt * 64 + wm * 16 + lr;
        const size_t r1 = r0 + 8;
#pragma unroll
        for (int nf = 0; nf < 16; nf++) {
            const int col = h * DHD + wn * 128 + nf * 8 + lc * 2;
            float v0 = accO[nf][0] * il0, v1 = accO[nf][1] * il0;
            float v2 = accO[nf][2] * il1, v3 = accO[nf][3] * il1;
            float h0 = rtf(v0), h1 = rtf(v1), h2 = rtf(v2), h3 = rtf(v3);
            *(float2*)&g_att_hi[r0 * (NH * DHD) + col] = make_float2(h0, h1);
            *(float2*)&g_att_hi[r1 * (NH * DHD) + col] = make_float2(h2, h3);
            *(float2*)&g_att_lo[r0 * (NH * DHD) + col] = make_float2(rtf(v0 - h0), rtf(v1 - h1));
            *(float2*)&g_att_lo[r1 * (NH * DHD) + col] = make_float2(rtf(v2 - h2), rtf(v3 - h3));
        }
    }
}

// ---------------- launch ----------------------------------------------------
extern "C" void kernel_launch(void* const* d_in, const int* in_sizes, int n_in,
                              void* d_out, int out_size)
{
    const float* pg   = (const float*)d_in[0];
    const float* ex   = (const float*)d_in[1];
    const float* cs   = (const float*)d_in[2];
    const float* sn   = (const float*)d_in[3];
    const float* mask = (const float*)d_in[4];
    const float* Wq0  = (const float*)d_in[5];
    const float* Wk0  = (const float*)d_in[6];
    const float* Wv0  = (const float*)d_in[7];
    const float* Wo0  = (const float*)d_in[8];
    const float* Wq1  = (const float*)d_in[9];
    const float* Wk1  = (const float*)d_in[10];
    const float* Wv1  = (const float*)d_in[11];
    const float* Wo1  = (const float*)d_in[12];
    float* out = (float*)d_out;

    float *Qd, *Kd, *Vd, *Ahd, *Ald;
    unsigned *Hv, *Lv;
    cudaGetSymbolAddress((void**)&Qd, g_Q);
    cudaGetSymbolAddress((void**)&Kd, g_K);
    cudaGetSymbolAddress((void**)&Vd, g_V);
    cudaGetSymbolAddress((void**)&Ahd, g_att_hi);
    cudaGetSymbolAddress((void**)&Ald, g_att_lo);
    cudaGetSymbolAddress((void**)&Hv, g_hi);
    cudaGetSymbolAddress((void**)&Lv, g_lo);

    cudaFuncSetAttribute(gemm3x, cudaFuncAttributeMaxDynamicSharedMemorySize, GSMEM_BYTES);
    cudaFuncSetAttribute(attn_mma, cudaFuncAttributeMaxDynamicSharedMemorySize, SMEM_ATTN);

    const int MQ = NH * DHD;    // 2048
    const int MKV = NKV * DHD;  // 1024

    // --- split all projection operands into tf32 hi/lo ---
    struct { const float* src; unsigned off; int n; } cv[10] = {
        { pg,  OFF_PG,  BB * L1C * DPG }, { ex,  OFF_EX,  BB * L2C * DEX },
        { Wq0, OFF_WQ0, MQ * DPG },       { Wk0, OFF_WK0, MKV * DPG },
        { Wv0, OFF_WV0, MKV * DPG },      { Wo0, OFF_WO0, DPG * MQ },
        { Wq1, OFF_WQ1, MQ * DEX },       { Wk1, OFF_WK1, MKV * DEX },
        { Wv1, OFF_WV1, MKV * DEX },      { Wo1, OFF_WO1, DEX * MQ },
    };
    for (int i = 0; i < 10; i++) {
        int n4 = cv[i].n / 4;
        cvt_split<<<(n4 + 255) / 256, 256>>>((const float4*)cv[i].src,
                                             (uint4*)(Hv + cv[i].off),
                                             (uint4*)(Lv + cv[i].off), n4);
    }

    // --- QKV projections, pg stream (M = 4096, K = 2304) ---
    gemm3x<<<dim3(MQ / 128, (BB * L1C) / 128), 256, GSMEM_BYTES>>>(
        Hv + OFF_PG, Lv + OFF_PG, Hv + OFF_WQ0, Lv + OFF_WQ0, Qd, DPG,
        BB * L1C, 0, 0, L1C, LT, 0, MQ);
    gemm3x<<<dim3(MKV / 128, (BB * L1C) / 128), 256, GSMEM_BYTES>>>(
        Hv + OFF_PG, Lv + OFF_PG, Hv + OFF_WK0, Lv + OFF_WK0, Kd, DPG,
        BB * L1C, 0, 0, L1C, LT, 0, MKV);
    gemm3x<<<dim3(MKV / 128, (BB * L1C) / 128), 256, GSMEM_BYTES>>>(
        Hv + OFF_PG, Lv + OFF_PG, Hv + OFF_WV0, Lv + OFF_WV0, Vd, DPG,
        BB * L1C, 0, 0, L1C, LT, 0, MKV);

    // --- QKV projections, ex stream (M = 2048, K = 1024) ---
    gemm3x<<<dim3(MQ / 128, (BB * L2C) / 128), 256, GSMEM_BYTES>>>(
        Hv + OFF_EX, Lv + OFF_EX, Hv + OFF_WQ1, Lv + OFF_WQ1, Qd, DEX,
        BB * L2C, 0, 0, L2C, LT, L1C, MQ);
    gemm3x<<<dim3(MKV / 128, (BB * L2C) / 128), 256, GSMEM_BYTES>>>(
        Hv + OFF_EX, Lv + OFF_EX, Hv + OFF_WK1, Lv + OFF_WK1, Kd, DEX,
        BB * L2C, 0, 0, L2C, LT, L1C, MKV);
    gemm3x<<<dim3(MKV / 128, (BB * L2C) / 128), 256, GSMEM_BYTES>>>(
        Hv + OFF_EX, Lv + OFF_EX, Hv + OFF_WV1, Lv + OFF_WV1, Vd, DEX,
        BB * L2C, 0, 0, L2C, LT, L1C, MKV);

    // --- RoPE (fold softmax scale into Q) ---
    rope_kernel<<<dim3(NH, LT, BB), DHD / 2>>>(Qd, cs, sn, NH, QK_SCALE);
    rope_kernel<<<dim3(NKV, LT, BB), DHD / 2>>>(Kd, cs, sn, NKV, 1.0f);

    // --- attention (tensor cores, emits hi/lo) ---
    attn_mma<<<dim3(LT / 64, NH, BB), 256, SMEM_ATTN>>>(mask);

    // --- output projections (consume attention hi/lo directly) ---
    gemm3x<<<dim3(DPG / 128, (BB * L1C) / 128), 256, GSMEM_BYTES>>>(
        (const unsigned*)Ahd, (const unsigned*)Ald,
        Hv + OFF_WO0, Lv + OFF_WO0, out, MQ,
        L1C, LT, 0, BB * L1C, 0, 0, DPG);
    gemm3x<<<dim3(DEX / 128, (BB * L2C) / 128), 256, GSMEM_BYTES>>>(
        (const unsigned*)Ahd, (const unsigned*)Ald,
        Hv + OFF_WO1, Lv + OFF_WO1, out + (size_t)BB * L1C * DPG, MQ,
        L2C, LT, L1C, BB * L2C, 0, 0, DEX);
}

// round 5
// speedup vs baseline: 1.5008x; 1.5008x over previous
#include <cuda_runtime.h>
#include <math.h>
#include <stdint.h>

#define BB   4
#define L1C  1024
#define L2C  512
#define LT   1536
#define DPG  2304
#define DEX  1024
#define NH   8
#define NKV  4
#define DHD  256
#define QK_SCALE 0.0625f

// ---------------- scratch (device globals; no allocation allowed) ----------
__device__ float g_Q[(size_t)BB * LT * NH * DHD];     // [b, l, h, d] fp32 (exact)
__device__ float g_K[(size_t)BB * LT * NKV * DHD];
__device__ float g_V[(size_t)BB * LT * NKV * DHD];
__device__ float g_att_hi[(size_t)BB * LT * NH * DHD];  // attention out, tf32 hi
__device__ float g_att_lo[(size_t)BB * LT * NH * DHD];  // attention out, tf32 lo

// tf32 hi/lo copies of GEMM operands
#define OFF_PG   0u
#define OFF_EX   9437184u
#define OFF_WQ0  11534336u
#define OFF_WK0  16252928u
#define OFF_WV0  18612224u
#define OFF_WO0  20971520u
#define OFF_WQ1  25690112u
#define OFF_WK1  27787264u
#define OFF_WV1  28835840u
#define OFF_WO1  29884416u
#define CVT_TOTAL 31981568u
__device__ unsigned g_hi[CVT_TOTAL];
__device__ unsigned g_lo[CVT_TOTAL];

// ---------------- tf32 helpers ----------------------------------------------
__device__ __forceinline__ unsigned rtf_u(float x)
{
    unsigned u;
    asm("cvt.rna.tf32.f32 %0, %1;" : "=r"(u) : "f"(x));
    return u;
}
__device__ __forceinline__ float rtf(float x) { return __uint_as_float(rtf_u(x)); }

// split conversion: hi = tf32(x), lo = tf32(x - hi)
__global__ void cvt_split(const float4* __restrict__ in, uint4* __restrict__ hi,
                          uint4* __restrict__ lo, int n4)
{
    int i = blockIdx.x * blockDim.x + threadIdx.x;
    if (i < n4) {
        float4 v = in[i];
        uint4 h, l;
        h.x = rtf_u(v.x); l.x = rtf_u(v.x - __uint_as_float(h.x));
        h.y = rtf_u(v.y); l.y = rtf_u(v.y - __uint_as_float(h.y));
        h.z = rtf_u(v.z); l.z = rtf_u(v.z - __uint_as_float(h.z));
        h.w = rtf_u(v.w); l.w = rtf_u(v.w - __uint_as_float(h.w));
        hi[i] = h; lo[i] = l;
    }
}

#define MMA_TF32(d, a, b)                                                     \
    asm volatile("mma.sync.aligned.m16n8k8.row.col.f32.tf32.tf32.f32 "        \
                 "{%0,%1,%2,%3}, {%4,%5,%6,%7}, {%8,%9}, {%0,%1,%2,%3};"      \
                 : "+f"(d[0]), "+f"(d[1]), "+f"(d[2]), "+f"(d[3])             \
                 : "r"(a[0]), "r"(a[1]), "r"(a[2]), "r"(a[3]),                \
                   "r"(b[0]), "r"(b[1]))

__device__ __forceinline__ void cpa16(uint32_t dst, const void* src)
{
    asm volatile("cp.async.cg.shared.global [%0], [%1], 16;" :: "r"(dst), "l"(src));
}

// ---------------- 3xTF32 NT GEMM (near-fp32 exact) ---------------------------
// C[m,n] = sum_k A[m,k]*W[n,k] with A = A_hi + A_lo, W = W_hi + W_lo (tf32 pairs)
// acc += A_lo*W_hi + A_hi*W_lo + A_hi*W_hi   (lo*lo dropped, ~2^-22)
#define GLDA 36
#define GBUF (128 * GLDA)
#define GSMEM_BYTES (8 * GBUF * 4)   // 2 stages x {A_hi, A_lo, W_hi, W_lo}

__global__ __launch_bounds__(256, 1) void gemm3x(
    const unsigned* __restrict__ Ah, const unsigned* __restrict__ Al,
    const unsigned* __restrict__ Wh, const unsigned* __restrict__ Wl,
    float* __restrict__ C, int K,
    int a_rpb, int a_bstride, int a_off,
    int c_rpb, int c_bstride, int c_off, int ldc)
{
    extern __shared__ unsigned smem[];

    const int tid    = threadIdx.x;
    const int wid    = tid >> 5;
    const int lane   = tid & 31;
    const int warp_m = wid >> 1;
    const int warp_n = wid & 1;
    const int bm = blockIdx.y * 128;
    const int bn = blockIdx.x * 128;

    const int lrow = tid >> 1;
    const int lcol = (tid & 1) * 16;
    const int am = bm + lrow;
    const int ar = (am / a_rpb) * a_bstride + a_off + (am % a_rpb);
    const size_t aoff = (size_t)ar * K + lcol;
    const size_t woff = (size_t)(bn + lrow) * K + lcol;

    const uint32_t sbase = (uint32_t)__cvta_generic_to_shared(smem);
    const uint32_t dst0 = sbase + (lrow * GLDA + lcol) * 4;

    float acc[2][8][4];
#pragma unroll
    for (int i = 0; i < 2; i++)
#pragma unroll
        for (int j = 0; j < 8; j++)
#pragma unroll
            for (int r = 0; r < 4; r++) acc[i][j][r] = 0.f;

    const int nk = K >> 5;
    const unsigned* srcs[4];

    // prologue: chunk 0 -> stage 0
    {
        const unsigned* s0 = Ah + aoff; const unsigned* s1 = Al + aoff;
        const unsigned* s2 = Wh + woff; const unsigned* s3 = Wl + woff;
        srcs[0] = s0; srcs[1] = s1; srcs[2] = s2; srcs[3] = s3;
#pragma unroll
        for (int t = 0; t < 4; t++)
#pragma unroll
            for (int j = 0; j < 4; j++)
                cpa16(dst0 + (t * GBUF) * 4 + j * 16, srcs[t] + j * 4);
        asm volatile("cp.async.commit_group;");
    }

    const int lr = lane >> 2;
    const int lc = lane & 3;

    for (int kc = 0; kc < nk; kc++) {
        const int cur = kc & 1;
        if (kc + 1 < nk) {
            const int nxt = (kc + 1) & 1;
            const int ko = (kc + 1) * 32;
            srcs[0] = Ah + aoff + ko; srcs[1] = Al + aoff + ko;
            srcs[2] = Wh + woff + ko; srcs[3] = Wl + woff + ko;
            const uint32_t db = dst0 + (nxt * 4 * GBUF) * 4;
#pragma unroll
            for (int t = 0; t < 4; t++)
#pragma unroll
                for (int j = 0; j < 4; j++)
                    cpa16(db + (t * GBUF) * 4 + j * 16, srcs[t] + j * 4);
            asm volatile("cp.async.commit_group;");
            asm volatile("cp.async.wait_group 1;");
        } else {
            asm volatile("cp.async.wait_group 0;");
        }
        __syncthreads();

        const unsigned* ash = smem + (cur * 4 + 0) * GBUF + (warp_m * 32 + lr) * GLDA + lc;
        const unsigned* asl = smem + (cur * 4 + 1) * GBUF + (warp_m * 32 + lr) * GLDA + lc;
        const unsigned* wsh = smem + (cur * 4 + 2) * GBUF + (warp_n * 64 + lr) * GLDA + lc;
        const unsigned* wsl = smem + (cur * 4 + 3) * GBUF + (warp_n * 64 + lr) * GLDA + lc;

#pragma unroll
        for (int ks = 0; ks < 4; ks++) {
            const int k0 = ks * 8;
            unsigned ah[2][4], al[2][4], bh[8][2], bl[8][2];
#pragma unroll
            for (int mf = 0; mf < 2; mf++) {
                const unsigned* ph = ash + mf * 16 * GLDA + k0;
                const unsigned* pl = asl + mf * 16 * GLDA + k0;
                ah[mf][0] = ph[0]; ah[mf][1] = ph[8 * GLDA];
                ah[mf][2] = ph[4]; ah[mf][3] = ph[8 * GLDA + 4];
                al[mf][0] = pl[0]; al[mf][1] = pl[8 * GLDA];
                al[mf][2] = pl[4]; al[mf][3] = pl[8 * GLDA + 4];
            }
#pragma unroll
            for (int nf = 0; nf < 8; nf++) {
                const unsigned* ph = wsh + nf * 8 * GLDA + k0;
                const unsigned* pl = wsl + nf * 8 * GLDA + k0;
                bh[nf][0] = ph[0]; bh[nf][1] = ph[4];
                bl[nf][0] = pl[0]; bl[nf][1] = pl[4];
            }
#pragma unroll
            for (int mf = 0; mf < 2; mf++)
#pragma unroll
                for (int nf = 0; nf < 8; nf++) {
                    MMA_TF32(acc[mf][nf], al[mf], bh[nf]);
                    MMA_TF32(acc[mf][nf], ah[mf], bl[nf]);
                    MMA_TF32(acc[mf][nf], ah[mf], bh[nf]);
                }
        }
        __syncthreads();
    }

#pragma unroll
    for (int mf = 0; mf < 2; mf++) {
        const int m0 = bm + warp_m * 32 + mf * 16 + lr;
        const int m1 = m0 + 8;
        const int r0 = (m0 / c_rpb) * c_bstride + c_off + (m0 % c_rpb);
        const int r1 = (m1 / c_rpb) * c_bstride + c_off + (m1 % c_rpb);
#pragma unroll
        for (int nf = 0; nf < 8; nf++) {
            const int col = bn + warp_n * 64 + nf * 8 + lc * 2;
            *(float2*)&C[(size_t)r0 * ldc + col] = make_float2(acc[mf][nf][0], acc[mf][nf][1]);
            *(float2*)&C[(size_t)r1 * ldc + col] = make_float2(acc[mf][nf][2], acc[mf][nf][3]);
        }
    }
}

// ---------------- RoPE (folds QK scale into Q) -------------------------------
__global__ void rope_kernel(float* __restrict__ X, const float* __restrict__ cs,
                            const float* __restrict__ sn, int nheads, float scale)
{
    const int h = blockIdx.x;
    const int l = blockIdx.y;
    const int b = blockIdx.z;
    const int i = threadIdx.x;
    const size_t row = (size_t)b * LT + l;
    const float c = cs[row * (DHD / 2) + i];
    const float s = sn[row * (DHD / 2) + i];
    const size_t base = (row * nheads + h) * DHD;
    const float x1 = X[base + i];
    const float x2 = X[base + (DHD / 2) + i];
    X[base + i]             = (x1 * c - x2 * s) * scale;
    X[base + (DHD / 2) + i] = (x2 * c + x1 * s) * scale;
}

// ---------------- tensor-core flash attention --------------------------------
// Block: (64-query tile, head, batch), 256 threads = 8 warps (wm 0..3, wn 0..1)
// smem strides chosen conflict-free: Q/K stride 268 (12*lr+lc spans 32 banks),
// V^T / S stride 68 (4*lr+lc spans 32 banks).
#define QKS 268
#define VTS 68
#define SS  68
#define SM_QS 0
#define SM_KS 17152
#define SM_VT 34304
#define SM_S  51712
#define SM_AL 56064
#define SM_LS 56128
#define SMEM_ATTN ((56192) * 4)

__global__ __launch_bounds__(256, 1) void attn_mma(const float* __restrict__ mask)
{
    extern __shared__ float sm[];
    float* Qs  = sm + SM_QS;
    float* Ks  = sm + SM_KS;
    float* VT  = sm + SM_VT;
    float* S   = sm + SM_S;
    float* Asc = sm + SM_AL;
    float* Lsc = sm + SM_LS;

    const int tid = threadIdx.x;
    const int qt = blockIdx.x;    // 0..23
    const int h  = blockIdx.y;
    const int b  = blockIdx.z;
    const int hkv = h >> 1;
    const int wid = tid >> 5, lane = tid & 31;
    const int wm = wid >> 1, wn = wid & 1;
    const int lr = lane >> 2, lc = lane & 3;
    const int srow = tid >> 2, spart = tid & 3;   // softmax: 4 threads / row

    // ---- stage Q (tf32-rounded; QK scale already folded by rope) ----
    for (int i = tid; i < 64 * 64; i += 256) {
        const int row = i >> 6, dq = i & 63;
        const float4 v = *(const float4*)&g_Q[((((size_t)b * LT + qt * 64 + row) * NH + h) * DHD) + dq * 4];
        float4 r = make_float4(rtf(v.x), rtf(v.y), rtf(v.z), rtf(v.w));
        *(float4*)&Qs[row * QKS + dq * 4] = r;
    }

    float accO[16][4];
#pragma unroll
    for (int i = 0; i < 16; i++)
#pragma unroll
        for (int j = 0; j < 4; j++) accO[i][j] = 0.f;
    float m_run = -1e30f, l_run = 0.f;

    for (int kt = 0; kt < LT / 64; kt++) {
        __syncthreads();  // prev PV/softmax done; smem free (covers Q staging too)
        // ---- stage K tile (rounded) ----
        for (int i = tid; i < 64 * 64; i += 256) {
            const int row = i >> 6, dq = i & 63;
            const float4 v = *(const float4*)&g_K[((((size_t)b * LT + kt * 64 + row) * NKV + hkv) * DHD) + dq * 4];
            float4 r = make_float4(rtf(v.x), rtf(v.y), rtf(v.z), rtf(v.w));
            *(float4*)&Ks[row * QKS + dq * 4] = r;
        }
        // ---- stage V^T (rounded): VT[d][key] ----
        for (int i = tid; i < 64 * 64; i += 256) {
            const int key = i & 63, dq = i >> 6;
            const float4 v = *(const float4*)&g_V[((((size_t)b * LT + kt * 64 + key) * NKV + hkv) * DHD) + dq * 4];
            VT[(dq * 4 + 0) * VTS + key] = rtf(v.x);
            VT[(dq * 4 + 1) * VTS + key] = rtf(v.y);
            VT[(dq * 4 + 2) * VTS + key] = rtf(v.z);
            VT[(dq * 4 + 3) * VTS + key] = rtf(v.w);
        }
        __syncthreads();

        // ---- S = Q K^T (warp tile 16x32, k = 256) ----
        float accS[4][4];
#pragma unroll
        for (int i = 0; i < 4; i++)
#pragma unroll
            for (int j = 0; j < 4; j++) accS[i][j] = 0.f;
        {
            const unsigned* qb = (const unsigned*)Qs + (wm * 16 + lr) * QKS + lc;
            const unsigned* kb = (const unsigned*)Ks + (wn * 32 + lr) * QKS + lc;
#pragma unroll 4
            for (int ks = 0; ks < 32; ks++) {
                const int k0 = ks * 8;
                unsigned a[4];
                a[0] = qb[k0]; a[1] = qb[8 * QKS + k0];
                a[2] = qb[k0 + 4]; a[3] = qb[8 * QKS + k0 + 4];
#pragma unroll
                for (int nf = 0; nf < 4; nf++) {
                    unsigned bfr[2];
                    const unsigned* p = kb + nf * 8 * QKS + k0;
                    bfr[0] = p[0]; bfr[1] = p[4];
                    MMA_TF32(accS[nf], a, bfr);
                }
            }
        }
        // ---- add mask, write S (fp32) ----
        {
            const size_t mrow0 = ((size_t)b * LT + qt * 64 + wm * 16 + lr) * LT + kt * 64 + wn * 32;
            const size_t mrow1 = mrow0 + (size_t)8 * LT;
#pragma unroll
            for (int nf = 0; nf < 4; nf++) {
                const int col = nf * 8 + lc * 2;
                const float2 m0 = *(const float2*)&mask[mrow0 + col];
                const float2 m1 = *(const float2*)&mask[mrow1 + col];
                *(float2*)&S[(wm * 16 + lr) * SS + wn * 32 + col] =
                    make_float2(accS[nf][0] + m0.x, accS[nf][1] + m0.y);
                *(float2*)&S[(wm * 16 + lr + 8) * SS + wn * 32 + col] =
                    make_float2(accS[nf][2] + m1.x, accS[nf][3] + m1.y);
            }
        }
        __syncthreads();

        // ---- online softmax (4 threads per row, 16 cols each) ----
        {
            float* sp = S + srow * SS + spart * 16;
            float lm = -1e30f;
#pragma unroll
            for (int j = 0; j < 16; j++) lm = fmaxf(lm, sp[j]);
            lm = fmaxf(lm, __shfl_xor_sync(0xffffffffu, lm, 1));
            lm = fmaxf(lm, __shfl_xor_sync(0xffffffffu, lm, 2));
            const float mnew = fmaxf(m_run, lm);
            const float alpha = __expf(m_run - mnew);
            float ls = 0.f;
#pragma unroll
            for (int j = 0; j < 16; j++) {
                const float p = __expf(sp[j] - mnew);
                ls += p;
                sp[j] = rtf(p);   // P as tf32 for PV mma
            }
            ls += __shfl_xor_sync(0xffffffffu, ls, 1);
            ls += __shfl_xor_sync(0xffffffffu, ls, 2);
            l_run = l_run * alpha + ls;
            m_run = mnew;
            if (spart == 0) Asc[srow] = alpha;
        }
        __syncthreads();

        // ---- rescale O, then O += P V (warp tile 16x128, k = 64) ----
        {
            const float a0 = Asc[wm * 16 + lr];
            const float a1 = Asc[wm * 16 + lr + 8];
#pragma unroll
            for (int nf = 0; nf < 16; nf++) {
                accO[nf][0] *= a0; accO[nf][1] *= a0;
                accO[nf][2] *= a1; accO[nf][3] *= a1;
            }
            const unsigned* pb = (const unsigned*)S + (wm * 16 + lr) * SS + lc;
            const unsigned* vb = (const unsigned*)VT + (wn * 128 + lr) * VTS + lc;
#pragma unroll
            for (int ks = 0; ks < 8; ks++) {
                const int k0 = ks * 8;
                unsigned a[4];
                a[0] = pb[k0]; a[1] = pb[8 * SS + k0];
                a[2] = pb[k0 + 4]; a[3] = pb[8 * SS + k0 + 4];
#pragma unroll
                for (int nf = 0; nf < 16; nf++) {
                    unsigned bfr[2];
                    const unsigned* p = vb + nf * 8 * VTS + k0;
                    bfr[0] = p[0]; bfr[1] = p[4];
                    MMA_TF32(accO[nf], a, bfr);
                }
            }
        }
    }

    if (spart == 0) Lsc[srow] = l_run;
    __syncthreads();

    // ---- epilogue: normalize, emit tf32 hi/lo for out-projection ----
    {
        const float il0 = 1.f / Lsc[wm * 16 + lr];
        const float il1 = 1.f / Lsc[wm * 16 + lr + 8];
        const size_t r0 = (size_t)b * LT + qt * 64 + wm * 16 + lr;
        const size_t r1 = r0 + 8;
#pragma unroll
        for (int nf = 0; nf < 16; nf++) {
            const int col = h * DHD + wn * 128 + nf * 8 + lc * 2;
            float v0 = accO[nf][0] * il0, v1 = accO[nf][1] * il0;
            float v2 = accO[nf][2] * il1, v3 = accO[nf][3] * il1;
            float h0 = rtf(v0), h1 = rtf(v1), h2 = rtf(v2), h3 = rtf(v3);
            *(float2*)&g_att_hi[r0 * (NH * DHD) + col] = make_float2(h0, h1);
            *(float2*)&g_att_hi[r1 * (NH * DHD) + col] = make_float2(h2, h3);
            *(float2*)&g_att_lo[r0 * (NH * DHD) + col] = make_float2(rtf(v0 - h0), rtf(v1 - h1));
            *(float2*)&g_att_lo[r1 * (NH * DHD) + col] = make_float2(rtf(v2 - h2), rtf(v3 - h3));
        }
    }
}

// ---------------- launch ----------------------------------------------------
extern "C" void kernel_launch(void* const* d_in, const int* in_sizes, int n_in,
                              void* d_out, int out_size)
{
    const float* pg   = (const float*)d_in[0];
    const float* ex   = (const float*)d_in[1];
    const float* cs   = (const float*)d_in[2];
    const float* sn   = (const float*)d_in[3];
    const float* mask = (const float*)d_in[4];
    const float* Wq0  = (const float*)d_in[5];
    const float* Wk0  = (const float*)d_in[6];
    const float* Wv0  = (const float*)d_in[7];
    const float* Wo0  = (const float*)d_in[8];
    const float* Wq1  = (const float*)d_in[9];
    const float* Wk1  = (const float*)d_in[10];
    const float* Wv1  = (const float*)d_in[11];
    const float* Wo1  = (const float*)d_in[12];
    float* out = (float*)d_out;

    float *Qd, *Kd, *Vd, *Ahd, *Ald;
    unsigned *Hv, *Lv;
    cudaGetSymbolAddress((void**)&Qd, g_Q);
    cudaGetSymbolAddress((void**)&Kd, g_K);
    cudaGetSymbolAddress((void**)&Vd, g_V);
    cudaGetSymbolAddress((void**)&Ahd, g_att_hi);
    cudaGetSymbolAddress((void**)&Ald, g_att_lo);
    cudaGetSymbolAddress((void**)&Hv, g_hi);
    cudaGetSymbolAddress((void**)&Lv, g_lo);

    cudaFuncSetAttribute(gemm3x, cudaFuncAttributeMaxDynamicSharedMemorySize, GSMEM_BYTES);
    cudaFuncSetAttribute(attn_mma, cudaFuncAttributeMaxDynamicSharedMemorySize, SMEM_ATTN);

    const int MQ = NH * DHD;    // 2048
    const int MKV = NKV * DHD;  // 1024

    // --- split all projection operands into tf32 hi/lo ---
    struct { const float* src; unsigned off; int n; } cv[10] = {
        { pg,  OFF_PG,  BB * L1C * DPG }, { ex,  OFF_EX,  BB * L2C * DEX },
        { Wq0, OFF_WQ0, MQ * DPG },       { Wk0, OFF_WK0, MKV * DPG },
        { Wv0, OFF_WV0, MKV * DPG },      { Wo0, OFF_WO0, DPG * MQ },
        { Wq1, OFF_WQ1, MQ * DEX },       { Wk1, OFF_WK1, MKV * DEX },
        { Wv1, OFF_WV1, MKV * DEX },      { Wo1, OFF_WO1, DEX * MQ },
    };
    for (int i = 0; i < 10; i++) {
        int n4 = cv[i].n / 4;
        cvt_split<<<(n4 + 255) / 256, 256>>>((const float4*)cv[i].src,
                                             (uint4*)(Hv + cv[i].off),
                                             (uint4*)(Lv + cv[i].off), n4);
    }

    // --- QKV projections, pg stream (M = 4096, K = 2304) ---
    gemm3x<<<dim3(MQ / 128, (BB * L1C) / 128), 256, GSMEM_BYTES>>>(
        Hv + OFF_PG, Lv + OFF_PG, Hv + OFF_WQ0, Lv + OFF_WQ0, Qd, DPG,
        BB * L1C, 0, 0, L1C, LT, 0, MQ);
    gemm3x<<<dim3(MKV / 128, (BB * L1C) / 128), 256, GSMEM_BYTES>>>(
        Hv + OFF_PG, Lv + OFF_PG, Hv + OFF_WK0, Lv + OFF_WK0, Kd, DPG,
        BB * L1C, 0, 0, L1C, LT, 0, MKV);
    gemm3x<<<dim3(MKV / 128, (BB * L1C) / 128), 256, GSMEM_BYTES>>>(
        Hv + OFF_PG, Lv + OFF_PG, Hv + OFF_WV0, Lv + OFF_WV0, Vd, DPG,
        BB * L1C, 0, 0, L1C, LT, 0, MKV);

    // --- QKV projections, ex stream (M = 2048, K = 1024) ---
    gemm3x<<<dim3(MQ / 128, (BB * L2C) / 128), 256, GSMEM_BYTES>>>(
        Hv + OFF_EX, Lv + OFF_EX, Hv + OFF_WQ1, Lv + OFF_WQ1, Qd, DEX,
        BB * L2C, 0, 0, L2C, LT, L1C, MQ);
    gemm3x<<<dim3(MKV / 128, (BB * L2C) / 128), 256, GSMEM_BYTES>>>(
        Hv + OFF_EX, Lv + OFF_EX, Hv + OFF_WK1, Lv + OFF_WK1, Kd, DEX,
        BB * L2C, 0, 0, L2C, LT, L1C, MKV);
    gemm3x<<<dim3(MKV / 128, (BB * L2C) / 128), 256, GSMEM_BYTES>>>(
        Hv + OFF_EX, Lv + OFF_EX, Hv + OFF_WV1, Lv + OFF_WV1, Vd, DEX,
        BB * L2C, 0, 0, L2C, LT, L1C, MKV);

    // --- RoPE (fold softmax scale into Q) ---
    rope_kernel<<<dim3(NH, LT, BB), DHD / 2>>>(Qd, cs, sn, NH, QK_SCALE);
    rope_kernel<<<dim3(NKV, LT, BB), DHD / 2>>>(Kd, cs, sn, NKV, 1.0f);

    // --- attention (tensor cores, emits hi/lo) ---
    attn_mma<<<dim3(LT / 64, NH, BB), 256, SMEM_ATTN>>>(mask);

    // --- output projections (consume attention hi/lo directly) ---
    gemm3x<<<dim3(DPG / 128, (BB * L1C) / 128), 256, GSMEM_BYTES>>>(
        (const unsigned*)Ahd, (const unsigned*)Ald,
        Hv + OFF_WO0, Lv + OFF_WO0, out, MQ,
        L1C, LT, 0, BB * L1C, 0, 0, DPG);
    gemm3x<<<dim3(DEX / 128, (BB * L2C) / 128), 256, GSMEM_BYTES>>>(
        (const unsigned*)Ahd, (const unsigned*)Ald,
        Hv + OFF_WO1, Lv + OFF_WO1, out + (size_t)BB * L1C * DPG, MQ,
        L2C, LT, L1C, BB * L2C, 0, 0, DEX);
}

// round 6
// speedup vs baseline: 2.1980x; 1.4646x over previous
#include <cuda_runtime.h>
#include <cuda_bf16.h>
#include <math.h>
#include <stdint.h>

#define BB   4
#define L1C  1024
#define L2C  512
#define LT   1536
#define DPG  2304
#define DEX  1024
#define NH   8
#define NKV  4
#define DHD  256
#define QK_SCALE 0.0625f

// logical u32 j (0..7) within a k16 group -> stored position (pairs 2lc,2lc+1)
#define PERM8(j) ((((j) & 3) << 1) | ((j) >> 2))

// ---------------- scratch (device globals; no allocation allowed) ----------
__device__ float g_Q[(size_t)BB * LT * NH * DHD];    // fp32 QKV-proj outputs
__device__ float g_K[(size_t)BB * LT * NKV * DHD];
__device__ float g_V[(size_t)BB * LT * NKV * DHD];

// attention output as packed bf16x2 hi/lo planes (A operand of out-proj)
__device__ uint32_t g_ahi[(size_t)BB * LT * NH * 128];
__device__ uint32_t g_alo[(size_t)BB * LT * NH * 128];

// bf16 hi/lo planes of the 10 projection operands (u32 = bf16x2 along k)
#define OP_PG   0u
#define OP_EX   4718592u
#define OP_WQ0  5767168u
#define OP_WK0  8126464u
#define OP_WV0  9306112u
#define OP_WO0  10485760u
#define OP_WQ1  12845056u
#define OP_WK1  13893632u
#define OP_WV1  14417920u
#define OP_WO1  14942208u
#define OP_TOT  15990784u
__device__ uint32_t g_hi[OP_TOT];
__device__ uint32_t g_lo[OP_TOT];

// ---------------- helpers ----------------------------------------------------
__device__ __forceinline__ float rtf(float x)
{
    unsigned u;
    asm("cvt.rna.tf32.f32 %0, %1;" : "=r"(u) : "f"(x));
    return __uint_as_float(u);
}
__device__ __forceinline__ uint32_t pack_bf(float a, float b)
{
    __nv_bfloat162 t = __floats2bfloat162_rn(a, b);
    return *(uint32_t*)&t;
}
__device__ __forceinline__ void cpa16(uint32_t dst, const void* src)
{
    asm volatile("cp.async.cg.shared.global [%0], [%1], 16;" :: "r"(dst), "l"(src));
}

#define MMA_BF16(d, a, b)                                                     \
    asm volatile("mma.sync.aligned.m16n8k16.row.col.f32.bf16.bf16.f32 "       \
                 "{%0,%1,%2,%3}, {%4,%5,%6,%7}, {%8,%9}, {%0,%1,%2,%3};"      \
                 : "+f"(d[0]), "+f"(d[1]), "+f"(d[2]), "+f"(d[3])             \
                 : "r"(a[0]), "r"(a[1]), "r"(a[2]), "r"(a[3]),                \
                   "r"(b[0]), "r"(b[1]))

#define MMA_TF32(d, a, b)                                                     \
    asm volatile("mma.sync.aligned.m16n8k8.row.col.f32.tf32.tf32.f32 "        \
                 "{%0,%1,%2,%3}, {%4,%5,%6,%7}, {%8,%9}, {%0,%1,%2,%3};"      \
                 : "+f"(d[0]), "+f"(d[1]), "+f"(d[2]), "+f"(d[3])             \
                 : "r"(a[0]), "r"(a[1]), "r"(a[2]), "r"(a[3]),                \
                   "r"(b[0]), "r"(b[1]))

// ---------------- fused bf16-split conversion (one launch, 10 operands) ------
struct CvtArgs {
    const float* src[10];
    uint32_t off[10];
    int n16[10];     // number of 16-element groups
};

__global__ void cvt_bsplit(CvtArgs a)
{
    const int e = blockIdx.y;
    const int i = blockIdx.x * blockDim.x + threadIdx.x;
    if (i >= a.n16[e]) return;
    const float4* s = (const float4*)(a.src[e]) + (size_t)i * 4;
    uint32_t* hb = g_hi + a.off[e] + (size_t)i * 8;
    uint32_t* lb = g_lo + a.off[e] + (size_t)i * 8;
    float v[16];
#pragma unroll
    for (int q = 0; q < 4; q++) {
        float4 f = s[q];
        v[q * 4 + 0] = f.x; v[q * 4 + 1] = f.y; v[q * 4 + 2] = f.z; v[q * 4 + 3] = f.w;
    }
#pragma unroll
    for (int j = 0; j < 8; j++) {
        const float x0 = v[2 * j], x1 = v[2 * j + 1];
        const float h0 = __bfloat162float(__float2bfloat16_rn(x0));
        const float h1 = __bfloat162float(__float2bfloat16_rn(x1));
        const int p = PERM8(j);
        hb[p] = pack_bf(h0, h1);
        lb[p] = pack_bf(x0 - h0, x1 - h1);
    }
}

// ---------------- bf16x3 NT GEMM ---------------------------------------------
// C[m,n] = sum_k A[m,k]*W[n,k]; operands are permuted bf16x2 hi/lo planes.
// Block 128x128, k-chunk 64 elems (32 u32), 8 warps (32x64), 2-stage cp.async.
#define GS 40                      // smem row stride in u32
#define GB (128 * GS)
#define GSM_BYTES (8 * GB * 4)     // 2 stages x {Ah, Al, Wh, Wl}

__global__ __launch_bounds__(256, 1) void gemm_b3(
    const uint32_t* __restrict__ Ah, const uint32_t* __restrict__ Al,
    const uint32_t* __restrict__ Wh, const uint32_t* __restrict__ Wl,
    float* __restrict__ C, int K2,
    int a_rpb, int a_bs, int a_off,
    int c_rpb, int c_bs, int c_off, int ldc)
{
    extern __shared__ uint32_t smg[];
    const int tid = threadIdx.x;
    const int wid = tid >> 5, lane = tid & 31;
    const int warp_m = wid >> 1, warp_n = wid & 1;
    const int bm = blockIdx.y * 128, bn = blockIdx.x * 128;

    const int lrow = tid >> 1, half = tid & 1;
    const int am = bm + lrow;
    const int ar = (am / a_rpb) * a_bs + a_off + (am % a_rpb);
    const size_t aoff = (size_t)ar * K2 + half * 16;
    const size_t woff = (size_t)(bn + lrow) * K2 + half * 16;
    const uint32_t* src[4] = { Ah + aoff, Al + aoff, Wh + woff, Wl + woff };

    const uint32_t sbase = (uint32_t)__cvta_generic_to_shared(smg);
    const uint32_t dst0 = sbase + (lrow * GS + half * 16) * 4;

    float acc[2][8][4];
#pragma unroll
    for (int i = 0; i < 2; i++)
#pragma unroll
        for (int j = 0; j < 8; j++)
#pragma unroll
            for (int r = 0; r < 4; r++) acc[i][j][r] = 0.f;

    const int nk = K2 >> 5;

    {
#pragma unroll
        for (int p = 0; p < 4; p++)
#pragma unroll
            for (int j = 0; j < 4; j++)
                cpa16(dst0 + (p * GB) * 4 + j * 16, src[p] + j * 4);
        asm volatile("cp.async.commit_group;");
    }

    const int lr = lane >> 2, lc = lane & 3;

    for (int kc = 0; kc < nk; kc++) {
        const int cur = kc & 1;
        if (kc + 1 < nk) {
            const int ko = (kc + 1) * 32;
            const uint32_t db = dst0 + (((kc + 1) & 1) * 4 * GB) * 4;
#pragma unroll
            for (int p = 0; p < 4; p++)
#pragma unroll
                for (int j = 0; j < 4; j++)
                    cpa16(db + (p * GB) * 4 + j * 16, src[p] + ko + j * 4);
            asm volatile("cp.async.commit_group;");
            asm volatile("cp.async.wait_group 1;");
        } else {
            asm volatile("cp.async.wait_group 0;");
        }
        __syncthreads();

        const uint32_t* ashp = smg + (cur * 4 + 0) * GB + (warp_m * 32 + lr) * GS + 2 * lc;
        const uint32_t* aslp = smg + (cur * 4 + 1) * GB + (warp_m * 32 + lr) * GS + 2 * lc;
        const uint32_t* wshp = smg + (cur * 4 + 2) * GB + (warp_n * 64 + lr) * GS + 2 * lc;
        const uint32_t* wslp = smg + (cur * 4 + 3) * GB + (warp_n * 64 + lr) * GS + 2 * lc;

#pragma unroll
        for (int ks = 0; ks < 4; ks++) {
            const int k8 = ks * 8;
            uint32_t ah[2][4], al[2][4], bh[8][2], bl[8][2];
            uint2 t;
#pragma unroll
            for (int mf = 0; mf < 2; mf++) {
                t = *(const uint2*)(ashp + mf * 16 * GS + k8);           ah[mf][0] = t.x; ah[mf][2] = t.y;
                t = *(const uint2*)(ashp + mf * 16 * GS + 8 * GS + k8);  ah[mf][1] = t.x; ah[mf][3] = t.y;
                t = *(const uint2*)(aslp + mf * 16 * GS + k8);           al[mf][0] = t.x; al[mf][2] = t.y;
                t = *(const uint2*)(aslp + mf * 16 * GS + 8 * GS + k8);  al[mf][1] = t.x; al[mf][3] = t.y;
            }
#pragma unroll
            for (int nf = 0; nf < 8; nf++) {
                t = *(const uint2*)(wshp + nf * 8 * GS + k8);  bh[nf][0] = t.x; bh[nf][1] = t.y;
                t = *(const uint2*)(wslp + nf * 8 * GS + k8);  bl[nf][0] = t.x; bl[nf][1] = t.y;
            }
#pragma unroll
            for (int mf = 0; mf < 2; mf++)
#pragma unroll
                for (int nf = 0; nf < 8; nf++) {
                    MMA_BF16(acc[mf][nf], al[mf], bh[nf]);
                    MMA_BF16(acc[mf][nf], ah[mf], bl[nf]);
                    MMA_BF16(acc[mf][nf], ah[mf], bh[nf]);
                }
        }
        __syncthreads();
    }

#pragma unroll
    for (int mf = 0; mf < 2; mf++) {
        const int m0 = bm + warp_m * 32 + mf * 16 + lr;
        const int m1 = m0 + 8;
        const int r0 = (m0 / c_rpb) * c_bs + c_off + (m0 % c_rpb);
        const int r1 = (m1 / c_rpb) * c_bs + c_off + (m1 % c_rpb);
#pragma unroll
        for (int nf = 0; nf < 8; nf++) {
            const int col = bn + warp_n * 64 + nf * 8 + lc * 2;
            *(float2*)&C[(size_t)r0 * ldc + col] = make_float2(acc[mf][nf][0], acc[mf][nf][1]);
            *(float2*)&C[(size_t)r1 * ldc + col] = make_float2(acc[mf][nf][2], acc[mf][nf][3]);
        }
    }
}

// ---------------- RoPE (folds QK scale into Q) -------------------------------
__global__ void rope_kernel(float* __restrict__ X, const float* __restrict__ cs,
                            const float* __restrict__ sn, int nheads, float scale)
{
    const int h = blockIdx.x;
    const int l = blockIdx.y;
    const int b = blockIdx.z;
    const int i = threadIdx.x;
    const size_t row = (size_t)b * LT + l;
    const float c = cs[row * (DHD / 2) + i];
    const float s = sn[row * (DHD / 2) + i];
    const size_t base = (row * nheads + h) * DHD;
    const float x1 = X[base + i];
    const float x2 = X[base + (DHD / 2) + i];
    X[base + i]             = (x1 * c - x2 * s) * scale;
    X[base + (DHD / 2) + i] = (x2 * c + x1 * s) * scale;
}

// ---------------- tensor-core flash attention (tf32) -------------------------
#define QKS 268
#define VTS 68
#define SS  68
#define SM_QS 0
#define SM_KS 17152
#define SM_VT 34304
#define SM_S  51712
#define SM_AL 56064
#define SM_LS 56128
#define SMEM_ATTN ((56192) * 4)

__global__ __launch_bounds__(256, 1) void attn_mma(const float* __restrict__ mask)
{
    extern __shared__ float sm[];
    float* Qs  = sm + SM_QS;
    float* Ks  = sm + SM_KS;
    float* VT  = sm + SM_VT;
    float* S   = sm + SM_S;
    float* Asc = sm + SM_AL;
    float* Lsc = sm + SM_LS;

    const int tid = threadIdx.x;
    const int qt = blockIdx.x;
    const int h  = blockIdx.y;
    const int b  = blockIdx.z;
    const int hkv = h >> 1;
    const int wid = tid >> 5, lane = tid & 31;
    const int wm = wid >> 1, wn = wid & 1;
    const int lr = lane >> 2, lc = lane & 3;
    const int srow = tid >> 2, spart = tid & 3;

    for (int i = tid; i < 64 * 64; i += 256) {
        const int row = i >> 6, dq = i & 63;
        const float4 v = *(const float4*)&g_Q[((((size_t)b * LT + qt * 64 + row) * NH + h) * DHD) + dq * 4];
        *(float4*)&Qs[row * QKS + dq * 4] = make_float4(rtf(v.x), rtf(v.y), rtf(v.z), rtf(v.w));
    }

    float accO[16][4];
#pragma unroll
    for (int i = 0; i < 16; i++)
#pragma unroll
        for (int j = 0; j < 4; j++) accO[i][j] = 0.f;
    float m_run = -1e30f, l_run = 0.f;

    for (int kt = 0; kt < LT / 64; kt++) {
        __syncthreads();
        for (int i = tid; i < 64 * 64; i += 256) {
            const int row = i >> 6, dq = i & 63;
            const float4 v = *(const float4*)&g_K[((((size_t)b * LT + kt * 64 + row) * NKV + hkv) * DHD) + dq * 4];
            *(float4*)&Ks[row * QKS + dq * 4] = make_float4(rtf(v.x), rtf(v.y), rtf(v.z), rtf(v.w));
        }
        for (int i = tid; i < 64 * 64; i += 256) {
            const int key = i & 63, dq = i >> 6;
            const float4 v = *(const float4*)&g_V[((((size_t)b * LT + kt * 64 + key) * NKV + hkv) * DHD) + dq * 4];
            VT[(dq * 4 + 0) * VTS + key] = rtf(v.x);
            VT[(dq * 4 + 1) * VTS + key] = rtf(v.y);
            VT[(dq * 4 + 2) * VTS + key] = rtf(v.z);
            VT[(dq * 4 + 3) * VTS + key] = rtf(v.w);
        }
        __syncthreads();

        float accS[4][4];
#pragma unroll
        for (int i = 0; i < 4; i++)
#pragma unroll
            for (int j = 0; j < 4; j++) accS[i][j] = 0.f;
        {
            const unsigned* qb = (const unsigned*)Qs + (wm * 16 + lr) * QKS + lc;
            const unsigned* kb = (const unsigned*)Ks + (wn * 32 + lr) * QKS + lc;
#pragma unroll 4
            for (int ks = 0; ks < 32; ks++) {
                const int k0 = ks * 8;
                unsigned a[4];
                a[0] = qb[k0]; a[1] = qb[8 * QKS + k0];
                a[2] = qb[k0 + 4]; a[3] = qb[8 * QKS + k0 + 4];
#pragma unroll
                for (int nf = 0; nf < 4; nf++) {
                    unsigned bfr[2];
                    const unsigned* p = kb + nf * 8 * QKS + k0;
                    bfr[0] = p[0]; bfr[1] = p[4];
                    MMA_TF32(accS[nf], a, bfr);
                }
            }
        }
        {
            const size_t mrow0 = ((size_t)b * LT + qt * 64 + wm * 16 + lr) * LT + kt * 64 + wn * 32;
            const size_t mrow1 = mrow0 + (size_t)8 * LT;
#pragma unroll
            for (int nf = 0; nf < 4; nf++) {
                const int col = nf * 8 + lc * 2;
                const float2 m0 = *(const float2*)&mask[mrow0 + col];
                const float2 m1 = *(const float2*)&mask[mrow1 + col];
                *(float2*)&S[(wm * 16 + lr) * SS + wn * 32 + col] =
                    make_float2(accS[nf][0] + m0.x, accS[nf][1] + m0.y);
                *(float2*)&S[(wm * 16 + lr + 8) * SS + wn * 32 + col] =
                    make_float2(accS[nf][2] + m1.x, accS[nf][3] + m1.y);
            }
        }
        __syncthreads();

        {
            float* sp = S + srow * SS + spart * 16;
            float lm = -1e30f;
#pragma unroll
            for (int j = 0; j < 16; j++) lm = fmaxf(lm, sp[j]);
            lm = fmaxf(lm, __shfl_xor_sync(0xffffffffu, lm, 1));
            lm = fmaxf(lm, __shfl_xor_sync(0xffffffffu, lm, 2));
            const float mnew = fmaxf(m_run, lm);
            const float alpha = __expf(m_run - mnew);
            float ls = 0.f;
#pragma unroll
            for (int j = 0; j < 16; j++) {
                const float p = __expf(sp[j] - mnew);
                ls += p;
                sp[j] = rtf(p);
            }
            ls += __shfl_xor_sync(0xffffffffu, ls, 1);
            ls += __shfl_xor_sync(0xffffffffu, ls, 2);
            l_run = l_run * alpha + ls;
            m_run = mnew;
            if (spart == 0) Asc[srow] = alpha;
        }
        __syncthreads();

        {
            const float a0 = Asc[wm * 16 + lr];
            const float a1 = Asc[wm * 16 + lr + 8];
#pragma unroll
            for (int nf = 0; nf < 16; nf++) {
                accO[nf][0] *= a0; accO[nf][1] *= a0;
                accO[nf][2] *= a1; accO[nf][3] *= a1;
            }
            const unsigned* pb = (const unsigned*)S + (wm * 16 + lr) * SS + lc;
            const unsigned* vb = (const unsigned*)VT + (wn * 128 + lr) * VTS + lc;
#pragma unroll
            for (int ks = 0; ks < 8; ks++) {
                const int k0 = ks * 8;
                unsigned a[4];
                a[0] = pb[k0]; a[1] = pb[8 * SS + k0];
                a[2] = pb[k0 + 4]; a[3] = pb[8 * SS + k0 + 4];
#pragma unroll
                for (int nf = 0; nf < 16; nf++) {
                    unsigned bfr[2];
                    const unsigned* p = vb + nf * 8 * VTS + k0;
                    bfr[0] = p[0]; bfr[1] = p[4];
                    MMA_TF32(accO[nf], a, bfr);
                }
            }
        }
    }

    if (spart == 0) Lsc[srow] = l_run;
    __syncthreads();

    // ---- epilogue: normalize, emit packed bf16 hi/lo planes (permuted) ----
    {
        const float il0 = 1.f / Lsc[wm * 16 + lr];
        const float il1 = 1.f / Lsc[wm * 16 + lr + 8];
        const size_t r0 = (size_t)b * LT + qt * 64 + wm * 16 + lr;
        const size_t r1 = r0 + 8;
#pragma unroll
        for (int nf = 0; nf < 16; nf++) {
            const int p = h * 128 + wn * 64 + nf * 4 + lc;   // u32 pair index
            const int pos = (p & ~7) | PERM8(p & 7);
            const float v0 = accO[nf][0] * il0, v1 = accO[nf][1] * il0;
            const float v2 = accO[nf][2] * il1, v3 = accO[nf][3] * il1;
            const float h0 = __bfloat162float(__float2bfloat16_rn(v0));
            const float h1 = __bfloat162float(__float2bfloat16_rn(v1));
            const float h2 = __bfloat162float(__float2bfloat16_rn(v2));
            const float h3 = __bfloat162float(__float2bfloat16_rn(v3));
            g_ahi[r0 * 1024 + pos] = pack_bf(h0, h1);
            g_alo[r0 * 1024 + pos] = pack_bf(v0 - h0, v1 - h1);
            g_ahi[r1 * 1024 + pos] = pack_bf(h2, h3);
            g_alo[r1 * 1024 + pos] = pack_bf(v2 - h2, v3 - h3);
        }
    }
}

// ---------------- launch ----------------------------------------------------
extern "C" void kernel_launch(void* const* d_in, const int* in_sizes, int n_in,
                              void* d_out, int out_size)
{
    const float* pg   = (const float*)d_in[0];
    const float* ex   = (const float*)d_in[1];
    const float* cs   = (const float*)d_in[2];
    const float* sn   = (const float*)d_in[3];
    const float* mask = (const float*)d_in[4];
    const float* Wq0  = (const float*)d_in[5];
    const float* Wk0  = (const float*)d_in[6];
    const float* Wv0  = (const float*)d_in[7];
    const float* Wo0  = (const float*)d_in[8];
    const float* Wq1  = (const float*)d_in[9];
    const float* Wk1  = (const float*)d_in[10];
    const float* Wv1  = (const float*)d_in[11];
    const float* Wo1  = (const float*)d_in[12];
    float* out = (float*)d_out;

    float *Qd, *Kd, *Vd;
    uint32_t *Ahd, *Ald, *Hv, *Lv;
    cudaGetSymbolAddress((void**)&Qd, g_Q);
    cudaGetSymbolAddress((void**)&Kd, g_K);
    cudaGetSymbolAddress((void**)&Vd, g_V);
    cudaGetSymbolAddress((void**)&Ahd, g_ahi);
    cudaGetSymbolAddress((void**)&Ald, g_alo);
    cudaGetSymbolAddress((void**)&Hv, g_hi);
    cudaGetSymbolAddress((void**)&Lv, g_lo);

    cudaFuncSetAttribute(gemm_b3, cudaFuncAttributeMaxDynamicSharedMemorySize, GSM_BYTES);
    cudaFuncSetAttribute(attn_mma, cudaFuncAttributeMaxDynamicSharedMemorySize, SMEM_ATTN);

    const int MQ = NH * DHD;    // 2048
    const int MKV = NKV * DHD;  // 1024

    // --- split all projection operands into permuted bf16 hi/lo planes ---
    CvtArgs ca;
    const float* srcs[10] = { pg, ex, Wq0, Wk0, Wv0, Wo0, Wq1, Wk1, Wv1, Wo1 };
    const uint32_t offs[10] = { OP_PG, OP_EX, OP_WQ0, OP_WK0, OP_WV0,
                                OP_WO0, OP_WQ1, OP_WK1, OP_WV1, OP_WO1 };
    const int ns[10] = { BB * L1C * DPG, BB * L2C * DEX, MQ * DPG, MKV * DPG,
                         MKV * DPG, DPG * MQ, MQ * DEX, MKV * DEX, MKV * DEX, DEX * MQ };
    int maxg = 0;
    for (int i = 0; i < 10; i++) {
        ca.src[i] = srcs[i]; ca.off[i] = offs[i]; ca.n16[i] = ns[i] / 16;
        if (ca.n16[i] > maxg) maxg = ca.n16[i];
    }
    cvt_bsplit<<<dim3((maxg + 255) / 256, 10), 256>>>(ca);

    // --- QKV projections, pg stream (K2 = 1152) ---
    gemm_b3<<<dim3(MQ / 128, (BB * L1C) / 128), 256, GSM_BYTES>>>(
        Hv + OP_PG, Lv + OP_PG, Hv + OP_WQ0, Lv + OP_WQ0, Qd, DPG / 2,
        BB * L1C, 0, 0, L1C, LT, 0, MQ);
    gemm_b3<<<dim3(MKV / 128, (BB * L1C) / 128), 256, GSM_BYTES>>>(
        Hv + OP_PG, Lv + OP_PG, Hv + OP_WK0, Lv + OP_WK0, Kd, DPG / 2,
        BB * L1C, 0, 0, L1C, LT, 0, MKV);
    gemm_b3<<<dim3(MKV / 128, (BB * L1C) / 128), 256, GSM_BYTES>>>(
        Hv + OP_PG, Lv + OP_PG, Hv + OP_WV0, Lv + OP_WV0, Vd, DPG / 2,
        BB * L1C, 0, 0, L1C, LT, 0, MKV);

    // --- QKV projections, ex stream (K2 = 512) ---
    gemm_b3<<<dim3(MQ / 128, (BB * L2C) / 128), 256, GSM_BYTES>>>(
        Hv + OP_EX, Lv + OP_EX, Hv + OP_WQ1, Lv + OP_WQ1, Qd, DEX / 2,
        BB * L2C, 0, 0, L2C, LT, L1C, MQ);
    gemm_b3<<<dim3(MKV / 128, (BB * L2C) / 128), 256, GSM_BYTES>>>(
        Hv + OP_EX, Lv + OP_EX, Hv + OP_WK1, Lv + OP_WK1, Kd, DEX / 2,
        BB * L2C, 0, 0, L2C, LT, L1C, MKV);
    gemm_b3<<<dim3(MKV / 128, (BB * L2C) / 128), 256, GSM_BYTES>>>(
        Hv + OP_EX, Lv + OP_EX, Hv + OP_WV1, Lv + OP_WV1, Vd, DEX / 2,
        BB * L2C, 0, 0, L2C, LT, L1C, MKV);

    // --- RoPE (fold softmax scale into Q) ---
    rope_kernel<<<dim3(NH, LT, BB), DHD / 2>>>(Qd, cs, sn, NH, QK_SCALE);
    rope_kernel<<<dim3(NKV, LT, BB), DHD / 2>>>(Kd, cs, sn, NKV, 1.0f);

    // --- attention (tensor cores; emits permuted bf16 hi/lo planes) ---
    attn_mma<<<dim3(LT / 64, NH, BB), 256, SMEM_ATTN>>>(mask);

    // --- output projections (K2 = 1024) ---
    gemm_b3<<<dim3(DPG / 128, (BB * L1C) / 128), 256, GSM_BYTES>>>(
        Ahd, Ald, Hv + OP_WO0, Lv + OP_WO0, out, MQ / 2,
        L1C, LT, 0, BB * L1C, 0, 0, DPG);
    gemm_b3<<<dim3(DEX / 128, (BB * L2C) / 128), 256, GSM_BYTES>>>(
        Ahd, Ald, Hv + OP_WO1, Lv + OP_WO1, out + (size_t)BB * L1C * DPG, MQ / 2,
        L2C, LT, L1C, BB * L2C, 0, 0, DEX);
}

// round 7
// speedup vs baseline: 2.2733x; 1.0342x over previous
#include <cuda_runtime.h>
#include <cuda_bf16.h>
#include <math.h>
#include <stdint.h>

#define BB   4
#define L1C  1024
#define L2C  512
#define LT   1536
#define DPG  2304
#define DEX  1024
#define NH   8
#define NKV  4
#define DHD  256
#define QK_SCALE 0.0625f

// logical u32 j (0..7) within a k16 group -> stored position
#define PERM8(j) ((((j) & 3) << 1) | ((j) >> 2))

// ---------------- scratch (device globals) -----------------------------------
__device__ float g_Q[(size_t)BB * LT * NH * DHD];    // fp32 QKV-proj outputs
__device__ float g_K[(size_t)BB * LT * NKV * DHD];
__device__ float g_V[(size_t)BB * LT * NKV * DHD];

// post-rope packed bf16 hi/lo planes (u32 = bf16x2 along d, pair-permuted)
__device__ uint32_t g_Qh[(size_t)BB * LT * NH * 128];
__device__ uint32_t g_Ql[(size_t)BB * LT * NH * 128];
__device__ uint32_t g_Kh[(size_t)BB * LT * NKV * 128];
__device__ uint32_t g_Kl[(size_t)BB * LT * NKV * 128];

// V transposed: [b][hkv][d][key-pair] (pair-permuted along keys)
__device__ uint32_t g_VTh[(size_t)BB * NKV * DHD * (LT / 2)];
__device__ uint32_t g_VTl[(size_t)BB * NKV * DHD * (LT / 2)];

// attention output planes (A operand of out-proj)
__device__ uint32_t g_ahi[(size_t)BB * LT * NH * 128];
__device__ uint32_t g_alo[(size_t)BB * LT * NH * 128];

// bf16 hi/lo planes of the 10 projection operands
#define OP_PG   0u
#define OP_EX   4718592u
#define OP_WQ0  5767168u
#define OP_WK0  8126464u
#define OP_WV0  9306112u
#define OP_WO0  10485760u
#define OP_WQ1  12845056u
#define OP_WK1  13893632u
#define OP_WV1  14417920u
#define OP_WO1  14942208u
#define OP_TOT  15990784u
__device__ uint32_t g_hi[OP_TOT];
__device__ uint32_t g_lo[OP_TOT];

// ---------------- helpers ----------------------------------------------------
__device__ __forceinline__ uint32_t pack_bf(float a, float b)
{
    __nv_bfloat162 t = __floats2bfloat162_rn(a, b);
    return *(uint32_t*)&t;
}
__device__ __forceinline__ void cpa16(uint32_t dst, const void* src)
{
    asm volatile("cp.async.cg.shared.global [%0], [%1], 16;" :: "r"(dst), "l"(src));
}

#define MMA_BF16(d, a, b)                                                     \
    asm volatile("mma.sync.aligned.m16n8k16.row.col.f32.bf16.bf16.f32 "       \
                 "{%0,%1,%2,%3}, {%4,%5,%6,%7}, {%8,%9}, {%0,%1,%2,%3};"      \
                 : "+f"(d[0]), "+f"(d[1]), "+f"(d[2]), "+f"(d[3])             \
                 : "r"(a[0]), "r"(a[1]), "r"(a[2]), "r"(a[3]),                \
                   "r"(b[0]), "r"(b[1]))

// ---------------- fused bf16-split conversion --------------------------------
struct CvtArgs {
    const float* src[10];
    uint32_t off[10];
    int n16[10];
};

__global__ void cvt_bsplit(CvtArgs a)
{
    const int e = blockIdx.y;
    const int i = blockIdx.x * blockDim.x + threadIdx.x;
    if (i >= a.n16[e]) return;
    const float4* s = (const float4*)(a.src[e]) + (size_t)i * 4;
    uint32_t* hb = g_hi + a.off[e] + (size_t)i * 8;
    uint32_t* lb = g_lo + a.off[e] + (size_t)i * 8;
    float v[16];
#pragma unroll
    for (int q = 0; q < 4; q++) {
        float4 f = s[q];
        v[q * 4 + 0] = f.x; v[q * 4 + 1] = f.y; v[q * 4 + 2] = f.z; v[q * 4 + 3] = f.w;
    }
#pragma unroll
    for (int j = 0; j < 8; j++) {
        const float x0 = v[2 * j], x1 = v[2 * j + 1];
        const float h0 = __bfloat162float(__float2bfloat16_rn(x0));
        const float h1 = __bfloat162float(__float2bfloat16_rn(x1));
        const int p = PERM8(j);
        hb[p] = pack_bf(h0, h1);
        lb[p] = pack_bf(x0 - h0, x1 - h1);
    }
}

// ---------------- bf16x3 NT GEMM: 3-stage, swizzled, 2 CTAs/SM ---------------
#define CH 16                      // u32 per row per chunk (32 bf16)
#define PLN (128 * CH)             // 2048 u32 per plane
#define STG (4 * PLN)              // 8192 u32 per stage
#define GSM_BYTES (3 * STG * 4)    // 98304 B

__global__ __launch_bounds__(256, 2) void gemm_b3(
    const uint32_t* __restrict__ Ah, const uint32_t* __restrict__ Al,
    const uint32_t* __restrict__ Wh, const uint32_t* __restrict__ Wl,
    float* __restrict__ C, int K2,
    int a_rpb, int a_bs, int a_off,
    int c_rpb, int c_bs, int c_off, int ldc)
{
    extern __shared__ uint32_t smg[];
    const int tid = threadIdx.x;
    const int wid = tid >> 5, lane = tid & 31;
    const int warp_m = wid >> 1, warp_n = wid & 1;
    const int bm = blockIdx.y * 128, bn = blockIdx.x * 128;

    // staging: plane p = tid>>6, rows 2*rr, 2*rr+1
    const int p  = tid >> 6;
    const int rr = tid & 63;
    const int r0 = rr * 2, r1 = rr * 2 + 1;
    int gr0, gr1;
    if (p < 2) {
        const int m0 = bm + r0, m1 = bm + r1;
        gr0 = (m0 / a_rpb) * a_bs + a_off + (m0 % a_rpb);
        gr1 = (m1 / a_rpb) * a_bs + a_off + (m1 % a_rpb);
    } else {
        gr0 = bn + r0; gr1 = bn + r1;
    }
    const uint32_t* pb = (p == 0) ? Ah : (p == 1) ? Al : (p == 2) ? Wh : Wl;
    const uint32_t* s0 = pb + (size_t)gr0 * K2;
    const uint32_t* s1 = pb + (size_t)gr1 * K2;

    const uint32_t sbase = (uint32_t)__cvta_generic_to_shared(smg);
    const int sw0 = (r0 & 2) << 1, sw1 = (r1 & 2) << 1;
    // dst byte offsets for the 4 16B chunks of each row (swizzled)
    uint32_t d0[4], d1[4];
#pragma unroll
    for (int j = 0; j < 4; j++) {
        d0[j] = sbase + (p * PLN + r0 * CH) * 4 + (((2 * j) ^ sw0) * 2) * 4;
        d1[j] = sbase + (p * PLN + r1 * CH) * 4 + (((2 * j) ^ sw1) * 2) * 4;
    }

    float acc[2][8][4];
#pragma unroll
    for (int i = 0; i < 2; i++)
#pragma unroll
        for (int j = 0; j < 8; j++)
#pragma unroll
            for (int r = 0; r < 4; r++) acc[i][j][r] = 0.f;

    const int nk = K2 >> 4;   // chunks of 16 u32

#define G_ISSUE(kc)                                                           \
    do {                                                                      \
        const int _sl = (kc) % 3;                                             \
        const int _ko = (kc) * CH;                                            \
        const uint32_t _sb = _sl * STG * 4;                                   \
        _Pragma("unroll")                                                     \
        for (int j = 0; j < 4; j++) {                                         \
            cpa16(d0[j] + _sb, s0 + _ko + j * 4);                             \
            cpa16(d1[j] + _sb, s1 + _ko + j * 4);                             \
        }                                                                     \
        asm volatile("cp.async.commit_group;");                               \
    } while (0)

    G_ISSUE(0);
    G_ISSUE(1);

    const int lr = lane >> 2, lc = lane & 3;
    const int fsw = (lr & 2) << 1;   // fragment swizzle (rows share &2 with lr)

    for (int kc = 0; kc < nk; kc++) {
        __syncthreads();                         // slot (kc+2)%3 free
        if (kc + 2 < nk) {
            G_ISSUE(kc + 2);
            asm volatile("cp.async.wait_group 2;");
        } else if (kc + 1 < nk) {
            asm volatile("cp.async.wait_group 1;");
        } else {
            asm volatile("cp.async.wait_group 0;");
        }
        __syncthreads();

        const uint32_t* st = smg + (kc % 3) * STG;
        const uint32_t* ah_p = st + 0 * PLN + (warp_m * 32 + lr) * CH;
        const uint32_t* al_p = st + 1 * PLN + (warp_m * 32 + lr) * CH;
        const uint32_t* wh_p = st + 2 * PLN + (warp_n * 64 + lr) * CH;
        const uint32_t* wl_p = st + 3 * PLN + (warp_n * 64 + lr) * CH;

#pragma unroll
        for (int g = 0; g < 2; g++) {
            const int q2 = ((g * 4 + lc) ^ fsw) * 2;
            uint32_t ah[2][4], al[2][4];
            uint2 t;
#pragma unroll
            for (int mf = 0; mf < 2; mf++) {
                t = *(const uint2*)(ah_p + mf * 16 * CH + q2);            ah[mf][0] = t.x; ah[mf][2] = t.y;
                t = *(const uint2*)(ah_p + mf * 16 * CH + 8 * CH + q2);   ah[mf][1] = t.x; ah[mf][3] = t.y;
                t = *(const uint2*)(al_p + mf * 16 * CH + q2);            al[mf][0] = t.x; al[mf][2] = t.y;
                t = *(const uint2*)(al_p + mf * 16 * CH + 8 * CH + q2);   al[mf][1] = t.x; al[mf][3] = t.y;
            }
#pragma unroll
            for (int nf = 0; nf < 8; nf++) {
                uint32_t bh[2], bl[2];
                t = *(const uint2*)(wh_p + nf * 8 * CH + q2);  bh[0] = t.x; bh[1] = t.y;
                t = *(const uint2*)(wl_p + nf * 8 * CH + q2);  bl[0] = t.x; bl[1] = t.y;
#pragma unroll
                for (int mf = 0; mf < 2; mf++) {
                    MMA_BF16(acc[mf][nf], al[mf], bh);
                    MMA_BF16(acc[mf][nf], ah[mf], bl);
                    MMA_BF16(acc[mf][nf], ah[mf], bh);
                }
            }
        }
    }
#undef G_ISSUE

#pragma unroll
    for (int mf = 0; mf < 2; mf++) {
        const int m0 = bm + warp_m * 32 + mf * 16 + lr;
        const int m1 = m0 + 8;
        const int cr0 = (m0 / c_rpb) * c_bs + c_off + (m0 % c_rpb);
        const int cr1 = (m1 / c_rpb) * c_bs + c_off + (m1 % c_rpb);
#pragma unroll
        for (int nf = 0; nf < 8; nf++) {
            const int col = bn + warp_n * 64 + nf * 8 + lc * 2;
            *(float2*)&C[(size_t)cr0 * ldc + col] = make_float2(acc[mf][nf][0], acc[mf][nf][1]);
            *(float2*)&C[(size_t)cr1 * ldc + col] = make_float2(acc[mf][nf][2], acc[mf][nf][3]);
        }
    }
}

// ---------------- RoPE + bf16 split + pack (permuted planes) -----------------
__global__ void rope_pack(const float* __restrict__ X, const float* __restrict__ cs,
                          const float* __restrict__ sn, int nheads, float scale,
                          uint32_t* __restrict__ oh, uint32_t* __restrict__ ol)
{
    const int h = blockIdx.x;
    const int l = blockIdx.y;
    const int b = blockIdx.z;
    const int j = threadIdx.x;   // 0..63  (pair j and pair j+64)
    const size_t row = (size_t)b * LT + l;
    const float2 c2 = *(const float2*)&cs[row * 128 + 2 * j];
    const float2 s2 = *(const float2*)&sn[row * 128 + 2 * j];
    const size_t base = (row * nheads + h) * DHD;
    const float2 xa = *(const float2*)&X[base + 2 * j];
    const float2 xb = *(const float2*)&X[base + 128 + 2 * j];
    const float y1a = (xa.x * c2.x - xb.x * s2.x) * scale;
    const float y1b = (xa.y * c2.y - xb.y * s2.y) * scale;
    const float y2a = (xb.x * c2.x + xa.x * s2.x) * scale;
    const float y2b = (xb.y * c2.y + xa.y * s2.y) * scale;

    const size_t ob = (row * nheads + h) * 128;
    const int p1 = (j & ~7) | PERM8(j & 7);
    const int p2 = 64 + p1;
    const float h1a = __bfloat162float(__float2bfloat16_rn(y1a));
    const float h1b = __bfloat162float(__float2bfloat16_rn(y1b));
    const float h2a = __bfloat162float(__float2bfloat16_rn(y2a));
    const float h2b = __bfloat162float(__float2bfloat16_rn(y2b));
    oh[ob + p1] = pack_bf(h1a, h1b);
    ol[ob + p1] = pack_bf(y1a - h1a, y1b - h1b);
    oh[ob + p2] = pack_bf(h2a, h2b);
    ol[ob + p2] = pack_bf(y2a - h2a, y2b - h2b);
}

// ---------------- V transpose + bf16 split (permuted key-pairs) --------------
__global__ __launch_bounds__(256) void vt_pack()
{
    __shared__ float t[64][65];
    const int b   = blockIdx.z >> 2;
    const int hkv = blockIdx.z & 3;
    const int l0 = blockIdx.x * 64;
    const int d0 = blockIdx.y * 64;
    const int tid = threadIdx.x;

    for (int i = tid; i < 64 * 64; i += 256) {
        const int lrow = i >> 6, dcol = i & 63;
        t[lrow][dcol] = g_V[(((size_t)b * LT + l0 + lrow) * NKV + hkv) * DHD + d0 + dcol];
    }
    __syncthreads();

    const int drow = tid & 63;
    const int mg = tid >> 6;   // 0..3: pair-group of 8
    const size_t obase = (((size_t)b * NKV + hkv) * DHD + d0 + drow) * (LT / 2) + l0 / 2;
#pragma unroll
    for (int m = 0; m < 8; m++) {
        const int lp = mg * 8 + m;
        const float v0 = t[2 * lp][drow];
        const float v1 = t[2 * lp + 1][drow];
        const float h0 = __bfloat162float(__float2bfloat16_rn(v0));
        const float h1 = __bfloat162float(__float2bfloat16_rn(v1));
        const int pos = mg * 8 + PERM8(m);
        g_VTh[obase + pos] = pack_bf(h0, h1);
        g_VTl[obase + pos] = pack_bf(v0 - h0, v1 - h1);
    }
}

// ---------------- bf16x3 tensor-core flash attention -------------------------
// smem (u32 offsets): QH 0, QL 8192, KH 16384, KL 24576, VH 32768, VL 40960,
// S(fp32) 49152 (64x68), PH 53504, PL 55552, ASC 57600, LSC 57664.
#define AQH 0
#define AQL 8192
#define AKH 16384
#define AKL 24576
#define AVH 32768
#define AVL 40960
#define ASF 49152
#define APH 53504
#define APL 55552
#define AAS 57600
#define ALS 57664
#define SMEM_ATTN (57728 * 4)

__global__ __launch_bounds__(256, 1) void attn_mma(const float* __restrict__ mask)
{
    extern __shared__ uint32_t su[];
    float* S   = (float*)(su + ASF);
    float* Asc = (float*)(su + AAS);
    float* Lsc = (float*)(su + ALS);

    const int tid = threadIdx.x;
    const int qt = blockIdx.x;
    const int h  = blockIdx.y;
    const int b  = blockIdx.z;
    const int hkv = h >> 1;
    const int wid = tid >> 5, lane = tid & 31;
    const int wm = wid >> 1, wn = wid & 1;
    const int lr = lane >> 2, lc = lane & 3;
    const int srow = tid >> 2, spart = tid & 3;

    const uint32_t sb = (uint32_t)__cvta_generic_to_shared(su);

    // ---- prologue: stage Q planes + K(0) planes (group 0), V(0) (group 1) ----
    {
        const uint32_t* qsrc[2] = { g_Qh, g_Ql };
        const uint32_t* ksrc[2] = { g_Kh, g_Kl };
#pragma unroll
        for (int pl = 0; pl < 2; pl++) {
            for (int i = tid; i < 2048; i += 256) {
                const int row = i >> 5, ch = i & 31;
                const uint32_t dst = sb + ((pl ? AQL : AQH) + row * 128 +
                                           (((2 * ch) ^ ((row & 3) << 2)) * 2)) * 4;
                cpa16(dst, qsrc[pl] + (((size_t)b * LT + qt * 64 + row) * NH + h) * 128 + ch * 4);
            }
            for (int i = tid; i < 2048; i += 256) {
                const int row = i >> 5, ch = i & 31;
                const uint32_t dst = sb + ((pl ? AKL : AKH) + row * 128 +
                                           (((2 * ch) ^ ((row & 3) << 2)) * 2)) * 4;
                cpa16(dst, ksrc[pl] + (((size_t)b * LT + row) * NKV + hkv) * 128 + ch * 4);
            }
        }
        asm volatile("cp.async.commit_group;");
        const uint32_t* vsrc[2] = { g_VTh, g_VTl };
#pragma unroll
        for (int pl = 0; pl < 2; pl++)
            for (int i = tid; i < 2048; i += 256) {
                const int row = i >> 3, ch = i & 7;
                const uint32_t dst = sb + ((pl ? AVL : AVH) + row * 32 +
                                           (((2 * ch) ^ ((row & 3) << 2)) * 2)) * 4;
                cpa16(dst, vsrc[pl] + (((size_t)b * NKV + hkv) * DHD + row) * (LT / 2) + ch * 4);
            }
        asm volatile("cp.async.commit_group;");
    }

    float accO[16][4];
#pragma unroll
    for (int i = 0; i < 16; i++)
#pragma unroll
        for (int j = 0; j < 4; j++) accO[i][j] = 0.f;
    float m_run = -1e30f, l_run = 0.f;

    const int fsw = (lr & 3) << 2;   // fragment swizzle

    for (int kt = 0; kt < LT / 64; kt++) {
        asm volatile("cp.async.wait_group 1;");   // K(kt) (and Q) arrived
        __syncthreads();

        // ---- S = Q K^T  (bf16x3, k = 256 = 16 groups) ----
        float accS[4][4];
#pragma unroll
        for (int i = 0; i < 4; i++)
#pragma unroll
            for (int j = 0; j < 4; j++) accS[i][j] = 0.f;
        {
            const uint32_t* qh = su + AQH + (wm * 16 + lr) * 128;
            const uint32_t* ql = su + AQL + (wm * 16 + lr) * 128;
            const uint32_t* kh = su + AKH + (wn * 32 + lr) * 128;
            const uint32_t* kl = su + AKL + (wn * 32 + lr) * 128;
#pragma unroll 4
            for (int g = 0; g < 16; g++) {
                const int q2 = ((g * 4 + lc) ^ fsw) * 2;
                uint32_t ah[4], al[4];
                uint2 t;
                t = *(const uint2*)(qh + q2);             ah[0] = t.x; ah[2] = t.y;
                t = *(const uint2*)(qh + 8 * 128 + q2);   ah[1] = t.x; ah[3] = t.y;
                t = *(const uint2*)(ql + q2);             al[0] = t.x; al[2] = t.y;
                t = *(const uint2*)(ql + 8 * 128 + q2);   al[1] = t.x; al[3] = t.y;
#pragma unroll
                for (int nf = 0; nf < 4; nf++) {
                    uint32_t bh[2], bl[2];
                    t = *(const uint2*)(kh + nf * 8 * 128 + q2);  bh[0] = t.x; bh[1] = t.y;
                    t = *(const uint2*)(kl + nf * 8 * 128 + q2);  bl[0] = t.x; bl[1] = t.y;
                    MMA_BF16(accS[nf], al, bh);
                    MMA_BF16(accS[nf], ah, bl);
                    MMA_BF16(accS[nf], ah, bh);
                }
            }
        }
        // ---- add mask, write S ----
        {
            const size_t mrow0 = ((size_t)b * LT + qt * 64 + wm * 16 + lr) * LT + kt * 64 + wn * 32;
            const size_t mrow1 = mrow0 + (size_t)8 * LT;
#pragma unroll
            for (int nf = 0; nf < 4; nf++) {
                const int col = nf * 8 + lc * 2;
                const float2 m0 = *(const float2*)&mask[mrow0 + col];
                const float2 m1 = *(const float2*)&mask[mrow1 + col];
                *(float2*)&S[(wm * 16 + lr) * 68 + wn * 32 + col] =
                    make_float2(accS[nf][0] + m0.x, accS[nf][1] + m0.y);
                *(float2*)&S[(wm * 16 + lr + 8) * 68 + wn * 32 + col] =
                    make_float2(accS[nf][2] + m1.x, accS[nf][3] + m1.y);
            }
        }
        __syncthreads();          // S ready; K slot free

        if (kt + 1 < LT / 64) {   // stage K(kt+1) during softmax/PV
            const uint32_t* ksrc[2] = { g_Kh, g_Kl };
#pragma unroll
            for (int pl = 0; pl < 2; pl++)
                for (int i = tid; i < 2048; i += 256) {
                    const int row = i >> 5, ch = i & 31;
                    const uint32_t dst = sb + ((pl ? AKL : AKH) + row * 128 +
                                               (((2 * ch) ^ ((row & 3) << 2)) * 2)) * 4;
                    cpa16(dst, ksrc[pl] + (((size_t)b * LT + (kt + 1) * 64 + row) * NKV + hkv) * 128 + ch * 4);
                }
            asm volatile("cp.async.commit_group;");
        }

        // ---- online softmax -> P hi/lo planes ----
        {
            float* sp = S + srow * 68 + spart * 16;
            float pv[16];
            float lm = -1e30f;
#pragma unroll
            for (int j = 0; j < 16; j++) { pv[j] = sp[j]; lm = fmaxf(lm, pv[j]); }
            lm = fmaxf(lm, __shfl_xor_sync(0xffffffffu, lm, 1));
            lm = fmaxf(lm, __shfl_xor_sync(0xffffffffu, lm, 2));
            const float mnew = fmaxf(m_run, lm);
            const float alpha = __expf(m_run - mnew);
            float ls = 0.f;
#pragma unroll
            for (int j = 0; j < 16; j++) { pv[j] = __expf(pv[j] - mnew); ls += pv[j]; }
            ls += __shfl_xor_sync(0xffffffffu, ls, 1);
            ls += __shfl_xor_sync(0xffffffffu, ls, 2);
            l_run = l_run * alpha + ls;
            m_run = mnew;
            if (spart == 0) Asc[srow] = alpha;

            const int swz = (srow & 3) << 2;
#pragma unroll
            for (int m = 0; m < 8; m++) {
                const float p0 = pv[2 * m], p1 = pv[2 * m + 1];
                const float h0 = __bfloat162float(__float2bfloat16_rn(p0));
                const float h1 = __bfloat162float(__float2bfloat16_rn(p1));
                const int u = spart * 8 + PERM8(m);
                const int pos = srow * 32 + (((u >> 1) ^ swz) * 2) + (u & 1);
                su[APH + pos] = pack_bf(h0, h1);
                su[APL + pos] = pack_bf(p0 - h0, p1 - h1);
            }
        }
        if (kt + 1 < LT / 64) { asm volatile("cp.async.wait_group 1;"); }
        else                  { asm volatile("cp.async.wait_group 0;"); }
        __syncthreads();          // P/Asc ready; V(kt) arrived

        // ---- rescale O, O += P V (bf16x3, k = 64 keys = 4 groups) ----
        {
            const float a0 = Asc[wm * 16 + lr];
            const float a1 = Asc[wm * 16 + lr + 8];
#pragma unroll
            for (int nf = 0; nf < 16; nf++) {
                accO[nf][0] *= a0; accO[nf][1] *= a0;
                accO[nf][2] *= a1; accO[nf][3] *= a1;
            }
            const uint32_t* php = su + APH + (wm * 16 + lr) * 32;
            const uint32_t* plp = su + APL + (wm * 16 + lr) * 32;
            const uint32_t* vhp = su + AVH + (wn * 128 + lr) * 32;
            const uint32_t* vlp = su + AVL + (wn * 128 + lr) * 32;
#pragma unroll
            for (int g = 0; g < 4; g++) {
                const int q2 = ((g * 4 + lc) ^ fsw) * 2;
                uint32_t ph[4], pl[4];
                uint2 t;
                t = *(const uint2*)(php + q2);            ph[0] = t.x; ph[2] = t.y;
                t = *(const uint2*)(php + 8 * 32 + q2);   ph[1] = t.x; ph[3] = t.y;
                t = *(const uint2*)(plp + q2);            pl[0] = t.x; pl[2] = t.y;
                t = *(const uint2*)(plp + 8 * 32 + q2);   pl[1] = t.x; pl[3] = t.y;
#pragma unroll
                for (int nf = 0; nf < 16; nf++) {
                    uint32_t vh[2], vl[2];
                    t = *(const uint2*)(vhp + nf * 8 * 32 + q2);  vh[0] = t.x; vh[1] = t.y;
                    t = *(const uint2*)(vlp + nf * 8 * 32 + q2);  vl[0] = t.x; vl[1] = t.y;
                    MMA_BF16(accO[nf], pl, vh);
                    MMA_BF16(accO[nf], ph, vl);
                    MMA_BF16(accO[nf], ph, vh);
                }
            }
        }
        __syncthreads();          // PV done; V slot free

        if (kt + 1 < LT / 64) {   // stage V(kt+1)
            const uint32_t* vsrc[2] = { g_VTh, g_VTl };
#pragma unroll
            for (int pl = 0; pl < 2; pl++)
                for (int i = tid; i < 2048; i += 256) {
                    const int row = i >> 3, ch = i & 7;
                    const uint32_t dst = sb + ((pl ? AVL : AVH) + row * 32 +
                                               (((2 * ch) ^ ((row & 3) << 2)) * 2)) * 4;
                    cpa16(dst, vsrc[pl] + (((size_t)b * NKV + hkv) * DHD + row) * (LT / 2) +
                               (kt + 1) * 32 + ch * 4);
                }
            asm volatile("cp.async.commit_group;");
        }
    }

    if (spart == 0) Lsc[srow] = l_run;
    __syncthreads();

    // ---- epilogue: normalize, emit packed bf16 hi/lo planes (permuted) ----
    {
        const float il0 = 1.f / Lsc[wm * 16 + lr];
        const float il1 = 1.f / Lsc[wm * 16 + lr + 8];
        const size_t r0 = (size_t)b * LT + qt * 64 + wm * 16 + lr;
        const size_t r1 = r0 + 8;
#pragma unroll
        for (int nf = 0; nf < 16; nf++) {
            const int p = h * 128 + wn * 64 + nf * 4 + lc;
            const int pos = (p & ~7) | PERM8(p & 7);
            const float v0 = accO[nf][0] * il0, v1 = accO[nf][1] * il0;
            const float v2 = accO[nf][2] * il1, v3 = accO[nf][3] * il1;
            const float h0 = __bfloat162float(__float2bfloat16_rn(v0));
            const float h1 = __bfloat162float(__float2bfloat16_rn(v1));
            const float h2 = __bfloat162float(__float2bfloat16_rn(v2));
            const float h3 = __bfloat162float(__float2bfloat16_rn(v3));
            g_ahi[r0 * 1024 + pos] = pack_bf(h0, h1);
            g_alo[r0 * 1024 + pos] = pack_bf(v0 - h0, v1 - h1);
            g_ahi[r1 * 1024 + pos] = pack_bf(h2, h3);
            g_alo[r1 * 1024 + pos] = pack_bf(v2 - h2, v3 - h3);
        }
    }
}

// ---------------- launch ----------------------------------------------------
extern "C" void kernel_launch(void* const* d_in, const int* in_sizes, int n_in,
                              void* d_out, int out_size)
{
    const float* pg   = (const float*)d_in[0];
    const float* ex   = (const float*)d_in[1];
    const float* cs   = (const float*)d_in[2];
    const float* sn   = (const float*)d_in[3];
    const float* mask = (const float*)d_in[4];
    const float* Wq0  = (const float*)d_in[5];
    const float* Wk0  = (const float*)d_in[6];
    const float* Wv0  = (const float*)d_in[7];
    const float* Wo0  = (const float*)d_in[8];
    const float* Wq1  = (const float*)d_in[9];
    const float* Wk1  = (const float*)d_in[10];
    const float* Wv1  = (const float*)d_in[11];
    const float* Wo1  = (const float*)d_in[12];
    float* out = (float*)d_out;

    float *Qd, *Kd, *Vd;
    uint32_t *Ahd, *Ald, *Hv, *Lv, *Qhp, *Qlp, *Khp, *Klp;
    cudaGetSymbolAddress((void**)&Qd, g_Q);
    cudaGetSymbolAddress((void**)&Kd, g_K);
    cudaGetSymbolAddress((void**)&Vd, g_V);
    cudaGetSymbolAddress((void**)&Ahd, g_ahi);
    cudaGetSymbolAddress((void**)&Ald, g_alo);
    cudaGetSymbolAddress((void**)&Hv, g_hi);
    cudaGetSymbolAddress((void**)&Lv, g_lo);
    cudaGetSymbolAddress((void**)&Qhp, g_Qh);
    cudaGetSymbolAddress((void**)&Qlp, g_Ql);
    cudaGetSymbolAddress((void**)&Khp, g_Kh);
    cudaGetSymbolAddress((void**)&Klp, g_Kl);

    cudaFuncSetAttribute(gemm_b3, cudaFuncAttributeMaxDynamicSharedMemorySize, GSM_BYTES);
    cudaFuncSetAttribute(attn_mma, cudaFuncAttributeMaxDynamicSharedMemorySize, SMEM_ATTN);

    const int MQ = NH * DHD;    // 2048
    const int MKV = NKV * DHD;  // 1024

    // --- split projection operands into permuted bf16 hi/lo planes ---
    CvtArgs ca;
    const float* srcs[10] = { pg, ex, Wq0, Wk0, Wv0, Wo0, Wq1, Wk1, Wv1, Wo1 };
    const uint32_t offs[10] = { OP_PG, OP_EX, OP_WQ0, OP_WK0, OP_WV0,
                                OP_WO0, OP_WQ1, OP_WK1, OP_WV1, OP_WO1 };
    const int ns[10] = { BB * L1C * DPG, BB * L2C * DEX, MQ * DPG, MKV * DPG,
                         MKV * DPG, DPG * MQ, MQ * DEX, MKV * DEX, MKV * DEX, DEX * MQ };
    int maxg = 0;
    for (int i = 0; i < 10; i++) {
        ca.src[i] = srcs[i]; ca.off[i] = offs[i]; ca.n16[i] = ns[i] / 16;
        if (ca.n16[i] > maxg) maxg = ca.n16[i];
    }
    cvt_bsplit<<<dim3((maxg + 255) / 256, 10), 256>>>(ca);

    // --- QKV projections, pg stream (K2 = 1152) ---
    gemm_b3<<<dim3(MQ / 128, (BB * L1C) / 128), 256, GSM_BYTES>>>(
        Hv + OP_PG, Lv + OP_PG, Hv + OP_WQ0, Lv + OP_WQ0, Qd, DPG / 2,
        BB * L1C, 0, 0, L1C, LT, 0, MQ);
    gemm_b3<<<dim3(MKV / 128, (BB * L1C) / 128), 256, GSM_BYTES>>>(
        Hv + OP_PG, Lv + OP_PG, Hv + OP_WK0, Lv + OP_WK0, Kd, DPG / 2,
        BB * L1C, 0, 0, L1C, LT, 0, MKV);
    gemm_b3<<<dim3(MKV / 128, (BB * L1C) / 128), 256, GSM_BYTES>>>(
        Hv + OP_PG, Lv + OP_PG, Hv + OP_WV0, Lv + OP_WV0, Vd, DPG / 2,
        BB * L1C, 0, 0, L1C, LT, 0, MKV);

    // --- QKV projections, ex stream (K2 = 512) ---
    gemm_b3<<<dim3(MQ / 128, (BB * L2C) / 128), 256, GSM_BYTES>>>(
        Hv + OP_EX, Lv + OP_EX, Hv + OP_WQ1, Lv + OP_WQ1, Qd, DEX / 2,
        BB * L2C, 0, 0, L2C, LT, L1C, MQ);
    gemm_b3<<<dim3(MKV / 128, (BB * L2C) / 128), 256, GSM_BYTES>>>(
        Hv + OP_EX, Lv + OP_EX, Hv + OP_WK1, Lv + OP_WK1, Kd, DEX / 2,
        BB * L2C, 0, 0, L2C, LT, L1C, MKV);
    gemm_b3<<<dim3(MKV / 128, (BB * L2C) / 128), 256, GSM_BYTES>>>(
        Hv + OP_EX, Lv + OP_EX, Hv + OP_WV1, Lv + OP_WV1, Vd, DEX / 2,
        BB * L2C, 0, 0, L2C, LT, L1C, MKV);

    // --- RoPE + split/pack planes; V transpose/pack ---
    rope_pack<<<dim3(NH, LT, BB), 64>>>(Qd, cs, sn, NH, QK_SCALE, Qhp, Qlp);
    rope_pack<<<dim3(NKV, LT, BB), 64>>>(Kd, cs, sn, NKV, 1.0f, Khp, Klp);
    vt_pack<<<dim3(LT / 64, DHD / 64, BB * NKV), 256>>>();

    // --- attention ---
    attn_mma<<<dim3(LT / 64, NH, BB), 256, SMEM_ATTN>>>(mask);

    // --- output projections (K2 = 1024) ---
    gemm_b3<<<dim3(DPG / 128, (BB * L1C) / 128), 256, GSM_BYTES>>>(
        Ahd, Ald, Hv + OP_WO0, Lv + OP_WO0, out, MQ / 2,
        L1C, LT, 0, BB * L1C, 0, 0, DPG);
    gemm_b3<<<dim3(DEX / 128, (BB * L2C) / 128), 256, GSM_BYTES>>>(
        Ahd, Ald, Hv + OP_WO1, Lv + OP_WO1, out + (size_t)BB * L1C * DPG, MQ / 2,
        L2C, LT, L1C, BB * L2C, 0, 0, DEX);
}

// round 8
// speedup vs baseline: 2.3813x; 1.0475x over previous
#include <cuda_runtime.h>
#include <cuda_bf16.h>
#include <math.h>
#include <stdint.h>

#define BB   4
#define L1C  1024
#define L2C  512
#define LT   1536
#define DPG  2304
#define DEX  1024
#define NH   8
#define NKV  4
#define DHD  256
#define QK_SCALE 0.0625f

// logical u32 j (0..7) within a k16 group -> stored position
#define PERM8(j) ((((j) & 3) << 1) | ((j) >> 2))

// ---------------- scratch (device globals) -----------------------------------
__device__ float g_Q[(size_t)BB * LT * NH * DHD];    // fp32 QKV-proj outputs
__device__ float g_K[(size_t)BB * LT * NKV * DHD];
__device__ float g_V[(size_t)BB * LT * NKV * DHD];

// post-rope packed bf16 hi/lo planes (u32 = bf16x2 along d, pair-permuted)
__device__ uint32_t g_Qh[(size_t)BB * LT * NH * 128];
__device__ uint32_t g_Ql[(size_t)BB * LT * NH * 128];
__device__ uint32_t g_Kh[(size_t)BB * LT * NKV * 128];
__device__ uint32_t g_Kl[(size_t)BB * LT * NKV * 128];

// V transposed: [b][hkv][d][key-pair] (pair-permuted along keys)
__device__ uint32_t g_VTh[(size_t)BB * NKV * DHD * (LT / 2)];
__device__ uint32_t g_VTl[(size_t)BB * NKV * DHD * (LT / 2)];

// attention output planes (A operand of out-proj)
__device__ uint32_t g_ahi[(size_t)BB * LT * NH * 128];
__device__ uint32_t g_alo[(size_t)BB * LT * NH * 128];

// bf16 hi/lo planes of the 10 projection operands
// NOTE: WQ0,WK0,WV0 contiguous (stacked N=4096 x K=2304); WQ1,WK1,WV1 likewise.
#define OP_PG   0u
#define OP_EX   4718592u
#define OP_WQ0  5767168u
#define OP_WK0  8126464u
#define OP_WV0  9306112u
#define OP_WO0  10485760u
#define OP_WQ1  12845056u
#define OP_WK1  13893632u
#define OP_WV1  14417920u
#define OP_WO1  14942208u
#define OP_TOT  15990784u
__device__ uint32_t g_hi[OP_TOT];
__device__ uint32_t g_lo[OP_TOT];

// ---------------- helpers ----------------------------------------------------
__device__ __forceinline__ uint32_t pack_bf(float a, float b)
{
    __nv_bfloat162 t = __floats2bfloat162_rn(a, b);
    return *(uint32_t*)&t;
}
__device__ __forceinline__ void cpa16(uint32_t dst, const void* src)
{
    asm volatile("cp.async.cg.shared.global [%0], [%1], 16;" :: "r"(dst), "l"(src));
}

#define MMA_BF16(d, a, b)                                                     \
    asm volatile("mma.sync.aligned.m16n8k16.row.col.f32.bf16.bf16.f32 "       \
                 "{%0,%1,%2,%3}, {%4,%5,%6,%7}, {%8,%9}, {%0,%1,%2,%3};"      \
                 : "+f"(d[0]), "+f"(d[1]), "+f"(d[2]), "+f"(d[3])             \
                 : "r"(a[0]), "r"(a[1]), "r"(a[2]), "r"(a[3]),                \
                   "r"(b[0]), "r"(b[1]))

// ---------------- fused bf16-split conversion --------------------------------
struct CvtArgs {
    const float* src[10];
    uint32_t off[10];
    int n16[10];
};

__global__ void cvt_bsplit(CvtArgs a)
{
    const int e = blockIdx.y;
    const int i = blockIdx.x * blockDim.x + threadIdx.x;
    if (i >= a.n16[e]) return;
    const float4* s = (const float4*)(a.src[e]) + (size_t)i * 4;
    uint32_t* hb = g_hi + a.off[e] + (size_t)i * 8;
    uint32_t* lb = g_lo + a.off[e] + (size_t)i * 8;
    float v[16];
#pragma unroll
    for (int q = 0; q < 4; q++) {
        float4 f = s[q];
        v[q * 4 + 0] = f.x; v[q * 4 + 1] = f.y; v[q * 4 + 2] = f.z; v[q * 4 + 3] = f.w;
    }
#pragma unroll
    for (int j = 0; j < 8; j++) {
        const float x0 = v[2 * j], x1 = v[2 * j + 1];
        const float h0 = __bfloat162float(__float2bfloat16_rn(x0));
        const float h1 = __bfloat162float(__float2bfloat16_rn(x1));
        const int p = PERM8(j);
        hb[p] = pack_bf(h0, h1);
        lb[p] = pack_bf(x0 - h0, x1 - h1);
    }
}

// ---------------- bf16x3 NT GEMM: 3-stage, swizzled, segmented C -------------
// W is a stacked [N][K2] plane; C columns route to up to 3 segments.
#define CH 16                      // u32 per row per chunk (32 bf16)
#define PLN (128 * CH)
#define STG (4 * PLN)
#define GSM_BYTES (3 * STG * 4)    // 98304 B

__global__ __launch_bounds__(256, 2) void gemm_b3(
    const uint32_t* __restrict__ Ah, const uint32_t* __restrict__ Al,
    const uint32_t* __restrict__ Wh, const uint32_t* __restrict__ Wl,
    int K2,
    int a_rpb, int a_bs, int a_off,
    int c_rpb, int c_bs, int c_off,
    int n1, int n2,                       // segment boundaries (cols)
    float* C0, int ldc0,
    float* C1, int ldc1,
    float* C2, int ldc2)
{
    extern __shared__ uint32_t smg[];
    const int tid = threadIdx.x;
    const int wid = tid >> 5, lane = tid & 31;
    const int warp_m = wid >> 1, warp_n = wid & 1;
    const int bm = blockIdx.y * 128, bn = blockIdx.x * 128;

    // staging: plane p = tid>>6, rows 2*rr, 2*rr+1
    const int p  = tid >> 6;
    const int rr = tid & 63;
    const int r0 = rr * 2, r1 = rr * 2 + 1;
    int gr0, gr1;
    if (p < 2) {
        const int m0 = bm + r0, m1 = bm + r1;
        gr0 = (m0 / a_rpb) * a_bs + a_off + (m0 % a_rpb);
        gr1 = (m1 / a_rpb) * a_bs + a_off + (m1 % a_rpb);
    } else {
        gr0 = bn + r0; gr1 = bn + r1;
    }
    const uint32_t* pb = (p == 0) ? Ah : (p == 1) ? Al : (p == 2) ? Wh : Wl;
    const uint32_t* s0 = pb + (size_t)gr0 * K2;
    const uint32_t* s1 = pb + (size_t)gr1 * K2;

    const uint32_t sbase = (uint32_t)__cvta_generic_to_shared(smg);
    const int sw0 = (r0 & 2) << 1, sw1 = (r1 & 2) << 1;
    uint32_t d0[4], d1[4];
#pragma unroll
    for (int j = 0; j < 4; j++) {
        d0[j] = sbase + (p * PLN + r0 * CH) * 4 + (((2 * j) ^ sw0) * 2) * 4;
        d1[j] = sbase + (p * PLN + r1 * CH) * 4 + (((2 * j) ^ sw1) * 2) * 4;
    }

    float acc[2][8][4];
#pragma unroll
    for (int i = 0; i < 2; i++)
#pragma unroll
        for (int j = 0; j < 8; j++)
#pragma unroll
            for (int r = 0; r < 4; r++) acc[i][j][r] = 0.f;

    const int nk = K2 >> 4;

#define G_ISSUE(kc)                                                           \
    do {                                                                      \
        const int _ko = (kc) * CH;                                            \
        const uint32_t _sb = ((kc) % 3) * STG * 4;                            \
        _Pragma("unroll")                                                     \
        for (int j = 0; j < 4; j++) {                                         \
            cpa16(d0[j] + _sb, s0 + _ko + j * 4);                             \
            cpa16(d1[j] + _sb, s1 + _ko + j * 4);                             \
        }                                                                     \
        asm volatile("cp.async.commit_group;");                               \
    } while (0)

    G_ISSUE(0);
    G_ISSUE(1);

    const int lr = lane >> 2, lc = lane & 3;
    const int fsw = (lr & 2) << 1;

    for (int kc = 0; kc < nk; kc++) {
        if (kc + 2 < nk) { asm volatile("cp.async.wait_group 1;"); }
        else             { asm volatile("cp.async.wait_group 0;"); }
        __syncthreads();                  // stage kc visible; slot (kc+2)%3 free
        if (kc + 2 < nk) G_ISSUE(kc + 2);

        const uint32_t* st = smg + (kc % 3) * STG;
        const uint32_t* ah_p = st + 0 * PLN + (warp_m * 32 + lr) * CH;
        const uint32_t* al_p = st + 1 * PLN + (warp_m * 32 + lr) * CH;
        const uint32_t* wh_p = st + 2 * PLN + (warp_n * 64 + lr) * CH;
        const uint32_t* wl_p = st + 3 * PLN + (warp_n * 64 + lr) * CH;

#pragma unroll
        for (int g = 0; g < 2; g++) {
            const int q2 = ((g * 4 + lc) ^ fsw) * 2;
            uint32_t ah[2][4], al[2][4];
            uint2 t;
#pragma unroll
            for (int mf = 0; mf < 2; mf++) {
                t = *(const uint2*)(ah_p + mf * 16 * CH + q2);            ah[mf][0] = t.x; ah[mf][2] = t.y;
                t = *(const uint2*)(ah_p + mf * 16 * CH + 8 * CH + q2);   ah[mf][1] = t.x; ah[mf][3] = t.y;
                t = *(const uint2*)(al_p + mf * 16 * CH + q2);            al[mf][0] = t.x; al[mf][2] = t.y;
                t = *(const uint2*)(al_p + mf * 16 * CH + 8 * CH + q2);   al[mf][1] = t.x; al[mf][3] = t.y;
            }
#pragma unroll
            for (int nf = 0; nf < 8; nf++) {
                uint32_t bh[2], bl[2];
                t = *(const uint2*)(wh_p + nf * 8 * CH + q2);  bh[0] = t.x; bh[1] = t.y;
                t = *(const uint2*)(wl_p + nf * 8 * CH + q2);  bl[0] = t.x; bl[1] = t.y;
#pragma unroll
                for (int mf = 0; mf < 2; mf++) {
                    MMA_BF16(acc[mf][nf], al[mf], bh);
                    MMA_BF16(acc[mf][nf], ah[mf], bl);
                    MMA_BF16(acc[mf][nf], ah[mf], bh);
                }
            }
        }
        __syncthreads();                  // all reads of slot kc done
    }
#undef G_ISSUE

    // ---- segmented epilogue ----
    float* Cb; int ldc, coff;
    if (bn < n1)      { Cb = C0; ldc = ldc0; coff = 0;  }
    else if (bn < n2) { Cb = C1; ldc = ldc1; coff = n1; }
    else              { Cb = C2; ldc = ldc2; coff = n2; }

#pragma unroll
    for (int mf = 0; mf < 2; mf++) {
        const int m0 = bm + warp_m * 32 + mf * 16 + lr;
        const int m1 = m0 + 8;
        const int cr0 = (m0 / c_rpb) * c_bs + c_off + (m0 % c_rpb);
        const int cr1 = (m1 / c_rpb) * c_bs + c_off + (m1 % c_rpb);
#pragma unroll
        for (int nf = 0; nf < 8; nf++) {
            const int col = bn - coff + warp_n * 64 + nf * 8 + lc * 2;
            *(float2*)&Cb[(size_t)cr0 * ldc + col] = make_float2(acc[mf][nf][0], acc[mf][nf][1]);
            *(float2*)&Cb[(size_t)cr1 * ldc + col] = make_float2(acc[mf][nf][2], acc[mf][nf][3]);
        }
    }
}

// ---------------- RoPE + bf16 split + pack (permuted planes) -----------------
__global__ void rope_pack(const float* __restrict__ X, const float* __restrict__ cs,
                          const float* __restrict__ sn, int nheads, float scale,
                          uint32_t* __restrict__ oh, uint32_t* __restrict__ ol)
{
    const int h = blockIdx.x;
    const int l = blockIdx.y;
    const int b = blockIdx.z;
    const int j = threadIdx.x;   // 0..63
    const size_t row = (size_t)b * LT + l;
    const float2 c2 = *(const float2*)&cs[row * 128 + 2 * j];
    const float2 s2 = *(const float2*)&sn[row * 128 + 2 * j];
    const size_t base = (row * nheads + h) * DHD;
    const float2 xa = *(const float2*)&X[base + 2 * j];
    const float2 xb = *(const float2*)&X[base + 128 + 2 * j];
    const float y1a = (xa.x * c2.x - xb.x * s2.x) * scale;
    const float y1b = (xa.y * c2.y - xb.y * s2.y) * scale;
    const float y2a = (xb.x * c2.x + xa.x * s2.x) * scale;
    const float y2b = (xb.y * c2.y + xa.y * s2.y) * scale;

    const size_t ob = (row * nheads + h) * 128;
    const int p1 = (j & ~7) | PERM8(j & 7);
    const int p2 = 64 + p1;
    const float h1a = __bfloat162float(__float2bfloat16_rn(y1a));
    const float h1b = __bfloat162float(__float2bfloat16_rn(y1b));
    const float h2a = __bfloat162float(__float2bfloat16_rn(y2a));
    const float h2b = __bfloat162float(__float2bfloat16_rn(y2b));
    oh[ob + p1] = pack_bf(h1a, h1b);
    ol[ob + p1] = pack_bf(y1a - h1a, y1b - h1b);
    oh[ob + p2] = pack_bf(h2a, h2b);
    ol[ob + p2] = pack_bf(y2a - h2a, y2b - h2b);
}

// ---------------- V transpose + bf16 split (permuted key-pairs) --------------
__global__ __launch_bounds__(256) void vt_pack()
{
    __shared__ float t[64][65];
    const int b   = blockIdx.z >> 2;
    const int hkv = blockIdx.z & 3;
    const int l0 = blockIdx.x * 64;
    const int d0 = blockIdx.y * 64;
    const int tid = threadIdx.x;

    for (int i = tid; i < 64 * 64; i += 256) {
        const int lrow = i >> 6, dcol = i & 63;
        t[lrow][dcol] = g_V[(((size_t)b * LT + l0 + lrow) * NKV + hkv) * DHD + d0 + dcol];
    }
    __syncthreads();

    const int drow = tid & 63;
    const int mg = tid >> 6;
    const size_t obase = (((size_t)b * NKV + hkv) * DHD + d0 + drow) * (LT / 2) + l0 / 2;
#pragma unroll
    for (int m = 0; m < 8; m++) {
        const int lp = mg * 8 + m;
        const float v0 = t[2 * lp][drow];
        const float v1 = t[2 * lp + 1][drow];
        const float h0 = __bfloat162float(__float2bfloat16_rn(v0));
        const float h1 = __bfloat162float(__float2bfloat16_rn(v1));
        const int pos = mg * 8 + PERM8(m);
        g_VTh[obase + pos] = pack_bf(h0, h1);
        g_VTl[obase + pos] = pack_bf(v0 - h0, v1 - h1);
    }
}

// ---------------- bf16x3 tensor-core flash attention -------------------------
#define AQH 0
#define AQL 8192
#define AKH 16384
#define AKL 24576
#define AVH 32768
#define AVL 40960
#define ASF 49152
#define APH 53504
#define APL 55552
#define AAS 57600
#define ALS 57664
#define SMEM_ATTN (57728 * 4)

__global__ __launch_bounds__(256, 1) void attn_mma(const float* __restrict__ mask)
{
    extern __shared__ uint32_t su[];
    float* S   = (float*)(su + ASF);
    float* Asc = (float*)(su + AAS);
    float* Lsc = (float*)(su + ALS);

    const int tid = threadIdx.x;
    const int qt = blockIdx.x;
    const int h  = blockIdx.y;
    const int b  = blockIdx.z;
    const int hkv = h >> 1;
    const int wid = tid >> 5, lane = tid & 31;
    const int wm = wid >> 1, wn = wid & 1;
    const int lr = lane >> 2, lc = lane & 3;
    const int srow = tid >> 2, spart = tid & 3;

    const uint32_t sb = (uint32_t)__cvta_generic_to_shared(su);

    {
        const uint32_t* qsrc[2] = { g_Qh, g_Ql };
        const uint32_t* ksrc[2] = { g_Kh, g_Kl };
#pragma unroll
        for (int pl = 0; pl < 2; pl++) {
            for (int i = tid; i < 2048; i += 256) {
                const int row = i >> 5, ch = i & 31;
                const uint32_t dst = sb + ((pl ? AQL : AQH) + row * 128 +
                                           (((2 * ch) ^ ((row & 3) << 2)) * 2)) * 4;
                cpa16(dst, qsrc[pl] + (((size_t)b * LT + qt * 64 + row) * NH + h) * 128 + ch * 4);
            }
            for (int i = tid; i < 2048; i += 256) {
                const int row = i >> 5, ch = i & 31;
                const uint32_t dst = sb + ((pl ? AKL : AKH) + row * 128 +
                                           (((2 * ch) ^ ((row & 3) << 2)) * 2)) * 4;
                cpa16(dst, ksrc[pl] + (((size_t)b * LT + row) * NKV + hkv) * 128 + ch * 4);
            }
        }
        asm volatile("cp.async.commit_group;");
        const uint32_t* vsrc[2] = { g_VTh, g_VTl };
#pragma unroll
        for (int pl = 0; pl < 2; pl++)
            for (int i = tid; i < 2048; i += 256) {
                const int row = i >> 3, ch = i & 7;
                const uint32_t dst = sb + ((pl ? AVL : AVH) + row * 32 +
                                           (((2 * ch) ^ ((row & 3) << 2)) * 2)) * 4;
                cpa16(dst, vsrc[pl] + (((size_t)b * NKV + hkv) * DHD + row) * (LT / 2) + ch * 4);
            }
        asm volatile("cp.async.commit_group;");
    }

    float accO[16][4];
#pragma unroll
    for (int i = 0; i < 16; i++)
#pragma unroll
        for (int j = 0; j < 4; j++) accO[i][j] = 0.f;
    float m_run = -1e30f, l_run = 0.f;

    const int fsw = (lr & 3) << 2;

    for (int kt = 0; kt < LT / 64; kt++) {
        asm volatile("cp.async.wait_group 1;");
        __syncthreads();

        float accS[4][4];
#pragma unroll
        for (int i = 0; i < 4; i++)
#pragma unroll
            for (int j = 0; j < 4; j++) accS[i][j] = 0.f;
        {
            const uint32_t* qh = su + AQH + (wm * 16 + lr) * 128;
            const uint32_t* ql = su + AQL + (wm * 16 + lr) * 128;
            const uint32_t* kh = su + AKH + (wn * 32 + lr) * 128;
            const uint32_t* kl = su + AKL + (wn * 32 + lr) * 128;
#pragma unroll 4
            for (int g = 0; g < 16; g++) {
                const int q2 = ((g * 4 + lc) ^ fsw) * 2;
                uint32_t ah[4], al[4];
                uint2 t;
                t = *(const uint2*)(qh + q2);             ah[0] = t.x; ah[2] = t.y;
                t = *(const uint2*)(qh + 8 * 128 + q2);   ah[1] = t.x; ah[3] = t.y;
                t = *(const uint2*)(ql + q2);             al[0] = t.x; al[2] = t.y;
                t = *(const uint2*)(ql + 8 * 128 + q2);   al[1] = t.x; al[3] = t.y;
#pragma unroll
                for (int nf = 0; nf < 4; nf++) {
                    uint32_t bh[2], bl[2];
                    t = *(const uint2*)(kh + nf * 8 * 128 + q2);  bh[0] = t.x; bh[1] = t.y;
                    t = *(const uint2*)(kl + nf * 8 * 128 + q2);  bl[0] = t.x; bl[1] = t.y;
                    MMA_BF16(accS[nf], al, bh);
                    MMA_BF16(accS[nf], ah, bl);
                    MMA_BF16(accS[nf], ah, bh);
                }
            }
        }
        {
            const size_t mrow0 = ((size_t)b * LT + qt * 64 + wm * 16 + lr) * LT + kt * 64 + wn * 32;
            const size_t mrow1 = mrow0 + (size_t)8 * LT;
#pragma unroll
            for (int nf = 0; nf < 4; nf++) {
                const int col = nf * 8 + lc * 2;
                const float2 m0 = *(const float2*)&mask[mrow0 + col];
                const float2 m1 = *(const float2*)&mask[mrow1 + col];
                *(float2*)&S[(wm * 16 + lr) * 68 + wn * 32 + col] =
                    make_float2(accS[nf][0] + m0.x, accS[nf][1] + m0.y);
                *(float2*)&S[(wm * 16 + lr + 8) * 68 + wn * 32 + col] =
                    make_float2(accS[nf][2] + m1.x, accS[nf][3] + m1.y);
            }
        }
        __syncthreads();

        if (kt + 1 < LT / 64) {
            const uint32_t* ksrc[2] = { g_Kh, g_Kl };
#pragma unroll
            for (int pl = 0; pl < 2; pl++)
                for (int i = tid; i < 2048; i += 256) {
                    const int row = i >> 5, ch = i & 31;
                    const uint32_t dst = sb + ((pl ? AKL : AKH) + row * 128 +
                                               (((2 * ch) ^ ((row & 3) << 2)) * 2)) * 4;
                    cpa16(dst, ksrc[pl] + (((size_t)b * LT + (kt + 1) * 64 + row) * NKV + hkv) * 128 + ch * 4);
                }
            asm volatile("cp.async.commit_group;");
        }

        {
            float* sp = S + srow * 68 + spart * 16;
            float pv[16];
            float lm = -1e30f;
#pragma unroll
            for (int j = 0; j < 16; j++) { pv[j] = sp[j]; lm = fmaxf(lm, pv[j]); }
            lm = fmaxf(lm, __shfl_xor_sync(0xffffffffu, lm, 1));
            lm = fmaxf(lm, __shfl_xor_sync(0xffffffffu, lm, 2));
            const float mnew = fmaxf(m_run, lm);
            const float alpha = __expf(m_run - mnew);
            float ls = 0.f;
#pragma unroll
            for (int j = 0; j < 16; j++) { pv[j] = __expf(pv[j] - mnew); ls += pv[j]; }
            ls += __shfl_xor_sync(0xffffffffu, ls, 1);
            ls += __shfl_xor_sync(0xffffffffu, ls, 2);
            l_run = l_run * alpha + ls;
            m_run = mnew;
            if (spart == 0) Asc[srow] = alpha;

            const int swz = (srow & 3) << 2;
#pragma unroll
            for (int m = 0; m < 8; m++) {
                const float p0 = pv[2 * m], p1 = pv[2 * m + 1];
                const float h0 = __bfloat162float(__float2bfloat16_rn(p0));
                const float h1 = __bfloat162float(__float2bfloat16_rn(p1));
                const int u = spart * 8 + PERM8(m);
                const int pos = srow * 32 + (((u >> 1) ^ swz) * 2) + (u & 1);
                su[APH + pos] = pack_bf(h0, h1);
                su[APL + pos] = pack_bf(p0 - h0, p1 - h1);
            }
        }
        if (kt + 1 < LT / 64) { asm volatile("cp.async.wait_group 1;"); }
        else                  { asm volatile("cp.async.wait_group 0;"); }
        __syncthreads();

        {
            const float a0 = Asc[wm * 16 + lr];
            const float a1 = Asc[wm * 16 + lr + 8];
#pragma unroll
            for (int nf = 0; nf < 16; nf++) {
                accO[nf][0] *= a0; accO[nf][1] *= a0;
                accO[nf][2] *= a1; accO[nf][3] *= a1;
            }
            const uint32_t* php = su + APH + (wm * 16 + lr) * 32;
            const uint32_t* plp = su + APL + (wm * 16 + lr) * 32;
            const uint32_t* vhp = su + AVH + (wn * 128 + lr) * 32;
            const uint32_t* vlp = su + AVL + (wn * 128 + lr) * 32;
#pragma unroll
            for (int g = 0; g < 4; g++) {
                const int q2 = ((g * 4 + lc) ^ fsw) * 2;
                uint32_t ph[4], pl[4];
                uint2 t;
                t = *(const uint2*)(php + q2);            ph[0] = t.x; ph[2] = t.y;
                t = *(const uint2*)(php + 8 * 32 + q2);   ph[1] = t.x; ph[3] = t.y;
                t = *(const uint2*)(plp + q2);            pl[0] = t.x; pl[2] = t.y;
                t = *(const uint2*)(plp + 8 * 32 + q2);   pl[1] = t.x; pl[3] = t.y;
#pragma unroll
                for (int nf = 0; nf < 16; nf++) {
                    uint32_t vh[2], vl[2];
                    t = *(const uint2*)(vhp + nf * 8 * 32 + q2);  vh[0] = t.x; vh[1] = t.y;
                    t = *(const uint2*)(vlp + nf * 8 * 32 + q2);  vl[0] = t.x; vl[1] = t.y;
                    MMA_BF16(accO[nf], pl, vh);
                    MMA_BF16(accO[nf], ph, vl);
                    MMA_BF16(accO[nf], ph, vh);
                }
            }
        }
        __syncthreads();

        if (kt + 1 < LT / 64) {
            const uint32_t* vsrc[2] = { g_VTh, g_VTl };
#pragma unroll
            for (int pl = 0; pl < 2; pl++)
                for (int i = tid; i < 2048; i += 256) {
                    const int row = i >> 3, ch = i & 7;
                    const uint32_t dst = sb + ((pl ? AVL : AVH) + row * 32 +
                                               (((2 * ch) ^ ((row & 3) << 2)) * 2)) * 4;
                    cpa16(dst, vsrc[pl] + (((size_t)b * NKV + hkv) * DHD + row) * (LT / 2) +
                               (kt + 1) * 32 + ch * 4);
                }
            asm volatile("cp.async.commit_group;");
        }
    }

    if (spart == 0) Lsc[srow] = l_run;
    __syncthreads();

    {
        const float il0 = 1.f / Lsc[wm * 16 + lr];
        const float il1 = 1.f / Lsc[wm * 16 + lr + 8];
        const size_t r0 = (size_t)b * LT + qt * 64 + wm * 16 + lr;
        const size_t r1 = r0 + 8;
#pragma unroll
        for (int nf = 0; nf < 16; nf++) {
            const int p = h * 128 + wn * 64 + nf * 4 + lc;
            const int pos = (p & ~7) | PERM8(p & 7);
            const float v0 = accO[nf][0] * il0, v1 = accO[nf][1] * il0;
            const float v2 = accO[nf][2] * il1, v3 = accO[nf][3] * il1;
            const float h0 = __bfloat162float(__float2bfloat16_rn(v0));
            const float h1 = __bfloat162float(__float2bfloat16_rn(v1));
            const float h2 = __bfloat162float(__float2bfloat16_rn(v2));
            const float h3 = __bfloat162float(__float2bfloat16_rn(v3));
            g_ahi[r0 * 1024 + pos] = pack_bf(h0, h1);
            g_alo[r0 * 1024 + pos] = pack_bf(v0 - h0, v1 - h1);
            g_ahi[r1 * 1024 + pos] = pack_bf(h2, h3);
            g_alo[r1 * 1024 + pos] = pack_bf(v2 - h2, v3 - h3);
        }
    }
}

// ---------------- launch ----------------------------------------------------
extern "C" void kernel_launch(void* const* d_in, const int* in_sizes, int n_in,
                              void* d_out, int out_size)
{
    const float* pg   = (const float*)d_in[0];
    const float* ex   = (const float*)d_in[1];
    const float* cs   = (const float*)d_in[2];
    const float* sn   = (const float*)d_in[3];
    const float* mask = (const float*)d_in[4];
    const float* Wq0  = (const float*)d_in[5];
    const float* Wk0  = (const float*)d_in[6];
    const float* Wv0  = (const float*)d_in[7];
    const float* Wo0  = (const float*)d_in[8];
    const float* Wq1  = (const float*)d_in[9];
    const float* Wk1  = (const float*)d_in[10];
    const float* Wv1  = (const float*)d_in[11];
    const float* Wo1  = (const float*)d_in[12];
    float* out = (float*)d_out;

    float *Qd, *Kd, *Vd;
    uint32_t *Ahd, *Ald, *Hv, *Lv, *Qhp, *Qlp, *Khp, *Klp;
    cudaGetSymbolAddress((void**)&Qd, g_Q);
    cudaGetSymbolAddress((void**)&Kd, g_K);
    cudaGetSymbolAddress((void**)&Vd, g_V);
    cudaGetSymbolAddress((void**)&Ahd, g_ahi);
    cudaGetSymbolAddress((void**)&Ald, g_alo);
    cudaGetSymbolAddress((void**)&Hv, g_hi);
    cudaGetSymbolAddress((void**)&Lv, g_lo);
    cudaGetSymbolAddress((void**)&Qhp, g_Qh);
    cudaGetSymbolAddress((void**)&Qlp, g_Ql);
    cudaGetSymbolAddress((void**)&Khp, g_Kh);
    cudaGetSymbolAddress((void**)&Klp, g_Kl);

    cudaFuncSetAttribute(gemm_b3, cudaFuncAttributeMaxDynamicSharedMemorySize, GSM_BYTES);
    cudaFuncSetAttribute(attn_mma, cudaFuncAttributeMaxDynamicSharedMemorySize, SMEM_ATTN);

    const int MQ = NH * DHD;    // 2048
    const int MKV = NKV * DHD;  // 1024

    // --- split projection operands into permuted bf16 hi/lo planes ---
    CvtArgs ca;
    const float* srcs[10] = { pg, ex, Wq0, Wk0, Wv0, Wo0, Wq1, Wk1, Wv1, Wo1 };
    const uint32_t offs[10] = { OP_PG, OP_EX, OP_WQ0, OP_WK0, OP_WV0,
                                OP_WO0, OP_WQ1, OP_WK1, OP_WV1, OP_WO1 };
    const int ns[10] = { BB * L1C * DPG, BB * L2C * DEX, MQ * DPG, MKV * DPG,
                         MKV * DPG, DPG * MQ, MQ * DEX, MKV * DEX, MKV * DEX, DEX * MQ };
    int maxg = 0;
    for (int i = 0; i < 10; i++) {
        ca.src[i] = srcs[i]; ca.off[i] = offs[i]; ca.n16[i] = ns[i] / 16;
        if (ca.n16[i] > maxg) maxg = ca.n16[i];
    }
    cvt_bsplit<<<dim3((maxg + 255) / 256, 10), 256>>>(ca);

    // --- fused QKV projection, pg stream: N = 4096 stacked, K2 = 1152 ---
    gemm_b3<<<dim3(32, 32), 256, GSM_BYTES>>>(
        Hv + OP_PG, Lv + OP_PG, Hv + OP_WQ0, Lv + OP_WQ0, DPG / 2,
        BB * L1C, 0, 0, L1C, LT, 0,
        MQ, MQ + MKV, Qd, MQ, Kd, MKV, Vd, MKV);

    // --- fused QKV projection, ex stream: N = 4096 stacked, K2 = 512 ---
    gemm_b3<<<dim3(32, 16), 256, GSM_BYTES>>>(
        Hv + OP_EX, Lv + OP_EX, Hv + OP_WQ1, Lv + OP_WQ1, DEX / 2,
        BB * L2C, 0, 0, L2C, LT, L1C,
        MQ, MQ + MKV, Qd, MQ, Kd, MKV, Vd, MKV);

    // --- RoPE + split/pack planes; V transpose/pack ---
    rope_pack<<<dim3(NH, LT, BB), 64>>>(Qd, cs, sn, NH, QK_SCALE, Qhp, Qlp);
    rope_pack<<<dim3(NKV, LT, BB), 64>>>(Kd, cs, sn, NKV, 1.0f, Khp, Klp);
    vt_pack<<<dim3(LT / 64, DHD / 64, BB * NKV), 256>>>();

    // --- attention ---
    attn_mma<<<dim3(LT / 64, NH, BB), 256, SMEM_ATTN>>>(mask);

    // --- output projections (K2 = 1024) ---
    gemm_b3<<<dim3(DPG / 128, 32), 256, GSM_BYTES>>>(
        Ahd, Ald, Hv + OP_WO0, Lv + OP_WO0, MQ / 2,
        L1C, LT, 0, BB * L1C, 0, 0,
        DPG, DPG, out, DPG, out, DPG, out, DPG);
    gemm_b3<<<dim3(DEX / 128, 16), 256, GSM_BYTES>>>(
        Ahd, Ald, Hv + OP_WO1, Lv + OP_WO1, MQ / 2,
        L2C, LT, L1C, BB * L2C, 0, 0,
        DEX, DEX, out + (size_t)BB * L1C * DPG, DEX,
        out + (size_t)BB * L1C * DPG, DEX, out + (size_t)BB * L1C * DPG, DEX);
}

// round 9
// speedup vs baseline: 2.4337x; 1.0220x over previous
#include <cuda_runtime.h>
#include <cuda_bf16.h>
#include <math.h>
#include <stdint.h>

#define BB   4
#define L1C  1024
#define L2C  512
#define LT   1536
#define DPG  2304
#define DEX  1024
#define NH   8
#define NKV  4
#define DHD  256
#define QK_SCALE 0.0625f

#define PERM8(j) ((((j) & 3) << 1) | ((j) >> 2))

// ---------------- scratch (device globals) -----------------------------------
__device__ float g_Q[(size_t)BB * LT * NH * DHD];
__device__ float g_K[(size_t)BB * LT * NKV * DHD];
__device__ float g_V[(size_t)BB * LT * NKV * DHD];

__device__ uint32_t g_Qh[(size_t)BB * LT * NH * 128];
__device__ uint32_t g_Ql[(size_t)BB * LT * NH * 128];
__device__ uint32_t g_Kh[(size_t)BB * LT * NKV * 128];
__device__ uint32_t g_Kl[(size_t)BB * LT * NKV * 128];

__device__ uint32_t g_VTh[(size_t)BB * NKV * DHD * (LT / 2)];
__device__ uint32_t g_VTl[(size_t)BB * NKV * DHD * (LT / 2)];

__device__ uint32_t g_ahi[(size_t)BB * LT * NH * 128];
__device__ uint32_t g_alo[(size_t)BB * LT * NH * 128];

#define OP_PG   0u
#define OP_EX   4718592u
#define OP_WQ0  5767168u
#define OP_WK0  8126464u
#define OP_WV0  9306112u
#define OP_WO0  10485760u
#define OP_WQ1  12845056u
#define OP_WK1  13893632u
#define OP_WV1  14417920u
#define OP_WO1  14942208u
#define OP_TOT  15990784u
__device__ uint32_t g_hi[OP_TOT];
__device__ uint32_t g_lo[OP_TOT];

// ---------------- helpers ----------------------------------------------------
__device__ __forceinline__ uint32_t pack_bf(float a, float b)
{
    __nv_bfloat162 t = __floats2bfloat162_rn(a, b);
    return *(uint32_t*)&t;
}
__device__ __forceinline__ void cpa16(uint32_t dst, const void* src)
{
    asm volatile("cp.async.cg.shared.global [%0], [%1], 16;" :: "r"(dst), "l"(src));
}

#define MMA_BF16(d, a, b)                                                     \
    asm volatile("mma.sync.aligned.m16n8k16.row.col.f32.bf16.bf16.f32 "       \
                 "{%0,%1,%2,%3}, {%4,%5,%6,%7}, {%8,%9}, {%0,%1,%2,%3};"      \
                 : "+f"(d[0]), "+f"(d[1]), "+f"(d[2]), "+f"(d[3])             \
                 : "r"(a[0]), "r"(a[1]), "r"(a[2]), "r"(a[3]),                \
                   "r"(b[0]), "r"(b[1]))

// ---------------- fused bf16-split conversion --------------------------------
struct CvtArgs {
    const float* src[10];
    uint32_t off[10];
    int n16[10];
};

__global__ void cvt_bsplit(CvtArgs a)
{
    const int e = blockIdx.y;
    const int i = blockIdx.x * blockDim.x + threadIdx.x;
    if (i >= a.n16[e]) return;
    const float4* s = (const float4*)(a.src[e]) + (size_t)i * 4;
    uint32_t* hb = g_hi + a.off[e] + (size_t)i * 8;
    uint32_t* lb = g_lo + a.off[e] + (size_t)i * 8;
    float v[16];
#pragma unroll
    for (int q = 0; q < 4; q++) {
        float4 f = s[q];
        v[q * 4 + 0] = f.x; v[q * 4 + 1] = f.y; v[q * 4 + 2] = f.z; v[q * 4 + 3] = f.w;
    }
#pragma unroll
    for (int j = 0; j < 8; j++) {
        const float x0 = v[2 * j], x1 = v[2 * j + 1];
        const float h0 = __bfloat162float(__float2bfloat16_rn(x0));
        const float h1 = __bfloat162float(__float2bfloat16_rn(x1));
        const int p = PERM8(j);
        hb[p] = pack_bf(h0, h1);
        lb[p] = pack_bf(x0 - h0, x1 - h1);
    }
}

// ---------------- bf16x3 NT GEMM, dual-job (blockIdx.z) ----------------------
#define CH 16
#define PLN (128 * CH)
#define STG (4 * PLN)
#define GSM_BYTES (3 * STG * 4)

struct GemmJob {
    const uint32_t *Ah, *Al, *Wh, *Wl;
    int K2;
    int a_rpb, a_bs, a_off;
    int c_rpb, c_bs, c_off;
    int n1, n2;
    float *C0, *C1, *C2;
    int ldc0, ldc1, ldc2;
    int gx, gy;
};

__global__ __launch_bounds__(256, 2) void gemm_b3(GemmJob j0, GemmJob j1)
{
    const GemmJob J = blockIdx.z ? j1 : j0;
    if ((int)blockIdx.x >= J.gx || (int)blockIdx.y >= J.gy) return;

    extern __shared__ uint32_t smg[];
    const int tid = threadIdx.x;
    const int wid = tid >> 5, lane = tid & 31;
    const int warp_m = wid >> 1, warp_n = wid & 1;
    const int bm = blockIdx.y * 128, bn = blockIdx.x * 128;
    const int K2 = J.K2;

    const int p  = tid >> 6;
    const int rr = tid & 63;
    const int r0 = rr * 2, r1 = rr * 2 + 1;
    int gr0, gr1;
    if (p < 2) {
        const int m0 = bm + r0, m1 = bm + r1;
        gr0 = (m0 / J.a_rpb) * J.a_bs + J.a_off + (m0 % J.a_rpb);
        gr1 = (m1 / J.a_rpb) * J.a_bs + J.a_off + (m1 % J.a_rpb);
    } else {
        gr0 = bn + r0; gr1 = bn + r1;
    }
    const uint32_t* pb = (p == 0) ? J.Ah : (p == 1) ? J.Al : (p == 2) ? J.Wh : J.Wl;
    const uint32_t* s0 = pb + (size_t)gr0 * K2;
    const uint32_t* s1 = pb + (size_t)gr1 * K2;

    const uint32_t sbase = (uint32_t)__cvta_generic_to_shared(smg);
    const int sw0 = (r0 & 2) << 1, sw1 = (r1 & 2) << 1;
    uint32_t d0[4], d1[4];
#pragma unroll
    for (int j = 0; j < 4; j++) {
        d0[j] = sbase + (p * PLN + r0 * CH) * 4 + (((2 * j) ^ sw0) * 2) * 4;
        d1[j] = sbase + (p * PLN + r1 * CH) * 4 + (((2 * j) ^ sw1) * 2) * 4;
    }

    float acc[2][8][4];
#pragma unroll
    for (int i = 0; i < 2; i++)
#pragma unroll
        for (int j = 0; j < 8; j++)
#pragma unroll
            for (int r = 0; r < 4; r++) acc[i][j][r] = 0.f;

    const int nk = K2 >> 4;

#define G_ISSUE(kc)                                                           \
    do {                                                                      \
        const int _ko = (kc) * CH;                                            \
        const uint32_t _sb = ((kc) % 3) * STG * 4;                            \
        _Pragma("unroll")                                                     \
        for (int j = 0; j < 4; j++) {                                         \
            cpa16(d0[j] + _sb, s0 + _ko + j * 4);                             \
            cpa16(d1[j] + _sb, s1 + _ko + j * 4);                             \
        }                                                                     \
        asm volatile("cp.async.commit_group;");                               \
    } while (0)

    G_ISSUE(0);
    G_ISSUE(1);

    const int lr = lane >> 2, lc = lane & 3;
    const int fsw = (lr & 2) << 1;

    for (int kc = 0; kc < nk; kc++) {
        if (kc + 2 < nk) { asm volatile("cp.async.wait_group 1;"); }
        else             { asm volatile("cp.async.wait_group 0;"); }
        __syncthreads();
        if (kc + 2 < nk) G_ISSUE(kc + 2);

        const uint32_t* st = smg + (kc % 3) * STG;
        const uint32_t* ah_p = st + 0 * PLN + (warp_m * 32 + lr) * CH;
        const uint32_t* al_p = st + 1 * PLN + (warp_m * 32 + lr) * CH;
        const uint32_t* wh_p = st + 2 * PLN + (warp_n * 64 + lr) * CH;
        const uint32_t* wl_p = st + 3 * PLN + (warp_n * 64 + lr) * CH;

#pragma unroll
        for (int g = 0; g < 2; g++) {
            const int q2 = ((g * 4 + lc) ^ fsw) * 2;
            uint32_t ah[2][4], al[2][4];
            uint2 t;
#pragma unroll
            for (int mf = 0; mf < 2; mf++) {
                t = *(const uint2*)(ah_p + mf * 16 * CH + q2);            ah[mf][0] = t.x; ah[mf][2] = t.y;
                t = *(const uint2*)(ah_p + mf * 16 * CH + 8 * CH + q2);   ah[mf][1] = t.x; ah[mf][3] = t.y;
                t = *(const uint2*)(al_p + mf * 16 * CH + q2);            al[mf][0] = t.x; al[mf][2] = t.y;
                t = *(const uint2*)(al_p + mf * 16 * CH + 8 * CH + q2);   al[mf][1] = t.x; al[mf][3] = t.y;
            }
#pragma unroll
            for (int nf = 0; nf < 8; nf++) {
                uint32_t bh[2], bl[2];
                t = *(const uint2*)(wh_p + nf * 8 * CH + q2);  bh[0] = t.x; bh[1] = t.y;
                t = *(const uint2*)(wl_p + nf * 8 * CH + q2);  bl[0] = t.x; bl[1] = t.y;
#pragma unroll
                for (int mf = 0; mf < 2; mf++) {
                    MMA_BF16(acc[mf][nf], al[mf], bh);
                    MMA_BF16(acc[mf][nf], ah[mf], bl);
                    MMA_BF16(acc[mf][nf], ah[mf], bh);
                }
            }
        }
        __syncthreads();
    }
#undef G_ISSUE

    float* Cb; int ldc, coff;
    if (bn < J.n1)      { Cb = J.C0; ldc = J.ldc0; coff = 0;    }
    else if (bn < J.n2) { Cb = J.C1; ldc = J.ldc1; coff = J.n1; }
    else                { Cb = J.C2; ldc = J.ldc2; coff = J.n2; }

#pragma unroll
    for (int mf = 0; mf < 2; mf++) {
        const int m0 = bm + warp_m * 32 + mf * 16 + lr;
        const int m1 = m0 + 8;
        const int cr0 = (m0 / J.c_rpb) * J.c_bs + J.c_off + (m0 % J.c_rpb);
        const int cr1 = (m1 / J.c_rpb) * J.c_bs + J.c_off + (m1 % J.c_rpb);
#pragma unroll
        for (int nf = 0; nf < 8; nf++) {
            const int col = bn - coff + warp_n * 64 + nf * 8 + lc * 2;
            *(float2*)&Cb[(size_t)cr0 * ldc + col] = make_float2(acc[mf][nf][0], acc[mf][nf][1]);
            *(float2*)&Cb[(size_t)cr1 * ldc + col] = make_float2(acc[mf][nf][2], acc[mf][nf][3]);
        }
    }
}

// ---------------- RoPE + bf16 split + pack -----------------------------------
__global__ void rope_pack(const float* __restrict__ X, const float* __restrict__ cs,
                          const float* __restrict__ sn, int nheads, float scale,
                          uint32_t* __restrict__ oh, uint32_t* __restrict__ ol)
{
    const int h = blockIdx.x;
    const int l = blockIdx.y;
    const int b = blockIdx.z;
    const int j = threadIdx.x;
    const size_t row = (size_t)b * LT + l;
    const float2 c2 = *(const float2*)&cs[row * 128 + 2 * j];
    const float2 s2 = *(const float2*)&sn[row * 128 + 2 * j];
    const size_t base = (row * nheads + h) * DHD;
    const float2 xa = *(const float2*)&X[base + 2 * j];
    const float2 xb = *(const float2*)&X[base + 128 + 2 * j];
    const float y1a = (xa.x * c2.x - xb.x * s2.x) * scale;
    const float y1b = (xa.y * c2.y - xb.y * s2.y) * scale;
    const float y2a = (xb.x * c2.x + xa.x * s2.x) * scale;
    const float y2b = (xb.y * c2.y + xa.y * s2.y) * scale;

    const size_t ob = (row * nheads + h) * 128;
    const int p1 = (j & ~7) | PERM8(j & 7);
    const int p2 = 64 + p1;
    const float h1a = __bfloat162float(__float2bfloat16_rn(y1a));
    const float h1b = __bfloat162float(__float2bfloat16_rn(y1b));
    const float h2a = __bfloat162float(__float2bfloat16_rn(y2a));
    const float h2b = __bfloat162float(__float2bfloat16_rn(y2b));
    oh[ob + p1] = pack_bf(h1a, h1b);
    ol[ob + p1] = pack_bf(y1a - h1a, y1b - h1b);
    oh[ob + p2] = pack_bf(h2a, h2b);
    ol[ob + p2] = pack_bf(y2a - h2a, y2b - h2b);
}

// ---------------- V transpose + bf16 split -----------------------------------
__global__ __launch_bounds__(256) void vt_pack()
{
    __shared__ float t[64][65];
    const int b   = blockIdx.z >> 2;
    const int hkv = blockIdx.z & 3;
    const int l0 = blockIdx.x * 64;
    const int d0 = blockIdx.y * 64;
    const int tid = threadIdx.x;

    for (int i = tid; i < 64 * 64; i += 256) {
        const int lrow = i >> 6, dcol = i & 63;
        t[lrow][dcol] = g_V[(((size_t)b * LT + l0 + lrow) * NKV + hkv) * DHD + d0 + dcol];
    }
    __syncthreads();

    const int drow = tid & 63;
    const int mg = tid >> 6;
    const size_t obase = (((size_t)b * NKV + hkv) * DHD + d0 + drow) * (LT / 2) + l0 / 2;
#pragma unroll
    for (int m = 0; m < 8; m++) {
        const int lp = mg * 8 + m;
        const float v0 = t[2 * lp][drow];
        const float v1 = t[2 * lp + 1][drow];
        const float h0 = __bfloat162float(__float2bfloat16_rn(v0));
        const float h1 = __bfloat162float(__float2bfloat16_rn(v1));
        const int pos = mg * 8 + PERM8(m);
        g_VTh[obase + pos] = pack_bf(h0, h1);
        g_VTl[obase + pos] = pack_bf(v0 - h0, v1 - h1);
    }
}

// ---------------- bf16x3 flash attention, 512 threads ------------------------
#define AQH 0
#define AQL 8192
#define AKH 16384
#define AKL 24576
#define AVH 32768
#define AVL 40960
#define ASF 49152
#define APH 53504
#define APL 55552
#define AAS 57600
#define ALS 57664
#define SMEM_ATTN (57728 * 4)

__global__ __launch_bounds__(512, 1) void attn_mma(const float* __restrict__ mask)
{
    extern __shared__ uint32_t su[];
    float* S   = (float*)(su + ASF);
    float* Asc = (float*)(su + AAS);
    float* Lsc = (float*)(su + ALS);

    const int tid = threadIdx.x;
    const int qt = blockIdx.x;
    const int h  = blockIdx.y;
    const int b  = blockIdx.z;
    const int hkv = h >> 1;
    const int wid = tid >> 5, lane = tid & 31;
    const int wm = wid & 3, wn = wid >> 2;       // 4x4 warp grid
    const int lr = lane >> 2, lc = lane & 3;
    const int srow = tid >> 3, part = tid & 7;   // softmax: 8 threads/row

    const uint32_t sb = (uint32_t)__cvta_generic_to_shared(su);

    // ---- prologue: Q + K(0) (group 0), V(0) (group 1) ----
    {
        const uint32_t* qsrc[2] = { g_Qh, g_Ql };
        const uint32_t* ksrc[2] = { g_Kh, g_Kl };
#pragma unroll
        for (int pl = 0; pl < 2; pl++) {
            for (int i = tid; i < 2048; i += 512) {
                const int row = i >> 5, ch = i & 31;
                const uint32_t dst = sb + ((pl ? AQL : AQH) + row * 128 +
                                           (((2 * ch) ^ ((row & 3) << 2)) * 2)) * 4;
                cpa16(dst, qsrc[pl] + (((size_t)b * LT + qt * 64 + row) * NH + h) * 128 + ch * 4);
            }
            for (int i = tid; i < 2048; i += 512) {
                const int row = i >> 5, ch = i & 31;
                const uint32_t dst = sb + ((pl ? AKL : AKH) + row * 128 +
                                           (((2 * ch) ^ ((row & 3) << 2)) * 2)) * 4;
                cpa16(dst, ksrc[pl] + (((size_t)b * LT + row) * NKV + hkv) * 128 + ch * 4);
            }
        }
        asm volatile("cp.async.commit_group;");
        const uint32_t* vsrc[2] = { g_VTh, g_VTl };
#pragma unroll
        for (int pl = 0; pl < 2; pl++)
            for (int i = tid; i < 2048; i += 512) {
                const int row = i >> 3, ch = i & 7;
                const uint32_t dst = sb + ((pl ? AVL : AVH) + row * 32 +
                                           (((2 * ch) ^ ((row & 3) << 2)) * 2)) * 4;
                cpa16(dst, vsrc[pl] + (((size_t)b * NKV + hkv) * DHD + row) * (LT / 2) + ch * 4);
            }
        asm volatile("cp.async.commit_group;");
    }

    float accO[8][4];
#pragma unroll
    for (int i = 0; i < 8; i++)
#pragma unroll
        for (int j = 0; j < 4; j++) accO[i][j] = 0.f;
    float m_run = -1e30f, l_run = 0.f;

    const int fsw = (lr & 3) << 2;

    for (int kt = 0; kt < LT / 64; kt++) {
        asm volatile("cp.async.wait_group 1;");
        __syncthreads();

        // ---- S = Q K^T : warp tile 16x16, k = 256 ----
        float accS[2][4];
#pragma unroll
        for (int i = 0; i < 2; i++)
#pragma unroll
            for (int j = 0; j < 4; j++) accS[i][j] = 0.f;
        {
            const uint32_t* qh = su + AQH + (wm * 16 + lr) * 128;
            const uint32_t* ql = su + AQL + (wm * 16 + lr) * 128;
            const uint32_t* kh = su + AKH + (wn * 16 + lr) * 128;
            const uint32_t* kl = su + AKL + (wn * 16 + lr) * 128;
#pragma unroll 4
            for (int g = 0; g < 16; g++) {
                const int q2 = ((g * 4 + lc) ^ fsw) * 2;
                uint32_t ah[4], al[4];
                uint2 t;
                t = *(const uint2*)(qh + q2);             ah[0] = t.x; ah[2] = t.y;
                t = *(const uint2*)(qh + 8 * 128 + q2);   ah[1] = t.x; ah[3] = t.y;
                t = *(const uint2*)(ql + q2);             al[0] = t.x; al[2] = t.y;
                t = *(const uint2*)(ql + 8 * 128 + q2);   al[1] = t.x; al[3] = t.y;
#pragma unroll
                for (int nf = 0; nf < 2; nf++) {
                    uint32_t bh[2], bl[2];
                    t = *(const uint2*)(kh + nf * 8 * 128 + q2);  bh[0] = t.x; bh[1] = t.y;
                    t = *(const uint2*)(kl + nf * 8 * 128 + q2);  bl[0] = t.x; bl[1] = t.y;
                    MMA_BF16(accS[nf], al, bh);
                    MMA_BF16(accS[nf], ah, bl);
                    MMA_BF16(accS[nf], ah, bh);
                }
            }
        }
        // ---- add mask, write S ----
        {
            const size_t mrow0 = ((size_t)b * LT + qt * 64 + wm * 16 + lr) * LT + kt * 64 + wn * 16;
            const size_t mrow1 = mrow0 + (size_t)8 * LT;
#pragma unroll
            for (int nf = 0; nf < 2; nf++) {
                const int col = nf * 8 + lc * 2;
                const float2 m0 = *(const float2*)&mask[mrow0 + col];
                const float2 m1 = *(const float2*)&mask[mrow1 + col];
                *(float2*)&S[(wm * 16 + lr) * 68 + wn * 16 + col] =
                    make_float2(accS[nf][0] + m0.x, accS[nf][1] + m0.y);
                *(float2*)&S[(wm * 16 + lr + 8) * 68 + wn * 16 + col] =
                    make_float2(accS[nf][2] + m1.x, accS[nf][3] + m1.y);
            }
        }
        __syncthreads();

        if (kt + 1 < LT / 64) {
            const uint32_t* ksrc[2] = { g_Kh, g_Kl };
#pragma unroll
            for (int pl = 0; pl < 2; pl++)
                for (int i = tid; i < 2048; i += 512) {
                    const int row = i >> 5, ch = i & 31;
                    const uint32_t dst = sb + ((pl ? AKL : AKH) + row * 128 +
                                               (((2 * ch) ^ ((row & 3) << 2)) * 2)) * 4;
                    cpa16(dst, ksrc[pl] + (((size_t)b * LT + (kt + 1) * 64 + row) * NKV + hkv) * 128 + ch * 4);
                }
            asm volatile("cp.async.commit_group;");
        }

        // ---- online softmax: 8 threads per row, 8 cols each ----
        {
            float* sp = S + srow * 68 + part * 8;
            float pv[8];
            float lm = -1e30f;
#pragma unroll
            for (int j = 0; j < 8; j++) { pv[j] = sp[j]; lm = fmaxf(lm, pv[j]); }
            lm = fmaxf(lm, __shfl_xor_sync(0xffffffffu, lm, 1));
            lm = fmaxf(lm, __shfl_xor_sync(0xffffffffu, lm, 2));
            lm = fmaxf(lm, __shfl_xor_sync(0xffffffffu, lm, 4));
            const float mnew = fmaxf(m_run, lm);
            const float alpha = __expf(m_run - mnew);
            float ls = 0.f;
#pragma unroll
            for (int j = 0; j < 8; j++) { pv[j] = __expf(pv[j] - mnew); ls += pv[j]; }
            ls += __shfl_xor_sync(0xffffffffu, ls, 1);
            ls += __shfl_xor_sync(0xffffffffu, ls, 2);
            ls += __shfl_xor_sync(0xffffffffu, ls, 4);
            l_run = l_run * alpha + ls;
            m_run = mnew;
            if (part == 0) Asc[srow] = alpha;

            const int swz = (srow & 3) << 2;
#pragma unroll
            for (int m = 0; m < 4; m++) {
                const float p0 = pv[2 * m], p1 = pv[2 * m + 1];
                const float h0 = __bfloat162float(__float2bfloat16_rn(p0));
                const float h1 = __bfloat162float(__float2bfloat16_rn(p1));
                const int pp = part * 4 + m;
                const int u = (pp & ~7) | PERM8(pp & 7);
                const int pos = srow * 32 + (((u >> 1) ^ swz) * 2) + (u & 1);
                su[APH + pos] = pack_bf(h0, h1);
                su[APL + pos] = pack_bf(p0 - h0, p1 - h1);
            }
        }
        if (kt + 1 < LT / 64) { asm volatile("cp.async.wait_group 1;"); }
        else                  { asm volatile("cp.async.wait_group 0;"); }
        __syncthreads();

        // ---- rescale O, O += P V : warp tile 16x64, k = 64 ----
        {
            const float a0 = Asc[wm * 16 + lr];
            const float a1 = Asc[wm * 16 + lr + 8];
#pragma unroll
            for (int nf = 0; nf < 8; nf++) {
                accO[nf][0] *= a0; accO[nf][1] *= a0;
                accO[nf][2] *= a1; accO[nf][3] *= a1;
            }
            const uint32_t* php = su + APH + (wm * 16 + lr) * 32;
            const uint32_t* plp = su + APL + (wm * 16 + lr) * 32;
            const uint32_t* vhp = su + AVH + (wn * 64 + lr) * 32;
            const uint32_t* vlp = su + AVL + (wn * 64 + lr) * 32;
#pragma unroll
            for (int g = 0; g < 4; g++) {
                const int q2 = ((g * 4 + lc) ^ fsw) * 2;
                uint32_t ph[4], pl[4];
                uint2 t;
                t = *(const uint2*)(php + q2);            ph[0] = t.x; ph[2] = t.y;
                t = *(const uint2*)(php + 8 * 32 + q2);   ph[1] = t.x; ph[3] = t.y;
                t = *(const uint2*)(plp + q2);            pl[0] = t.x; pl[2] = t.y;
                t = *(const uint2*)(plp + 8 * 32 + q2);   pl[1] = t.x; pl[3] = t.y;
#pragma unroll
                for (int nf = 0; nf < 8; nf++) {
                    uint32_t vh[2], vl[2];
                    t = *(const uint2*)(vhp + nf * 8 * 32 + q2);  vh[0] = t.x; vh[1] = t.y;
                    t = *(const uint2*)(vlp + nf * 8 * 32 + q2);  vl[0] = t.x; vl[1] = t.y;
                    MMA_BF16(accO[nf], pl, vh);
                    MMA_BF16(accO[nf], ph, vl);
                    MMA_BF16(accO[nf], ph, vh);
                }
            }
        }
        __syncthreads();

        if (kt + 1 < LT / 64) {
            const uint32_t* vsrc[2] = { g_VTh, g_VTl };
#pragma unroll
            for (int pl = 0; pl < 2; pl++)
                for (int i = tid; i < 2048; i += 512) {
                    const int row = i >> 3, ch = i & 7;
                    const uint32_t dst = sb + ((pl ? AVL : AVH) + row * 32 +
                                               (((2 * ch) ^ ((row & 3) << 2)) * 2)) * 4;
                    cpa16(dst, vsrc[pl] + (((size_t)b * NKV + hkv) * DHD + row) * (LT / 2) +
                               (kt + 1) * 32 + ch * 4);
                }
            asm volatile("cp.async.commit_group;");
        }
    }

    if (part == 0) Lsc[srow] = l_run;
    __syncthreads();

    // ---- epilogue ----
    {
        const float il0 = 1.f / Lsc[wm * 16 + lr];
        const float il1 = 1.f / Lsc[wm * 16 + lr + 8];
        const size_t r0 = (size_t)b * LT + qt * 64 + wm * 16 + lr;
        const size_t r1 = r0 + 8;
#pragma unroll
        for (int nf = 0; nf < 8; nf++) {
            const int p = h * 128 + wn * 32 + nf * 4 + lc;
            const int pos = (p & ~7) | PERM8(p & 7);
            const float v0 = accO[nf][0] * il0, v1 = accO[nf][1] * il0;
            const float v2 = accO[nf][2] * il1, v3 = accO[nf][3] * il1;
            const float h0 = __bfloat162float(__float2bfloat16_rn(v0));
            const float h1 = __bfloat162float(__float2bfloat16_rn(v1));
            const float h2 = __bfloat162float(__float2bfloat16_rn(v2));
            const float h3 = __bfloat162float(__float2bfloat16_rn(v3));
            g_ahi[r0 * 1024 + pos] = pack_bf(h0, h1);
            g_alo[r0 * 1024 + pos] = pack_bf(v0 - h0, v1 - h1);
            g_ahi[r1 * 1024 + pos] = pack_bf(h2, h3);
            g_alo[r1 * 1024 + pos] = pack_bf(v2 - h2, v3 - h3);
        }
    }
}

// ---------------- launch ----------------------------------------------------
extern "C" void kernel_launch(void* const* d_in, const int* in_sizes, int n_in,
                              void* d_out, int out_size)
{
    const float* pg   = (const float*)d_in[0];
    const float* ex   = (const float*)d_in[1];
    const float* cs   = (const float*)d_in[2];
    const float* sn   = (const float*)d_in[3];
    const float* mask = (const float*)d_in[4];
    const float* Wq0  = (const float*)d_in[5];
    const float* Wk0  = (const float*)d_in[6];
    const float* Wv0  = (const float*)d_in[7];
    const float* Wo0  = (const float*)d_in[8];
    const float* Wq1  = (const float*)d_in[9];
    const float* Wk1  = (const float*)d_in[10];
    const float* Wv1  = (const float*)d_in[11];
    const float* Wo1  = (const float*)d_in[12];
    float* out = (float*)d_out;

    float *Qd, *Kd, *Vd;
    uint32_t *Ahd, *Ald, *Hv, *Lv, *Qhp, *Qlp, *Khp, *Klp;
    cudaGetSymbolAddress((void**)&Qd, g_Q);
    cudaGetSymbolAddress((void**)&Kd, g_K);
    cudaGetSymbolAddress((void**)&Vd, g_V);
    cudaGetSymbolAddress((void**)&Ahd, g_ahi);
    cudaGetSymbolAddress((void**)&Ald, g_alo);
    cudaGetSymbolAddress((void**)&Hv, g_hi);
    cudaGetSymbolAddress((void**)&Lv, g_lo);
    cudaGetSymbolAddress((void**)&Qhp, g_Qh);
    cudaGetSymbolAddress((void**)&Qlp, g_Ql);
    cudaGetSymbolAddress((void**)&Khp, g_Kh);
    cudaGetSymbolAddress((void**)&Klp, g_Kl);

    cudaFuncSetAttribute(gemm_b3, cudaFuncAttributeMaxDynamicSharedMemorySize, GSM_BYTES);
    cudaFuncSetAttribute(attn_mma, cudaFuncAttributeMaxDynamicSharedMemorySize, SMEM_ATTN);

    const int MQ = NH * DHD;    // 2048
    const int MKV = NKV * DHD;  // 1024

    // --- split projection operands ---
    CvtArgs ca;
    const float* srcs[10] = { pg, ex, Wq0, Wk0, Wv0, Wo0, Wq1, Wk1, Wv1, Wo1 };
    const uint32_t offs[10] = { OP_PG, OP_EX, OP_WQ0, OP_WK0, OP_WV0,
                                OP_WO0, OP_WQ1, OP_WK1, OP_WV1, OP_WO1 };
    const int ns[10] = { BB * L1C * DPG, BB * L2C * DEX, MQ * DPG, MKV * DPG,
                         MKV * DPG, DPG * MQ, MQ * DEX, MKV * DEX, MKV * DEX, DEX * MQ };
    int maxg = 0;
    for (int i = 0; i < 10; i++) {
        ca.src[i] = srcs[i]; ca.off[i] = offs[i]; ca.n16[i] = ns[i] / 16;
        if (ca.n16[i] > maxg) maxg = ca.n16[i];
    }
    cvt_bsplit<<<dim3((maxg + 255) / 256, 10), 256>>>(ca);

    // --- fused QKV projections, both streams in one launch ---
    {
        GemmJob j0 = { Hv + OP_PG, Lv + OP_PG, Hv + OP_WQ0, Lv + OP_WQ0,
                       DPG / 2, BB * L1C, 0, 0, L1C, LT, 0,
                       MQ, MQ + MKV, Qd, Kd, Vd, MQ, MKV, MKV, 32, 32 };
        GemmJob j1 = { Hv + OP_EX, Lv + OP_EX, Hv + OP_WQ1, Lv + OP_WQ1,
                       DEX / 2, BB * L2C, 0, 0, L2C, LT, L1C,
                       MQ, MQ + MKV, Qd, Kd, Vd, MQ, MKV, MKV, 32, 16 };
        gemm_b3<<<dim3(32, 32, 2), 256, GSM_BYTES>>>(j0, j1);
    }

    // --- RoPE + split/pack; V transpose/pack ---
    rope_pack<<<dim3(NH, LT, BB), 64>>>(Qd, cs, sn, NH, QK_SCALE, Qhp, Qlp);
    rope_pack<<<dim3(NKV, LT, BB), 64>>>(Kd, cs, sn, NKV, 1.0f, Khp, Klp);
    vt_pack<<<dim3(LT / 64, DHD / 64, BB * NKV), 256>>>();

    // --- attention (512 threads) ---
    attn_mma<<<dim3(LT / 64, NH, BB), 512, SMEM_ATTN>>>(mask);

    // --- output projections, both streams in one launch ---
    {
        float* out1 = out + (size_t)BB * L1C * DPG;
        GemmJob j0 = { Ahd, Ald, Hv + OP_WO0, Lv + OP_WO0,
                       MQ / 2, L1C, LT, 0, BB * L1C, 0, 0,
                       DPG, DPG, out, out, out, DPG, DPG, DPG, 18, 32 };
        GemmJob j1 = { Ahd, Ald, Hv + OP_WO1, Lv + OP_WO1,
                       MQ / 2, L2C, LT, L1C, BB * L2C, 0, 0,
                       DEX, DEX, out1, out1, out1, DEX, DEX, DEX, 8, 16 };
        gemm_b3<<<dim3(18, 32, 2), 256, GSM_BYTES>>>(j0, j1);
    }
}

// round 11
// speedup vs baseline: 2.4713x; 1.0154x over previous
#include <cuda_runtime.h>
#include <cuda_bf16.h>
#include <math.h>
#include <stdint.h>

#define BB   4
#define L1C  1024
#define L2C  512
#define LT   1536
#define DPG  2304
#define DEX  1024
#define NH   8
#define NKV  4
#define DHD  256
#define QK_SCALE 0.0625f

#define PERM8(j) ((((j) & 3) << 1) | ((j) >> 2))

// ---------------- scratch (device globals) -----------------------------------
__device__ float g_Q[(size_t)BB * LT * NH * DHD];
__device__ float g_K[(size_t)BB * LT * NKV * DHD];
__device__ float g_V[(size_t)BB * LT * NKV * DHD];

__device__ uint32_t g_Qh[(size_t)BB * LT * NH * 128];
__device__ uint32_t g_Ql[(size_t)BB * LT * NH * 128];
__device__ uint32_t g_Kh[(size_t)BB * LT * NKV * 128];
__device__ uint32_t g_Kl[(size_t)BB * LT * NKV * 128];

__device__ uint32_t g_VTh[(size_t)BB * NKV * DHD * (LT / 2)];
__device__ uint32_t g_VTl[(size_t)BB * NKV * DHD * (LT / 2)];

__device__ uint32_t g_ahi[(size_t)BB * LT * NH * 128];
__device__ uint32_t g_alo[(size_t)BB * LT * NH * 128];

#define OP_PG   0u
#define OP_EX   4718592u
#define OP_WQ0  5767168u
#define OP_WK0  8126464u
#define OP_WV0  9306112u
#define OP_WO0  10485760u
#define OP_WQ1  12845056u
#define OP_WK1  13893632u
#define OP_WV1  14417920u
#define OP_WO1  14942208u
#define OP_TOT  15990784u
__device__ uint32_t g_hi[OP_TOT];
__device__ uint32_t g_lo[OP_TOT];

// ---------------- helpers ----------------------------------------------------
__device__ __forceinline__ uint32_t pack_bf(float a, float b)
{
    __nv_bfloat162 t = __floats2bfloat162_rn(a, b);
    return *(uint32_t*)&t;
}
__device__ __forceinline__ void cpa16(uint32_t dst, const void* src)
{
    asm volatile("cp.async.cg.shared.global [%0], [%1], 16;" :: "r"(dst), "l"(src));
}

#define MMA_BF16(d, a, b)                                                     \
    asm volatile("mma.sync.aligned.m16n8k16.row.col.f32.bf16.bf16.f32 "       \
                 "{%0,%1,%2,%3}, {%4,%5,%6,%7}, {%8,%9}, {%0,%1,%2,%3};"      \
                 : "+f"(d[0]), "+f"(d[1]), "+f"(d[2]), "+f"(d[3])             \
                 : "r"(a[0]), "r"(a[1]), "r"(a[2]), "r"(a[3]),                \
                   "r"(b[0]), "r"(b[1]))

// ---------------- fused bf16-split conversion --------------------------------
struct CvtArgs {
    const float* src[10];
    uint32_t off[10];
    int n16[10];
};

__global__ void cvt_bsplit(CvtArgs a)
{
    const int e = blockIdx.y;
    const int i = blockIdx.x * blockDim.x + threadIdx.x;
    if (i >= a.n16[e]) return;
    const float4* s = (const float4*)(a.src[e]) + (size_t)i * 4;
    uint32_t* hb = g_hi + a.off[e] + (size_t)i * 8;
    uint32_t* lb = g_lo + a.off[e] + (size_t)i * 8;
    float v[16];
#pragma unroll
    for (int q = 0; q < 4; q++) {
        float4 f = s[q];
        v[q * 4 + 0] = f.x; v[q * 4 + 1] = f.y; v[q * 4 + 2] = f.z; v[q * 4 + 3] = f.w;
    }
#pragma unroll
    for (int j = 0; j < 8; j++) {
        const float x0 = v[2 * j], x1 = v[2 * j + 1];
        const float h0 = __bfloat162float(__float2bfloat16_rn(x0));
        const float h1 = __bfloat162float(__float2bfloat16_rn(x1));
        const int p = PERM8(j);
        hb[p] = pack_bf(h0, h1);
        lb[p] = pack_bf(x0 - h0, x1 - h1);
    }
}

// ---------------- bf16x3 NT GEMM, dual-job, single-barrier pipeline ----------
#define CH 16
#define PLN (128 * CH)
#define STG (4 * PLN)
#define GSM_BYTES (3 * STG * 4)

struct GemmJob {
    const uint32_t *Ah, *Al, *Wh, *Wl;
    int K2;
    int a_rpb, a_bs, a_off;
    int c_rpb, c_bs, c_off;
    int n1, n2;
    float *C0, *C1, *C2;
    int ldc0, ldc1, ldc2;
    int gx, gy;
};

__global__ __launch_bounds__(256, 2) void gemm_b3(GemmJob j0, GemmJob j1)
{
    const GemmJob J = blockIdx.z ? j1 : j0;
    if ((int)blockIdx.x >= J.gx || (int)blockIdx.y >= J.gy) return;

    extern __shared__ uint32_t smg[];
    const int tid = threadIdx.x;
    const int wid = tid >> 5, lane = tid & 31;
    const int warp_m = wid >> 1, warp_n = wid & 1;
    const int bm = blockIdx.y * 128, bn = blockIdx.x * 128;
    const int K2 = J.K2;

    const int p  = tid >> 6;
    const int rr = tid & 63;
    const int r0 = rr * 2, r1 = rr * 2 + 1;
    int gr0, gr1;
    if (p < 2) {
        const int m0 = bm + r0, m1 = bm + r1;
        gr0 = (m0 / J.a_rpb) * J.a_bs + J.a_off + (m0 % J.a_rpb);
        gr1 = (m1 / J.a_rpb) * J.a_bs + J.a_off + (m1 % J.a_rpb);
    } else {
        gr0 = bn + r0; gr1 = bn + r1;
    }
    const uint32_t* pb = (p == 0) ? J.Ah : (p == 1) ? J.Al : (p == 2) ? J.Wh : J.Wl;
    const uint32_t* s0 = pb + (size_t)gr0 * K2;
    const uint32_t* s1 = pb + (size_t)gr1 * K2;

    const uint32_t sbase = (uint32_t)__cvta_generic_to_shared(smg);
    const int sw0 = (r0 & 2) << 1, sw1 = (r1 & 2) << 1;
    uint32_t d0[4], d1[4];
#pragma unroll
    for (int j = 0; j < 4; j++) {
        d0[j] = sbase + (p * PLN + r0 * CH) * 4 + (((2 * j) ^ sw0) * 2) * 4;
        d1[j] = sbase + (p * PLN + r1 * CH) * 4 + (((2 * j) ^ sw1) * 2) * 4;
    }

    float acc[2][8][4];
#pragma unroll
    for (int i = 0; i < 2; i++)
#pragma unroll
        for (int j = 0; j < 8; j++)
#pragma unroll
            for (int r = 0; r < 4; r++) acc[i][j][r] = 0.f;

    const int nk = K2 >> 4;

#define G_ISSUE(kc)                                                           \
    do {                                                                      \
        const int _ko = (kc) * CH;                                            \
        const uint32_t _sb = ((kc) % 3) * STG * 4;                            \
        _Pragma("unroll")                                                     \
        for (int j = 0; j < 4; j++) {                                         \
            cpa16(d0[j] + _sb, s0 + _ko + j * 4);                             \
            cpa16(d1[j] + _sb, s1 + _ko + j * 4);                             \
        }                                                                     \
        asm volatile("cp.async.commit_group;");                               \
    } while (0)

    G_ISSUE(0);
    G_ISSUE(1);

    const int lr = lane >> 2, lc = lane & 3;
    const int fsw = (lr & 2) << 1;

    for (int kc = 0; kc < nk; kc++) {
        if (kc + 2 < nk) { asm volatile("cp.async.wait_group 1;"); }
        else             { asm volatile("cp.async.wait_group 0;"); }
        __syncthreads();          // stage kc visible; slot (kc+2)%3 fully read
        if (kc + 2 < nk) G_ISSUE(kc + 2);

        const uint32_t* st = smg + (kc % 3) * STG;
        const uint32_t* ah_p = st + 0 * PLN + (warp_m * 32 + lr) * CH;
        const uint32_t* al_p = st + 1 * PLN + (warp_m * 32 + lr) * CH;
        const uint32_t* wh_p = st + 2 * PLN + (warp_n * 64 + lr) * CH;
        const uint32_t* wl_p = st + 3 * PLN + (warp_n * 64 + lr) * CH;

#pragma unroll
        for (int g = 0; g < 2; g++) {
            const int q2 = ((g * 4 + lc) ^ fsw) * 2;
            uint32_t ah[2][4], bh[8][2];
            uint2 t;
            // hi fragments first
#pragma unroll
            for (int mf = 0; mf < 2; mf++) {
                t = *(const uint2*)(ah_p + mf * 16 * CH + q2);            ah[mf][0] = t.x; ah[mf][2] = t.y;
                t = *(const uint2*)(ah_p + mf * 16 * CH + 8 * CH + q2);   ah[mf][1] = t.x; ah[mf][3] = t.y;
            }
#pragma unroll
            for (int nf = 0; nf < 8; nf++) {
                t = *(const uint2*)(wh_p + nf * 8 * CH + q2);  bh[nf][0] = t.x; bh[nf][1] = t.y;
            }
            // hi*hi MMAs start early
#pragma unroll
            for (int nf = 0; nf < 8; nf++)
#pragma unroll
                for (int mf = 0; mf < 2; mf++)
                    MMA_BF16(acc[mf][nf], ah[mf], bh[nf]);
            // lo loads overlap remaining MMAs
            uint32_t al[2][4];
#pragma unroll
            for (int mf = 0; mf < 2; mf++) {
                t = *(const uint2*)(al_p + mf * 16 * CH + q2);            al[mf][0] = t.x; al[mf][2] = t.y;
                t = *(const uint2*)(al_p + mf * 16 * CH + 8 * CH + q2);   al[mf][1] = t.x; al[mf][3] = t.y;
            }
#pragma unroll
            for (int nf = 0; nf < 8; nf++) {
                uint32_t bl[2];
                t = *(const uint2*)(wl_p + nf * 8 * CH + q2);  bl[0] = t.x; bl[1] = t.y;
#pragma unroll
                for (int mf = 0; mf < 2; mf++) {
                    MMA_BF16(acc[mf][nf], al[mf], bh[nf]);
                    MMA_BF16(acc[mf][nf], ah[mf], bl);
                }
            }
        }
        // no trailing barrier: next iteration's top barrier provides ordering
    }
#undef G_ISSUE

    float* Cb; int ldc, coff;
    if (bn < J.n1)      { Cb = J.C0; ldc = J.ldc0; coff = 0;    }
    else if (bn < J.n2) { Cb = J.C1; ldc = J.ldc1; coff = J.n1; }
    else                { Cb = J.C2; ldc = J.ldc2; coff = J.n2; }

#pragma unroll
    for (int mf = 0; mf < 2; mf++) {
        const int m0 = bm + warp_m * 32 + mf * 16 + lr;
        const int m1 = m0 + 8;
        const int cr0 = (m0 / J.c_rpb) * J.c_bs + J.c_off + (m0 % J.c_rpb);
        const int cr1 = (m1 / J.c_rpb) * J.c_bs + J.c_off + (m1 % J.c_rpb);
#pragma unroll
        for (int nf = 0; nf < 8; nf++) {
            const int col = bn - coff + warp_n * 64 + nf * 8 + lc * 2;
            *(float2*)&Cb[(size_t)cr0 * ldc + col] = make_float2(acc[mf][nf][0], acc[mf][nf][1]);
            *(float2*)&Cb[(size_t)cr1 * ldc + col] = make_float2(acc[mf][nf][2], acc[mf][nf][3]);
        }
    }
}

// ---------------- RoPE + bf16 split + pack (Q and K in one launch) -----------
__global__ void rope_pack2(const float* __restrict__ Xq, const float* __restrict__ Xk,
                           const float* __restrict__ cs, const float* __restrict__ sn,
                           uint32_t* __restrict__ qh_, uint32_t* __restrict__ ql_,
                           uint32_t* __restrict__ kh_, uint32_t* __restrict__ kl_)
{
    const int hh = blockIdx.x;           // 0..NH+NKV-1
    const int l = blockIdx.y;
    const int b = blockIdx.z;
    const int j = threadIdx.x;           // 0..63
    const int isQ = hh < NH;
    const int h = isQ ? hh : hh - NH;
    const int nheads = isQ ? NH : NKV;
    const float scale = isQ ? QK_SCALE : 1.0f;
    const float* X = isQ ? Xq : Xk;
    uint32_t* oh = isQ ? qh_ : kh_;
    uint32_t* ol = isQ ? ql_ : kl_;

    const size_t row = (size_t)b * LT + l;
    const float2 c2 = *(const float2*)&cs[row * 128 + 2 * j];
    const float2 s2 = *(const float2*)&sn[row * 128 + 2 * j];
    const size_t base = (row * nheads + h) * DHD;
    const float2 xa = *(const float2*)&X[base + 2 * j];
    const float2 xb = *(const float2*)&X[base + 128 + 2 * j];
    const float y1a = (xa.x * c2.x - xb.x * s2.x) * scale;
    const float y1b = (xa.y * c2.y - xb.y * s2.y) * scale;
    const float y2a = (xb.x * c2.x + xa.x * s2.x) * scale;
    const float y2b = (xb.y * c2.y + xa.y * s2.y) * scale;

    const size_t ob = (row * nheads + h) * 128;
    const int p1 = (j & ~7) | PERM8(j & 7);
    const int p2 = 64 + p1;
    const float h1a = __bfloat162float(__float2bfloat16_rn(y1a));
    const float h1b = __bfloat162float(__float2bfloat16_rn(y1b));
    const float h2a = __bfloat162float(__float2bfloat16_rn(y2a));
    const float h2b = __bfloat162float(__float2bfloat16_rn(y2b));
    oh[ob + p1] = pack_bf(h1a, h1b);
    ol[ob + p1] = pack_bf(y1a - h1a, y1b - h1b);
    oh[ob + p2] = pack_bf(h2a, h2b);
    ol[ob + p2] = pack_bf(y2a - h2a, y2b - h2b);
}

// ---------------- V transpose + bf16 split -----------------------------------
__global__ __launch_bounds__(256) void vt_pack()
{
    __shared__ float t[64][65];
    const int b   = blockIdx.z >> 2;
    const int hkv = blockIdx.z & 3;
    const int l0 = blockIdx.x * 64;
    const int d0 = blockIdx.y * 64;
    const int tid = threadIdx.x;

    for (int i = tid; i < 64 * 64; i += 256) {
        const int lrow = i >> 6, dcol = i & 63;
        t[lrow][dcol] = g_V[(((size_t)b * LT + l0 + lrow) * NKV + hkv) * DHD + d0 + dcol];
    }
    __syncthreads();

    const int drow = tid & 63;
    const int mg = tid >> 6;
    const size_t obase = (((size_t)b * NKV + hkv) * DHD + d0 + drow) * (LT / 2) + l0 / 2;
#pragma unroll
    for (int m = 0; m < 8; m++) {
        const int lp = mg * 8 + m;
        const float v0 = t[2 * lp][drow];
        const float v1 = t[2 * lp + 1][drow];
        const float h0 = __bfloat162float(__float2bfloat16_rn(v0));
        const float h1 = __bfloat162float(__float2bfloat16_rn(v1));
        const int pos = mg * 8 + PERM8(m);
        g_VTh[obase + pos] = pack_bf(h0, h1);
        g_VTl[obase + pos] = pack_bf(v0 - h0, v1 - h1);
    }
}

// ---------------- bf16x3 flash attention, 512 threads ------------------------
#define AQH 0
#define AQL 8192
#define AKH 16384
#define AKL 24576
#define AVH 32768
#define AVL 40960
#define ASF 49152
#define APH 53504
#define APL 55552
#define AAS 57600
#define ALS 57664
#define SMEM_ATTN (57728 * 4)

__global__ __launch_bounds__(512, 1) void attn_mma(const float* __restrict__ mask)
{
    extern __shared__ uint32_t su[];
    float* S   = (float*)(su + ASF);
    float* Asc = (float*)(su + AAS);
    float* Lsc = (float*)(su + ALS);

    const int tid = threadIdx.x;
    const int qt = blockIdx.x;
    const int h  = blockIdx.y;
    const int b  = blockIdx.z;
    const int hkv = h >> 1;
    const int wid = tid >> 5, lane = tid & 31;
    const int wm = wid & 3, wn = wid >> 2;
    const int lr = lane >> 2, lc = lane & 3;
    const int srow = tid >> 3, part = tid & 7;

    const uint32_t sb = (uint32_t)__cvta_generic_to_shared(su);

    {
        const uint32_t* qsrc[2] = { g_Qh, g_Ql };
        const uint32_t* ksrc[2] = { g_Kh, g_Kl };
#pragma unroll
        for (int pl = 0; pl < 2; pl++) {
            for (int i = tid; i < 2048; i += 512) {
                const int row = i >> 5, ch = i & 31;
                const uint32_t dst = sb + ((pl ? AQL : AQH) + row * 128 +
                                           (((2 * ch) ^ ((row & 3) << 2)) * 2)) * 4;
                cpa16(dst, qsrc[pl] + (((size_t)b * LT + qt * 64 + row) * NH + h) * 128 + ch * 4);
            }
            for (int i = tid; i < 2048; i += 512) {
                const int row = i >> 5, ch = i & 31;
                const uint32_t dst = sb + ((pl ? AKL : AKH) + row * 128 +
                                           (((2 * ch) ^ ((row & 3) << 2)) * 2)) * 4;
                cpa16(dst, ksrc[pl] + (((size_t)b * LT + row) * NKV + hkv) * 128 + ch * 4);
            }
        }
        asm volatile("cp.async.commit_group;");
        const uint32_t* vsrc[2] = { g_VTh, g_VTl };
#pragma unroll
        for (int pl = 0; pl < 2; pl++)
            for (int i = tid; i < 2048; i += 512) {
                const int row = i >> 3, ch = i & 7;
                const uint32_t dst = sb + ((pl ? AVL : AVH) + row * 32 +
                                           (((2 * ch) ^ ((row & 3) << 2)) * 2)) * 4;
                cpa16(dst, vsrc[pl] + (((size_t)b * NKV + hkv) * DHD + row) * (LT / 2) + ch * 4);
            }
        asm volatile("cp.async.commit_group;");
    }

    float accO[8][4];
#pragma unroll
    for (int i = 0; i < 8; i++)
#pragma unroll
        for (int j = 0; j < 4; j++) accO[i][j] = 0.f;
    float m_run = -1e30f, l_run = 0.f;

    const int fsw = (lr & 3) << 2;

    for (int kt = 0; kt < LT / 64; kt++) {
        asm volatile("cp.async.wait_group 1;");
        __syncthreads();

        float accS[2][4];
#pragma unroll
        for (int i = 0; i < 2; i++)
#pragma unroll
            for (int j = 0; j < 4; j++) accS[i][j] = 0.f;
        {
            const uint32_t* qh = su + AQH + (wm * 16 + lr) * 128;
            const uint32_t* ql = su + AQL + (wm * 16 + lr) * 128;
            const uint32_t* kh = su + AKH + (wn * 16 + lr) * 128;
            const uint32_t* kl = su + AKL + (wn * 16 + lr) * 128;
#pragma unroll 4
            for (int g = 0; g < 16; g++) {
                const int q2 = ((g * 4 + lc) ^ fsw) * 2;
                uint32_t ah[4], bh[2][2];
                uint2 t;
                t = *(const uint2*)(qh + q2);             ah[0] = t.x; ah[2] = t.y;
                t = *(const uint2*)(qh + 8 * 128 + q2);   ah[1] = t.x; ah[3] = t.y;
#pragma unroll
                for (int nf = 0; nf < 2; nf++) {
                    t = *(const uint2*)(kh + nf * 8 * 128 + q2);  bh[nf][0] = t.x; bh[nf][1] = t.y;
                }
#pragma unroll
                for (int nf = 0; nf < 2; nf++) MMA_BF16(accS[nf], ah, bh[nf]);
                uint32_t al[4];
                t = *(const uint2*)(ql + q2);             al[0] = t.x; al[2] = t.y;
                t = *(const uint2*)(ql + 8 * 128 + q2);   al[1] = t.x; al[3] = t.y;
#pragma unroll
                for (int nf = 0; nf < 2; nf++) {
                    uint32_t bl[2];
                    t = *(const uint2*)(kl + nf * 8 * 128 + q2);  bl[0] = t.x; bl[1] = t.y;
                    MMA_BF16(accS[nf], al, bh[nf]);
                    MMA_BF16(accS[nf], ah, bl);
                }
            }
        }
        {
            const size_t mrow0 = ((size_t)b * LT + qt * 64 + wm * 16 + lr) * LT + kt * 64 + wn * 16;
            const size_t mrow1 = mrow0 + (size_t)8 * LT;
#pragma unroll
            for (int nf = 0; nf < 2; nf++) {
                const int col = nf * 8 + lc * 2;
                const float2 m0 = *(const float2*)&mask[mrow0 + col];
                const float2 m1 = *(const float2*)&mask[mrow1 + col];
                *(float2*)&S[(wm * 16 + lr) * 68 + wn * 16 + col] =
                    make_float2(accS[nf][0] + m0.x, accS[nf][1] + m0.y);
                *(float2*)&S[(wm * 16 + lr + 8) * 68 + wn * 16 + col] =
                    make_float2(accS[nf][2] + m1.x, accS[nf][3] + m1.y);
            }
        }
        __syncthreads();

        if (kt + 1 < LT / 64) {
            const uint32_t* ksrc[2] = { g_Kh, g_Kl };
#pragma unroll
            for (int pl = 0; pl < 2; pl++)
                for (int i = tid; i < 2048; i += 512) {
                    const int row = i >> 5, ch = i & 31;
                    const uint32_t dst = sb + ((pl ? AKL : AKH) + row * 128 +
                                               (((2 * ch) ^ ((row & 3) << 2)) * 2)) * 4;
                    cpa16(dst, ksrc[pl] + (((size_t)b * LT + (kt + 1) * 64 + row) * NKV + hkv) * 128 + ch * 4);
                }
            asm volatile("cp.async.commit_group;");
        }

        {
            float* sp = S + srow * 68 + part * 8;
            float pv[8];
            float lm = -1e30f;
#pragma unroll
            for (int j = 0; j < 8; j++) { pv[j] = sp[j]; lm = fmaxf(lm, pv[j]); }
            lm = fmaxf(lm, __shfl_xor_sync(0xffffffffu, lm, 1));
            lm = fmaxf(lm, __shfl_xor_sync(0xffffffffu, lm, 2));
            lm = fmaxf(lm, __shfl_xor_sync(0xffffffffu, lm, 4));
            const float mnew = fmaxf(m_run, lm);
            const float alpha = __expf(m_run - mnew);
            float ls = 0.f;
#pragma unroll
            for (int j = 0; j < 8; j++) { pv[j] = __expf(pv[j] - mnew); ls += pv[j]; }
            ls += __shfl_xor_sync(0xffffffffu, ls, 1);
            ls += __shfl_xor_sync(0xffffffffu, ls, 2);
            ls += __shfl_xor_sync(0xffffffffu, ls, 4);
            l_run = l_run * alpha + ls;
            m_run = mnew;
            if (part == 0) Asc[srow] = alpha;

            const int swz = (srow & 3) << 2;
#pragma unroll
            for (int m = 0; m < 4; m++) {
                const float p0 = pv[2 * m], p1 = pv[2 * m + 1];
                const float h0 = __bfloat162float(__float2bfloat16_rn(p0));
                const float h1 = __bfloat162float(__float2bfloat16_rn(p1));
                const int pp = part * 4 + m;
                const int u = (pp & ~7) | PERM8(pp & 7);
                const int pos = srow * 32 + (((u >> 1) ^ swz) * 2) + (u & 1);
                su[APH + pos] = pack_bf(h0, h1);
                su[APL + pos] = pack_bf(p0 - h0, p1 - h1);
            }
        }
        if (kt + 1 < LT / 64) { asm volatile("cp.async.wait_group 1;"); }
        else                  { asm volatile("cp.async.wait_group 0;"); }
        __syncthreads();

        {
            const float a0 = Asc[wm * 16 + lr];
            const float a1 = Asc[wm * 16 + lr + 8];
#pragma unroll
            for (int nf = 0; nf < 8; nf++) {
                accO[nf][0] *= a0; accO[nf][1] *= a0;
                accO[nf][2] *= a1; accO[nf][3] *= a1;
            }
            const uint32_t* php = su + APH + (wm * 16 + lr) * 32;
            const uint32_t* plp = su + APL + (wm * 16 + lr) * 32;
            const uint32_t* vhp = su + AVH + (wn * 64 + lr) * 32;
            const uint32_t* vlp = su + AVL + (wn * 64 + lr) * 32;
#pragma unroll
            for (int g = 0; g < 4; g++) {
                const int q2 = ((g * 4 + lc) ^ fsw) * 2;
                uint32_t ph[4], vh[8][2];
                uint2 t;
                t = *(const uint2*)(php + q2);            ph[0] = t.x; ph[2] = t.y;
                t = *(const uint2*)(php + 8 * 32 + q2);   ph[1] = t.x; ph[3] = t.y;
#pragma unroll
                for (int nf = 0; nf < 8; nf++) {
                    t = *(const uint2*)(vhp + nf * 8 * 32 + q2);  vh[nf][0] = t.x; vh[nf][1] = t.y;
                }
#pragma unroll
                for (int nf = 0; nf < 8; nf++) MMA_BF16(accO[nf], ph, vh[nf]);
                uint32_t pl[4];
                t = *(const uint2*)(plp + q2);            pl[0] = t.x; pl[2] = t.y;
                t = *(const uint2*)(plp + 8 * 32 + q2);   pl[1] = t.x; pl[3] = t.y;
#pragma unroll
                for (int nf = 0; nf < 8; nf++) {
                    uint32_t vl[2];
                    t = *(const uint2*)(vlp + nf * 8 * 32 + q2);  vl[0] = t.x; vl[1] = t.y;
                    MMA_BF16(accO[nf], pl, vh[nf]);
                    MMA_BF16(accO[nf], ph, vl);
                }
            }
        }
        __syncthreads();

        if (kt + 1 < LT / 64) {
            const uint32_t* vsrc[2] = { g_VTh, g_VTl };
#pragma unroll
            for (int pl = 0; pl < 2; pl++)
                for (int i = tid; i < 2048; i += 512) {
                    const int row = i >> 3, ch = i & 7;
                    const uint32_t dst = sb + ((pl ? AVL : AVH) + row * 32 +
                                               (((2 * ch) ^ ((row & 3) << 2)) * 2)) * 4;
                    cpa16(dst, vsrc[pl] + (((size_t)b * NKV + hkv) * DHD + row) * (LT / 2) +
                               (kt + 1) * 32 + ch * 4);
                }
            asm volatile("cp.async.commit_group;");
        }
    }

    if (part == 0) Lsc[srow] = l_run;
    __syncthreads();

    {
        const float il0 = 1.f / Lsc[wm * 16 + lr];
        const float il1 = 1.f / Lsc[wm * 16 + lr + 8];
        const size_t r0 = (size_t)b * LT + qt * 64 + wm * 16 + lr;
        const size_t r1 = r0 + 8;
#pragma unroll
        for (int nf = 0; nf < 8; nf++) {
            const int p = h * 128 + wn * 32 + nf * 4 + lc;
            const int pos = (p & ~7) | PERM8(p & 7);
            const float v0 = accO[nf][0] * il0, v1 = accO[nf][1] * il0;
            const float v2 = accO[nf][2] * il1, v3 = accO[nf][3] * il1;
            const float h0 = __bfloat162float(__float2bfloat16_rn(v0));
            const float h1 = __bfloat162float(__float2bfloat16_rn(v1));
            const float h2 = __bfloat162float(__float2bfloat16_rn(v2));
            const float h3 = __bfloat162float(__float2bfloat16_rn(v3));
            g_ahi[r0 * 1024 + pos] = pack_bf(h0, h1);
            g_alo[r0 * 1024 + pos] = pack_bf(v0 - h0, v1 - h1);
            g_ahi[r1 * 1024 + pos] = pack_bf(h2, h3);
            g_alo[r1 * 1024 + pos] = pack_bf(v2 - h2, v3 - h3);
        }
    }
}

// ---------------- launch ----------------------------------------------------
extern "C" void kernel_launch(void* const* d_in, const int* in_sizes, int n_in,
                              void* d_out, int out_size)
{
    const float* pg   = (const float*)d_in[0];
    const float* ex   = (const float*)d_in[1];
    const float* cs   = (const float*)d_in[2];
    const float* sn   = (const float*)d_in[3];
    const float* mask = (const float*)d_in[4];
    const float* Wq0  = (const float*)d_in[5];
    const float* Wk0  = (const float*)d_in[6];
    const float* Wv0  = (const float*)d_in[7];
    const float* Wo0  = (const float*)d_in[8];
    const float* Wq1  = (const float*)d_in[9];
    const float* Wk1  = (const float*)d_in[10];
    const float* Wv1  = (const float*)d_in[11];
    const float* Wo1  = (const float*)d_in[12];
    float* out = (float*)d_out;

    float *Qd, *Kd, *Vd;
    uint32_t *Ahd, *Ald, *Hv, *Lv, *Qhp, *Qlp, *Khp, *Klp;
    cudaGetSymbolAddress((void**)&Qd, g_Q);
    cudaGetSymbolAddress((void**)&Kd, g_K);
    cudaGetSymbolAddress((void**)&Vd, g_V);
    cudaGetSymbolAddress((void**)&Ahd, g_ahi);
    cudaGetSymbolAddress((void**)&Ald, g_alo);
    cudaGetSymbolAddress((void**)&Hv, g_hi);
    cudaGetSymbolAddress((void**)&Lv, g_lo);
    cudaGetSymbolAddress((void**)&Qhp, g_Qh);
    cudaGetSymbolAddress((void**)&Qlp, g_Ql);
    cudaGetSymbolAddress((void**)&Khp, g_Kh);
    cudaGetSymbolAddress((void**)&Klp, g_Kl);

    cudaFuncSetAttribute(gemm_b3, cudaFuncAttributeMaxDynamicSharedMemorySize, GSM_BYTES);
    cudaFuncSetAttribute(attn_mma, cudaFuncAttributeMaxDynamicSharedMemorySize, SMEM_ATTN);

    const int MQ = NH * DHD;    // 2048
    const int MKV = NKV * DHD;  // 1024

    // --- split projection operands ---
    CvtArgs ca;
    const float* srcs[10] = { pg, ex, Wq0, Wk0, Wv0, Wo0, Wq1, Wk1, Wv1, Wo1 };
    const uint32_t offs[10] = { OP_PG, OP_EX, OP_WQ0, OP_WK0, OP_WV0,
                                OP_WO0, OP_WQ1, OP_WK1, OP_WV1, OP_WO1 };
    const int ns[10] = { BB * L1C * DPG, BB * L2C * DEX, MQ * DPG, MKV * DPG,
                         MKV * DPG, DPG * MQ, MQ * DEX, MKV * DEX, MKV * DEX, DEX * MQ };
    int maxg = 0;
    for (int i = 0; i < 10; i++) {
        ca.src[i] = srcs[i]; ca.off[i] = offs[i]; ca.n16[i] = ns[i] / 16;
        if (ca.n16[i] > maxg) maxg = ca.n16[i];
    }
    cvt_bsplit<<<dim3((maxg + 255) / 256, 10), 256>>>(ca);

    // --- fused QKV projections, both streams in one launch ---
    {
        GemmJob j0 = { Hv + OP_PG, Lv + OP_PG, Hv + OP_WQ0, Lv + OP_WQ0,
                       DPG / 2, BB * L1C, 0, 0, L1C, LT, 0,
                       MQ, MQ + MKV, Qd, Kd, Vd, MQ, MKV, MKV, 32, 32 };
        GemmJob j1 = { Hv + OP_EX, Lv + OP_EX, Hv + OP_WQ1, Lv + OP_WQ1,
                       DEX / 2, BB * L2C, 0, 0, L2C, LT, L1C,
                       MQ, MQ + MKV, Qd, Kd, Vd, MQ, MKV, MKV, 32, 16 };
        gemm_b3<<<dim3(32, 32, 2), 256, GSM_BYTES>>>(j0, j1);
    }

    // --- RoPE (Q+K fused) + pack; V transpose/pack ---
    rope_pack2<<<dim3(NH + NKV, LT, BB), 64>>>(Qd, Kd, cs, sn, Qhp, Qlp, Khp, Klp);
    vt_pack<<<dim3(LT / 64, DHD / 64, BB * NKV), 256>>>();

    // --- attention (512 threads) ---
    attn_mma<<<dim3(LT / 64, NH, BB), 512, SMEM_ATTN>>>(mask);

    // --- output projections, both streams in one launch ---
    {
        float* out1 = out + (size_t)BB * L1C * DPG;
        GemmJob j0 = { Ahd, Ald, Hv + OP_WO0, Lv + OP_WO0,
                       MQ / 2, L1C, LT, 0, BB * L1C, 0, 0,
                       DPG, DPG, out, out, out, DPG, DPG, DPG, 18, 32 };
        GemmJob j1 = { Ahd, Ald, Hv + OP_WO1, Lv + OP_WO1,
                       MQ / 2, L2C, LT, L1C, BB * L2C, 0, 0,
                       DEX, DEX, out1, out1, out1, DEX, DEX, DEX, 8, 16 };
        gemm_b3<<<dim3(18, 32, 2), 256, GSM_BYTES>>>(j0, j1);
    }
}

// round 12
// speedup vs baseline: 2.4902x; 1.0076x over previous
#include <cuda_runtime.h>
#include <cuda_bf16.h>
#include <math.h>
#include <stdint.h>

#define BB   4
#define L1C  1024
#define L2C  512
#define LT   1536
#define DPG  2304
#define DEX  1024
#define NH   8
#define NKV  4
#define DHD  256
#define QK_SCALE 0.0625f

#define PERM8(j) ((((j) & 3) << 1) | ((j) >> 2))

// ---------------- scratch (device globals) -----------------------------------
__device__ float g_Q[(size_t)BB * LT * NH * DHD];
__device__ float g_K[(size_t)BB * LT * NKV * DHD];
__device__ float g_V[(size_t)BB * LT * NKV * DHD];

__device__ uint32_t g_Qh[(size_t)BB * LT * NH * 128];
__device__ uint32_t g_Ql[(size_t)BB * LT * NH * 128];
__device__ uint32_t g_Kh[(size_t)BB * LT * NKV * 128];
__device__ uint32_t g_Kl[(size_t)BB * LT * NKV * 128];

__device__ uint32_t g_VTh[(size_t)BB * NKV * DHD * (LT / 2)];
__device__ uint32_t g_VTl[(size_t)BB * NKV * DHD * (LT / 2)];

__device__ uint32_t g_ahi[(size_t)BB * LT * NH * 128];
__device__ uint32_t g_alo[(size_t)BB * LT * NH * 128];

#define OP_PG   0u
#define OP_EX   4718592u
#define OP_WQ0  5767168u
#define OP_WK0  8126464u
#define OP_WV0  9306112u
#define OP_WO0  10485760u
#define OP_WQ1  12845056u
#define OP_WK1  13893632u
#define OP_WV1  14417920u
#define OP_WO1  14942208u
#define OP_TOT  15990784u
__device__ uint32_t g_hi[OP_TOT];
__device__ uint32_t g_lo[OP_TOT];

// ---------------- helpers ----------------------------------------------------
__device__ __forceinline__ uint32_t pack_bf(float a, float b)
{
    __nv_bfloat162 t = __floats2bfloat162_rn(a, b);
    return *(uint32_t*)&t;
}
__device__ __forceinline__ void cpa16(uint32_t dst, const void* src)
{
    asm volatile("cp.async.cg.shared.global [%0], [%1], 16;" :: "r"(dst), "l"(src));
}

#define MMA_BF16(d, a, b)                                                     \
    asm volatile("mma.sync.aligned.m16n8k16.row.col.f32.bf16.bf16.f32 "       \
                 "{%0,%1,%2,%3}, {%4,%5,%6,%7}, {%8,%9}, {%0,%1,%2,%3};"      \
                 : "+f"(d[0]), "+f"(d[1]), "+f"(d[2]), "+f"(d[3])             \
                 : "r"(a[0]), "r"(a[1]), "r"(a[2]), "r"(a[3]),                \
                   "r"(b[0]), "r"(b[1]))

// ---------------- fused bf16-split conversion --------------------------------
struct CvtArgs {
    const float* src[10];
    uint32_t off[10];
    int n16[10];
};

__global__ void cvt_bsplit(CvtArgs a)
{
    const int e = blockIdx.y;
    const int i = blockIdx.x * blockDim.x + threadIdx.x;
    if (i >= a.n16[e]) return;
    const float4* s = (const float4*)(a.src[e]) + (size_t)i * 4;
    uint32_t* hb = g_hi + a.off[e] + (size_t)i * 8;
    uint32_t* lb = g_lo + a.off[e] + (size_t)i * 8;
    float v[16];
#pragma unroll
    for (int q = 0; q < 4; q++) {
        float4 f = s[q];
        v[q * 4 + 0] = f.x; v[q * 4 + 1] = f.y; v[q * 4 + 2] = f.z; v[q * 4 + 3] = f.w;
    }
#pragma unroll
    for (int j = 0; j < 8; j++) {
        const float x0 = v[2 * j], x1 = v[2 * j + 1];
        const float h0 = __bfloat162float(__float2bfloat16_rn(x0));
        const float h1 = __bfloat162float(__float2bfloat16_rn(x1));
        const int p = PERM8(j);
        hb[p] = pack_bf(h0, h1);
        lb[p] = pack_bf(x0 - h0, x1 - h1);
    }
}

// ---------------- bf16x3 NT GEMM: 4 warps, 64x64 warp tile -------------------
#define CH 16
#define PLN (128 * CH)
#define STG (4 * PLN)
#define GSM_BYTES (3 * STG * 4)

struct GemmJob {
    const uint32_t *Ah, *Al, *Wh, *Wl;
    int K2;
    int a_rpb, a_bs, a_off;
    int c_rpb, c_bs, c_off;
    int n1, n2;
    float *C0, *C1, *C2;
    int ldc0, ldc1, ldc2;
    int gx, gy;
};

__global__ __launch_bounds__(128, 2) void gemm_b3(GemmJob j0, GemmJob j1)
{
    const GemmJob J = blockIdx.z ? j1 : j0;
    if ((int)blockIdx.x >= J.gx || (int)blockIdx.y >= J.gy) return;

    extern __shared__ uint32_t smg[];
    const int tid = threadIdx.x;
    const int wid = tid >> 5, lane = tid & 31;
    const int warp_m = wid >> 1, warp_n = wid & 1;   // 2x2 warps, 64x64 each
    const int bm = blockIdx.y * 128, bn = blockIdx.x * 128;
    const int K2 = J.K2;

    // staging: plane p = tid>>5 (Ah,Al,Wh,Wl); thread covers rows tr*4..tr*4+3
    const int p  = tid >> 5;
    const int tr = tid & 31;
    const uint32_t* pb = (p == 0) ? J.Ah : (p == 1) ? J.Al : (p == 2) ? J.Wh : J.Wl;
    const uint32_t sbase = (uint32_t)__cvta_generic_to_shared(smg);
    const uint32_t* srow[4];
    uint32_t dbase[4];
    int rsw[4];
#pragma unroll
    for (int i = 0; i < 4; i++) {
        const int r = tr * 4 + i;
        int g;
        if (p < 2) {
            const int m = bm + r;
            g = (m / J.a_rpb) * J.a_bs + J.a_off + (m % J.a_rpb);
        } else g = bn + r;
        srow[i] = pb + (size_t)g * K2;
        dbase[i] = sbase + (p * PLN + r * CH) * 4;
        rsw[i]  = (r & 2) << 1;
    }

    float acc[4][8][4];
#pragma unroll
    for (int i = 0; i < 4; i++)
#pragma unroll
        for (int j = 0; j < 8; j++)
#pragma unroll
            for (int r = 0; r < 4; r++) acc[i][j][r] = 0.f;

    const int nk = K2 >> 4;

#define G_ISSUE(kc)                                                           \
    do {                                                                      \
        const int _ko = (kc) * CH;                                            \
        const uint32_t _sb = ((kc) % 3) * STG * 4;                            \
        _Pragma("unroll")                                                     \
        for (int i = 0; i < 4; i++) {                                         \
            _Pragma("unroll")                                                 \
            for (int j = 0; j < 4; j++)                                       \
                cpa16(dbase[i] + _sb + (((2 * j) ^ rsw[i]) * 2) * 4,          \
                      srow[i] + _ko + j * 4);                                 \
        }                                                                     \
        asm volatile("cp.async.commit_group;");                               \
    } while (0)

    G_ISSUE(0);
    G_ISSUE(1);

    const int lr = lane >> 2, lc = lane & 3;
    const int fsw = (lr & 2) << 1;

    for (int kc = 0; kc < nk; kc++) {
        if (kc + 2 < nk) { asm volatile("cp.async.wait_group 1;"); }
        else             { asm volatile("cp.async.wait_group 0;"); }
        __syncthreads();
        if (kc + 2 < nk) G_ISSUE(kc + 2);

        const uint32_t* st = smg + (kc % 3) * STG;
        const uint32_t* ah_p = st + 0 * PLN + (warp_m * 64 + lr) * CH;
        const uint32_t* al_p = st + 1 * PLN + (warp_m * 64 + lr) * CH;
        const uint32_t* wh_p = st + 2 * PLN + (warp_n * 64 + lr) * CH;
        const uint32_t* wl_p = st + 3 * PLN + (warp_n * 64 + lr) * CH;

#pragma unroll
        for (int g = 0; g < 2; g++) {
            const int q2 = ((g * 4 + lc) ^ fsw) * 2;
            uint32_t ah[4][4], bh[8][2];
            uint2 t;
#pragma unroll
            for (int mf = 0; mf < 4; mf++) {
                t = *(const uint2*)(ah_p + mf * 16 * CH + q2);            ah[mf][0] = t.x; ah[mf][2] = t.y;
                t = *(const uint2*)(ah_p + mf * 16 * CH + 8 * CH + q2);   ah[mf][1] = t.x; ah[mf][3] = t.y;
            }
#pragma unroll
            for (int nf = 0; nf < 8; nf++) {
                t = *(const uint2*)(wh_p + nf * 8 * CH + q2);  bh[nf][0] = t.x; bh[nf][1] = t.y;
            }
            // hi*hi
#pragma unroll
            for (int nf = 0; nf < 8; nf++)
#pragma unroll
                for (int mf = 0; mf < 4; mf++)
                    MMA_BF16(acc[mf][nf], ah[mf], bh[nf]);
            // lo planes overlap remaining MMAs
#pragma unroll
            for (int mf = 0; mf < 4; mf++) {
                uint32_t al[4];
                t = *(const uint2*)(al_p + mf * 16 * CH + q2);            al[0] = t.x; al[2] = t.y;
                t = *(const uint2*)(al_p + mf * 16 * CH + 8 * CH + q2);   al[1] = t.x; al[3] = t.y;
#pragma unroll
                for (int nf = 0; nf < 8; nf++)
                    MMA_BF16(acc[mf][nf], al, bh[nf]);
            }
#pragma unroll
            for (int nf = 0; nf < 8; nf++) {
                uint32_t bl[2];
                t = *(const uint2*)(wl_p + nf * 8 * CH + q2);  bl[0] = t.x; bl[1] = t.y;
#pragma unroll
                for (int mf = 0; mf < 4; mf++)
                    MMA_BF16(acc[mf][nf], ah[mf], bl);
            }
        }
    }
#undef G_ISSUE

    float* Cb; int ldc, coff;
    if (bn < J.n1)      { Cb = J.C0; ldc = J.ldc0; coff = 0;    }
    else if (bn < J.n2) { Cb = J.C1; ldc = J.ldc1; coff = J.n1; }
    else                { Cb = J.C2; ldc = J.ldc2; coff = J.n2; }

#pragma unroll
    for (int mf = 0; mf < 4; mf++) {
        const int m0 = bm + warp_m * 64 + mf * 16 + lr;
        const int m1 = m0 + 8;
        const int cr0 = (m0 / J.c_rpb) * J.c_bs + J.c_off + (m0 % J.c_rpb);
        const int cr1 = (m1 / J.c_rpb) * J.c_bs + J.c_off + (m1 % J.c_rpb);
#pragma unroll
        for (int nf = 0; nf < 8; nf++) {
            const int col = bn - coff + warp_n * 64 + nf * 8 + lc * 2;
            *(float2*)&Cb[(size_t)cr0 * ldc + col] = make_float2(acc[mf][nf][0], acc[mf][nf][1]);
            *(float2*)&Cb[(size_t)cr1 * ldc + col] = make_float2(acc[mf][nf][2], acc[mf][nf][3]);
        }
    }
}

// ---------------- RoPE + bf16 split + pack (Q and K fused) -------------------
__global__ void rope_pack2(const float* __restrict__ Xq, const float* __restrict__ Xk,
                           const float* __restrict__ cs, const float* __restrict__ sn,
                           uint32_t* __restrict__ qh_, uint32_t* __restrict__ ql_,
                           uint32_t* __restrict__ kh_, uint32_t* __restrict__ kl_)
{
    const int hh = blockIdx.x;
    const int l = blockIdx.y;
    const int b = blockIdx.z;
    const int j = threadIdx.x;
    const int isQ = hh < NH;
    const int h = isQ ? hh : hh - NH;
    const int nheads = isQ ? NH : NKV;
    const float scale = isQ ? QK_SCALE : 1.0f;
    const float* X = isQ ? Xq : Xk;
    uint32_t* oh = isQ ? qh_ : kh_;
    uint32_t* ol = isQ ? ql_ : kl_;

    const size_t row = (size_t)b * LT + l;
    const float2 c2 = *(const float2*)&cs[row * 128 + 2 * j];
    const float2 s2 = *(const float2*)&sn[row * 128 + 2 * j];
    const size_t base = (row * nheads + h) * DHD;
    const float2 xa = *(const float2*)&X[base + 2 * j];
    const float2 xb = *(const float2*)&X[base + 128 + 2 * j];
    const float y1a = (xa.x * c2.x - xb.x * s2.x) * scale;
    const float y1b = (xa.y * c2.y - xb.y * s2.y) * scale;
    const float y2a = (xb.x * c2.x + xa.x * s2.x) * scale;
    const float y2b = (xb.y * c2.y + xa.y * s2.y) * scale;

    const size_t ob = (row * nheads + h) * 128;
    const int p1 = (j & ~7) | PERM8(j & 7);
    const int p2 = 64 + p1;
    const float h1a = __bfloat162float(__float2bfloat16_rn(y1a));
    const float h1b = __bfloat162float(__float2bfloat16_rn(y1b));
    const float h2a = __bfloat162float(__float2bfloat16_rn(y2a));
    const float h2b = __bfloat162float(__float2bfloat16_rn(y2b));
    oh[ob + p1] = pack_bf(h1a, h1b);
    ol[ob + p1] = pack_bf(y1a - h1a, y1b - h1b);
    oh[ob + p2] = pack_bf(h2a, h2b);
    ol[ob + p2] = pack_bf(y2a - h2a, y2b - h2b);
}

// ---------------- V transpose + bf16 split (coalesced writes) ----------------
__global__ __launch_bounds__(256) void vt_pack()
{
    __shared__ float t[64][65];
    const int b   = blockIdx.z >> 2;
    const int hkv = blockIdx.z & 3;
    const int l0 = blockIdx.x * 64;
    const int d0 = blockIdx.y * 64;
    const int tid = threadIdx.x;

    for (int i = tid; i < 64 * 64; i += 256) {
        const int lrow = i >> 6, dcol = i & 63;
        t[lrow][dcol] = g_V[(((size_t)b * LT + l0 + lrow) * NKV + hkv) * DHD + d0 + dcol];
    }
    __syncthreads();

    // 4 threads per d-row -> 128B-contiguous writes
    const int drow = tid >> 2;
    const int mg = tid & 3;
    const size_t obase = (((size_t)b * NKV + hkv) * DHD + d0 + drow) * (LT / 2) + l0 / 2;
#pragma unroll
    for (int m = 0; m < 8; m++) {
        const int lp = mg * 8 + m;
        const float v0 = t[2 * lp][drow];
        const float v1 = t[2 * lp + 1][drow];
        const float h0 = __bfloat162float(__float2bfloat16_rn(v0));
        const float h1 = __bfloat162float(__float2bfloat16_rn(v1));
        const int pos = mg * 8 + PERM8(m);
        g_VTh[obase + pos] = pack_bf(h0, h1);
        g_VTl[obase + pos] = pack_bf(v0 - h0, v1 - h1);
    }
}

// ---------------- bf16x3 flash attention, 512 threads ------------------------
#define AQH 0
#define AQL 8192
#define AKH 16384
#define AKL 24576
#define AVH 32768
#define AVL 40960
#define ASF 49152
#define APH 53504
#define APL 55552
#define AAS 57600
#define ALS 57664
#define SMEM_ATTN (57728 * 4)

__global__ __launch_bounds__(512, 1) void attn_mma(const float* __restrict__ mask)
{
    extern __shared__ uint32_t su[];
    float* S   = (float*)(su + ASF);
    float* Asc = (float*)(su + AAS);
    float* Lsc = (float*)(su + ALS);

    const int tid = threadIdx.x;
    const int qt = blockIdx.x;
    const int h  = blockIdx.y;
    const int b  = blockIdx.z;
    const int hkv = h >> 1;
    const int wid = tid >> 5, lane = tid & 31;
    const int wm = wid & 3, wn = wid >> 2;
    const int lr = lane >> 2, lc = lane & 3;
    const int srow = tid >> 3, part = tid & 7;

    const uint32_t sb = (uint32_t)__cvta_generic_to_shared(su);

    {
        const uint32_t* qsrc[2] = { g_Qh, g_Ql };
        const uint32_t* ksrc[2] = { g_Kh, g_Kl };
#pragma unroll
        for (int pl = 0; pl < 2; pl++) {
            for (int i = tid; i < 2048; i += 512) {
                const int row = i >> 5, ch = i & 31;
                const uint32_t dst = sb + ((pl ? AQL : AQH) + row * 128 +
                                           (((2 * ch) ^ ((row & 3) << 2)) * 2)) * 4;
                cpa16(dst, qsrc[pl] + (((size_t)b * LT + qt * 64 + row) * NH + h) * 128 + ch * 4);
            }
            for (int i = tid; i < 2048; i += 512) {
                const int row = i >> 5, ch = i & 31;
                const uint32_t dst = sb + ((pl ? AKL : AKH) + row * 128 +
                                           (((2 * ch) ^ ((row & 3) << 2)) * 2)) * 4;
                cpa16(dst, ksrc[pl] + (((size_t)b * LT + row) * NKV + hkv) * 128 + ch * 4);
            }
        }
        asm volatile("cp.async.commit_group;");
        const uint32_t* vsrc[2] = { g_VTh, g_VTl };
#pragma unroll
        for (int pl = 0; pl < 2; pl++)
            for (int i = tid; i < 2048; i += 512) {
                const int row = i >> 3, ch = i & 7;
                const uint32_t dst = sb + ((pl ? AVL : AVH) + row * 32 +
                                           (((2 * ch) ^ ((row & 3) << 2)) * 2)) * 4;
                cpa16(dst, vsrc[pl] + (((size_t)b * NKV + hkv) * DHD + row) * (LT / 2) + ch * 4);
            }
        asm volatile("cp.async.commit_group;");
    }

    float accO[8][4];
#pragma unroll
    for (int i = 0; i < 8; i++)
#pragma unroll
        for (int j = 0; j < 4; j++) accO[i][j] = 0.f;
    float m_run = -1e30f, l_run = 0.f;

    const int fsw = (lr & 3) << 2;

    for (int kt = 0; kt < LT / 64; kt++) {
        asm volatile("cp.async.wait_group 1;");
        __syncthreads();

        // ---- prefetch mask for this tile (overlaps QK MMAs) ----
        float2 mk0[2], mk1[2];
        {
            const size_t mrow0 = ((size_t)b * LT + qt * 64 + wm * 16 + lr) * LT + kt * 64 + wn * 16;
            const size_t mrow1 = mrow0 + (size_t)8 * LT;
#pragma unroll
            for (int nf = 0; nf < 2; nf++) {
                const int col = nf * 8 + lc * 2;
                mk0[nf] = *(const float2*)&mask[mrow0 + col];
                mk1[nf] = *(const float2*)&mask[mrow1 + col];
            }
        }

        float accS[2][4];
#pragma unroll
        for (int i = 0; i < 2; i++)
#pragma unroll
            for (int j = 0; j < 4; j++) accS[i][j] = 0.f;
        {
            const uint32_t* qh = su + AQH + (wm * 16 + lr) * 128;
            const uint32_t* ql = su + AQL + (wm * 16 + lr) * 128;
            const uint32_t* kh = su + AKH + (wn * 16 + lr) * 128;
            const uint32_t* kl = su + AKL + (wn * 16 + lr) * 128;
#pragma unroll 4
            for (int g = 0; g < 16; g++) {
                const int q2 = ((g * 4 + lc) ^ fsw) * 2;
                uint32_t ah[4], bh[2][2];
                uint2 t;
                t = *(const uint2*)(qh + q2);             ah[0] = t.x; ah[2] = t.y;
                t = *(const uint2*)(qh + 8 * 128 + q2);   ah[1] = t.x; ah[3] = t.y;
#pragma unroll
                for (int nf = 0; nf < 2; nf++) {
                    t = *(const uint2*)(kh + nf * 8 * 128 + q2);  bh[nf][0] = t.x; bh[nf][1] = t.y;
                }
#pragma unroll
                for (int nf = 0; nf < 2; nf++) MMA_BF16(accS[nf], ah, bh[nf]);
                uint32_t al[4];
                t = *(const uint2*)(ql + q2);             al[0] = t.x; al[2] = t.y;
                t = *(const uint2*)(ql + 8 * 128 + q2);   al[1] = t.x; al[3] = t.y;
#pragma unroll
                for (int nf = 0; nf < 2; nf++) {
                    uint32_t bl[2];
                    t = *(const uint2*)(kl + nf * 8 * 128 + q2);  bl[0] = t.x; bl[1] = t.y;
                    MMA_BF16(accS[nf], al, bh[nf]);
                    MMA_BF16(accS[nf], ah, bl);
                }
            }
        }
        {
#pragma unroll
            for (int nf = 0; nf < 2; nf++) {
                const int col = nf * 8 + lc * 2;
                *(float2*)&S[(wm * 16 + lr) * 68 + wn * 16 + col] =
                    make_float2(accS[nf][0] + mk0[nf].x, accS[nf][1] + mk0[nf].y);
                *(float2*)&S[(wm * 16 + lr + 8) * 68 + wn * 16 + col] =
                    make_float2(accS[nf][2] + mk1[nf].x, accS[nf][3] + mk1[nf].y);
            }
        }
        __syncthreads();

        if (kt + 1 < LT / 64) {
            const uint32_t* ksrc[2] = { g_Kh, g_Kl };
#pragma unroll
            for (int pl = 0; pl < 2; pl++)
                for (int i = tid; i < 2048; i += 512) {
                    const int row = i >> 5, ch = i & 31;
                    const uint32_t dst = sb + ((pl ? AKL : AKH) + row * 128 +
                                               (((2 * ch) ^ ((row & 3) << 2)) * 2)) * 4;
                    cpa16(dst, ksrc[pl] + (((size_t)b * LT + (kt + 1) * 64 + row) * NKV + hkv) * 128 + ch * 4);
                }
            asm volatile("cp.async.commit_group;");
        }

        {
            float* sp = S + srow * 68 + part * 8;
            float pv[8];
            float lm = -1e30f;
#pragma unroll
            for (int j = 0; j < 8; j++) { pv[j] = sp[j]; lm = fmaxf(lm, pv[j]); }
            lm = fmaxf(lm, __shfl_xor_sync(0xffffffffu, lm, 1));
            lm = fmaxf(lm, __shfl_xor_sync(0xffffffffu, lm, 2));
            lm = fmaxf(lm, __shfl_xor_sync(0xffffffffu, lm, 4));
            const float mnew = fmaxf(m_run, lm);
            const float alpha = __expf(m_run - mnew);
            float ls = 0.f;
#pragma unroll
            for (int j = 0; j < 8; j++) { pv[j] = __expf(pv[j] - mnew); ls += pv[j]; }
            ls += __shfl_xor_sync(0xffffffffu, ls, 1);
            ls += __shfl_xor_sync(0xffffffffu, ls, 2);
            ls += __shfl_xor_sync(0xffffffffu, ls, 4);
            l_run = l_run * alpha + ls;
            m_run = mnew;
            if (part == 0) Asc[srow] = alpha;

            const int swz = (srow & 3) << 2;
#pragma unroll
            for (int m = 0; m < 4; m++) {
                const float p0 = pv[2 * m], p1 = pv[2 * m + 1];
                const float h0 = __bfloat162float(__float2bfloat16_rn(p0));
                const float h1 = __bfloat162float(__float2bfloat16_rn(p1));
                const int pp = part * 4 + m;
                const int u = (pp & ~7) | PERM8(pp & 7);
                const int pos = srow * 32 + (((u >> 1) ^ swz) * 2) + (u & 1);
                su[APH + pos] = pack_bf(h0, h1);
                su[APL + pos] = pack_bf(p0 - h0, p1 - h1);
            }
        }
        if (kt + 1 < LT / 64) { asm volatile("cp.async.wait_group 1;"); }
        else                  { asm volatile("cp.async.wait_group 0;"); }
        __syncthreads();

        {
            const float a0 = Asc[wm * 16 + lr];
            const float a1 = Asc[wm * 16 + lr + 8];
#pragma unroll
            for (int nf = 0; nf < 8; nf++) {
                accO[nf][0] *= a0; accO[nf][1] *= a0;
                accO[nf][2] *= a1; accO[nf][3] *= a1;
            }
            const uint32_t* php = su + APH + (wm * 16 + lr) * 32;
            const uint32_t* plp = su + APL + (wm * 16 + lr) * 32;
            const uint32_t* vhp = su + AVH + (wn * 64 + lr) * 32;
            const uint32_t* vlp = su + AVL + (wn * 64 + lr) * 32;
#pragma unroll
            for (int g = 0; g < 4; g++) {
                const int q2 = ((g * 4 + lc) ^ fsw) * 2;
                uint32_t ph[4], vh[8][2];
                uint2 t;
                t = *(const uint2*)(php + q2);            ph[0] = t.x; ph[2] = t.y;
                t = *(const uint2*)(php + 8 * 32 + q2);   ph[1] = t.x; ph[3] = t.y;
#pragma unroll
                for (int nf = 0; nf < 8; nf++) {
                    t = *(const uint2*)(vhp + nf * 8 * 32 + q2);  vh[nf][0] = t.x; vh[nf][1] = t.y;
                }
#pragma unroll
                for (int nf = 0; nf < 8; nf++) MMA_BF16(accO[nf], ph, vh[nf]);
                uint32_t pl[4];
                t = *(const uint2*)(plp + q2);            pl[0] = t.x; pl[2] = t.y;
                t = *(const uint2*)(plp + 8 * 32 + q2);   pl[1] = t.x; pl[3] = t.y;
#pragma unroll
                for (int nf = 0; nf < 8; nf++) {
                    uint32_t vl[2];
                    t = *(const uint2*)(vlp + nf * 8 * 32 + q2);  vl[0] = t.x; vl[1] = t.y;
                    MMA_BF16(accO[nf], pl, vh[nf]);
                    MMA_BF16(accO[nf], ph, vl);
                }
            }
        }
        __syncthreads();

        if (kt + 1 < LT / 64) {
            const uint32_t* vsrc[2] = { g_VTh, g_VTl };
#pragma unroll
            for (int pl = 0; pl < 2; pl++)
                for (int i = tid; i < 2048; i += 512) {
                    const int row = i >> 3, ch = i & 7;
                    const uint32_t dst = sb + ((pl ? AVL : AVH) + row * 32 +
                                               (((2 * ch) ^ ((row & 3) << 2)) * 2)) * 4;
                    cpa16(dst, vsrc[pl] + (((size_t)b * NKV + hkv) * DHD + row) * (LT / 2) +
                               (kt + 1) * 32 + ch * 4);
                }
            asm volatile("cp.async.commit_group;");
        }
    }

    if (part == 0) Lsc[srow] = l_run;
    __syncthreads();

    {
        const float il0 = 1.f / Lsc[wm * 16 + lr];
        const float il1 = 1.f / Lsc[wm * 16 + lr + 8];
        const size_t r0 = (size_t)b * LT + qt * 64 + wm * 16 + lr;
        const size_t r1 = r0 + 8;
#pragma unroll
        for (int nf = 0; nf < 8; nf++) {
            const int p = h * 128 + wn * 32 + nf * 4 + lc;
            const int pos = (p & ~7) | PERM8(p & 7);
            const float v0 = accO[nf][0] * il0, v1 = accO[nf][1] * il0;
            const float v2 = accO[nf][2] * il1, v3 = accO[nf][3] * il1;
            const float h0 = __bfloat162float(__float2bfloat16_rn(v0));
            const float h1 = __bfloat162float(__float2bfloat16_rn(v1));
            const float h2 = __bfloat162float(__float2bfloat16_rn(v2));
            const float h3 = __bfloat162float(__float2bfloat16_rn(v3));
            g_ahi[r0 * 1024 + pos] = pack_bf(h0, h1);
            g_alo[r0 * 1024 + pos] = pack_bf(v0 - h0, v1 - h1);
            g_ahi[r1 * 1024 + pos] = pack_bf(h2, h3);
            g_alo[r1 * 1024 + pos] = pack_bf(v2 - h2, v3 - h3);
        }
    }
}

// ---------------- launch ----------------------------------------------------
extern "C" void kernel_launch(void* const* d_in, const int* in_sizes, int n_in,
                              void* d_out, int out_size)
{
    const float* pg   = (const float*)d_in[0];
    const float* ex   = (const float*)d_in[1];
    const float* cs   = (const float*)d_in[2];
    const float* sn   = (const float*)d_in[3];
    const float* mask = (const float*)d_in[4];
    const float* Wq0  = (const float*)d_in[5];
    const float* Wk0  = (const float*)d_in[6];
    const float* Wv0  = (const float*)d_in[7];
    const float* Wo0  = (const float*)d_in[8];
    const float* Wq1  = (const float*)d_in[9];
    const float* Wk1  = (const float*)d_in[10];
    const float* Wv1  = (const float*)d_in[11];
    const float* Wo1  = (const float*)d_in[12];
    float* out = (float*)d_out;

    float *Qd, *Kd, *Vd;
    uint32_t *Ahd, *Ald, *Hv, *Lv, *Qhp, *Qlp, *Khp, *Klp;
    cudaGetSymbolAddress((void**)&Qd, g_Q);
    cudaGetSymbolAddress((void**)&Kd, g_K);
    cudaGetSymbolAddress((void**)&Vd, g_V);
    cudaGetSymbolAddress((void**)&Ahd, g_ahi);
    cudaGetSymbolAddress((void**)&Ald, g_alo);
    cudaGetSymbolAddress((void**)&Hv, g_hi);
    cudaGetSymbolAddress((void**)&Lv, g_lo);
    cudaGetSymbolAddress((void**)&Qhp, g_Qh);
    cudaGetSymbolAddress((void**)&Qlp, g_Ql);
    cudaGetSymbolAddress((void**)&Khp, g_Kh);
    cudaGetSymbolAddress((void**)&Klp, g_Kl);

    cudaFuncSetAttribute(gemm_b3, cudaFuncAttributeMaxDynamicSharedMemorySize, GSM_BYTES);
    cudaFuncSetAttribute(attn_mma, cudaFuncAttributeMaxDynamicSharedMemorySize, SMEM_ATTN);

    const int MQ = NH * DHD;    // 2048
    const int MKV = NKV * DHD;  // 1024

    // --- split projection operands ---
    CvtArgs ca;
    const float* srcs[10] = { pg, ex, Wq0, Wk0, Wv0, Wo0, Wq1, Wk1, Wv1, Wo1 };
    const uint32_t offs[10] = { OP_PG, OP_EX, OP_WQ0, OP_WK0, OP_WV0,
                                OP_WO0, OP_WQ1, OP_WK1, OP_WV1, OP_WO1 };
    const int ns[10] = { BB * L1C * DPG, BB * L2C * DEX, MQ * DPG, MKV * DPG,
                         MKV * DPG, DPG * MQ, MQ * DEX, MKV * DEX, MKV * DEX, DEX * MQ };
    int maxg = 0;
    for (int i = 0; i < 10; i++) {
        ca.src[i] = srcs[i]; ca.off[i] = offs[i]; ca.n16[i] = ns[i] / 16;
        if (ca.n16[i] > maxg) maxg = ca.n16[i];
    }
    cvt_bsplit<<<dim3((maxg + 255) / 256, 10), 256>>>(ca);

    // --- fused QKV projections, both streams in one launch ---
    {
        GemmJob j0 = { Hv + OP_PG, Lv + OP_PG, Hv + OP_WQ0, Lv + OP_WQ0,
                       DPG / 2, BB * L1C, 0, 0, L1C, LT, 0,
                       MQ, MQ + MKV, Qd, Kd, Vd, MQ, MKV, MKV, 32, 32 };
        GemmJob j1 = { Hv + OP_EX, Lv + OP_EX, Hv + OP_WQ1, Lv + OP_WQ1,
                       DEX / 2, BB * L2C, 0, 0, L2C, LT, L1C,
                       MQ, MQ + MKV, Qd, Kd, Vd, MQ, MKV, MKV, 32, 16 };
        gemm_b3<<<dim3(32, 32, 2), 128, GSM_BYTES>>>(j0, j1);
    }

    // --- RoPE (Q+K fused) + pack; V transpose/pack ---
    rope_pack2<<<dim3(NH + NKV, LT, BB), 64>>>(Qd, Kd, cs, sn, Qhp, Qlp, Khp, Klp);
    vt_pack<<<dim3(LT / 64, DHD / 64, BB * NKV), 256>>>();

    // --- attention (512 threads) ---
    attn_mma<<<dim3(LT / 64, NH, BB), 512, SMEM_ATTN>>>(mask);

    // --- output projections, both streams in one launch ---
    {
        float* out1 = out + (size_t)BB * L1C * DPG;
        GemmJob j0 = { Ahd, Ald, Hv + OP_WO0, Lv + OP_WO0,
                       MQ / 2, L1C, LT, 0, BB * L1C, 0, 0,
                       DPG, DPG, out, out, out, DPG, DPG, DPG, 18, 32 };
        GemmJob j1 = { Ahd, Ald, Hv + OP_WO1, Lv + OP_WO1,
                       MQ / 2, L2C, LT, L1C, BB * L2C, 0, 0,
                       DEX, DEX, out1, out1, out1, DEX, DEX, DEX, 8, 16 };
        gemm_b3<<<dim3(18, 32, 2), 128, GSM_BYTES>>>(j0, j1);
    }
}